// round 1
// baseline (speedup 1.0000x reference)
#include <cuda_runtime.h>
#include <math.h>

#define HWN 1024
#define CDIM 128
#define EXPD 512
#define NB   16

// Scratch (allocation-free rule: static __device__ arrays)
__device__ float g_q[NB * EXPD * HWN];
__device__ float g_k[NB * EXPD * HWN];
__device__ float g_v[NB * EXPD * HWN];
__device__ float g_wsv[NB * EXPD * HWN];

// ---------------------------------------------------------------------------
// Generic channel GEMM: C[z] (M x 1024) = A (M x K, row-major) * B[z] (K x 1024)
//   + optional bias[M] + optional residual (same shape as C).
// Block tile 64x64, BK=16, 256 threads, 4x4 microtile.
// ---------------------------------------------------------------------------
__global__ __launch_bounds__(256) void gemm_k(
    const float* __restrict__ A, const float* __restrict__ Bbase,
    const float* __restrict__ bias, const float* __restrict__ resid,
    float* __restrict__ Cbase, int M, int K)
{
    __shared__ float As[16 * 64];   // [kk][o]
    __shared__ float Bs[16 * 64];   // [kk][n]

    const int z  = blockIdx.z;
    const float* B = Bbase + (size_t)z * K * HWN;
    float*       C = Cbase + (size_t)z * M * HWN;
    const float* R = resid ? resid + (size_t)z * M * HWN : nullptr;

    const int n0 = blockIdx.x * 64;
    const int o0 = blockIdx.y * 64;
    const int tid = threadIdx.x;
    const int ty = tid >> 4, tx = tid & 15;

    float acc[4][4] = {};

    for (int k0 = 0; k0 < K; k0 += 16) {
        // A tile: 64 rows x 16 k, stored transposed As[kk][o]
        {
            int r  = tid >> 2;
            int c4 = (tid & 3) * 4;
            float4 a4 = *(const float4*)&A[(size_t)(o0 + r) * K + k0 + c4];
            As[(c4 + 0) * 64 + r] = a4.x;
            As[(c4 + 1) * 64 + r] = a4.y;
            As[(c4 + 2) * 64 + r] = a4.z;
            As[(c4 + 3) * 64 + r] = a4.w;
        }
        // B tile: 16 k rows x 64 n
        {
            int r  = tid >> 4;
            int c4 = (tid & 15) * 4;
            *(float4*)&Bs[r * 64 + c4] =
                *(const float4*)&B[(size_t)(k0 + r) * HWN + n0 + c4];
        }
        __syncthreads();

        #pragma unroll
        for (int kk = 0; kk < 16; kk++) {
            float4 a4 = *(float4*)&As[kk * 64 + ty * 4];
            float4 b4 = *(float4*)&Bs[kk * 64 + tx * 4];
            float av[4] = {a4.x, a4.y, a4.z, a4.w};
            float bvv[4] = {b4.x, b4.y, b4.z, b4.w};
            #pragma unroll
            for (int i = 0; i < 4; i++)
                #pragma unroll
                for (int j = 0; j < 4; j++)
                    acc[i][j] += av[i] * bvv[j];
        }
        __syncthreads();
    }

    #pragma unroll
    for (int i = 0; i < 4; i++) {
        int o = o0 + ty * 4 + i;
        float bi = bias ? bias[o] : 0.f;
        size_t base = (size_t)o * HWN + n0 + tx * 4;
        float4 add = make_float4(bi, bi, bi, bi);
        if (R) {
            float4 x4 = *(const float4*)&R[base];
            add.x += x4.x; add.y += x4.y; add.z += x4.z; add.w += x4.w;
        }
        float4 o4 = make_float4(acc[i][0] + add.x, acc[i][1] + add.y,
                                acc[i][2] + add.z, acc[i][3] + add.w);
        *(float4*)&C[base] = o4;
    }
}

// ---------------------------------------------------------------------------
// Fused attention per (batch, head, 32-query-row block).
//   S = (Q^T K)/sqrt(128)  -> exact row softmax (S rows resident in smem)
//   O = P V^T, 1/rowsum folded into epilogue.
// Output written with the reference's reshape:
//   wsv[b, h*128 + (n>>3), (n&7)*128 + d] = O[n][d]
// ---------------------------------------------------------------------------
__global__ __launch_bounds__(256) void attn_k(
    const float* __restrict__ gq, const float* __restrict__ gk,
    const float* __restrict__ gv, float* __restrict__ gwsv)
{
    extern __shared__ float sm[];
    float* q_s  = sm;                   // [32][132]  (q * scale, [nr][d])
    float* s_s  = sm + 32 * 132;        // [1024][33] (S transposed: [m][nr])
    float* kv   = s_s + 1024 * 33;      // 8192 floats: K tile [d][64] / V tile swizzled
    float* rinv = kv + 8192;            // [32] reciprocal row sums

    const int b  = blockIdx.z;
    const int h  = blockIdx.y;
    const int n0 = blockIdx.x * 32;
    const int tid = threadIdx.x;

    const size_t base = ((size_t)b * EXPD + h * CDIM) * HWN;
    const float* Q = gq + base;
    const float* K = gk + base;
    const float* V = gv + base;
    const float scale = 0.08838834764831843f;  // 1/sqrt(128)

    // Load Q block (pre-scaled)
    {
        int nr = tid & 31, d0 = tid >> 5;
        #pragma unroll
        for (int p = 0; p < 16; p++) {
            int d = d0 + p * 8;
            q_s[nr * 132 + d] = Q[(size_t)d * HWN + n0 + nr] * scale;
        }
    }

    // ---- Phase 1: S = Q^T K, stored transposed s_s[m][nr] ----
    const int ml = tid & 31;      // m lane within 64-wide tile
    const int ng = tid >> 5;      // nr group (4 rows each)
    for (int mt = 0; mt < 16; mt++) {
        const int m0 = mt * 64;
        __syncthreads();
        {   // K tile [128 d][64 m], row-contiguous
            int c4 = (tid & 15) * 4, dr = tid >> 4;
            #pragma unroll
            for (int p = 0; p < 8; p++) {
                int d = dr + p * 16;
                *(float4*)&kv[d * 64 + c4] =
                    *(const float4*)&K[(size_t)d * HWN + m0 + c4];
            }
        }
        __syncthreads();

        float acc[4][2] = {};
        #pragma unroll 8
        for (int d4 = 0; d4 < 32; d4++) {
            float4 qv4[4];
            #pragma unroll
            for (int i = 0; i < 4; i++)
                qv4[i] = *(float4*)&q_s[(ng * 4 + i) * 132 + d4 * 4];
            const float* qf = (const float*)qv4;
            #pragma unroll
            for (int dd = 0; dd < 4; dd++) {
                float k0 = kv[(d4 * 4 + dd) * 64 + ml];
                float k1 = kv[(d4 * 4 + dd) * 64 + ml + 32];
                #pragma unroll
                for (int i = 0; i < 4; i++) {
                    acc[i][0] += qf[i * 4 + dd] * k0;
                    acc[i][1] += qf[i * 4 + dd] * k1;
                }
            }
        }
        #pragma unroll
        for (int i = 0; i < 4; i++) {
            s_s[(m0 + ml)      * 33 + ng * 4 + i] = acc[i][0];
            s_s[(m0 + ml + 32) * 33 + ng * 4 + i] = acc[i][1];
        }
    }
    __syncthreads();

    // ---- Phase 2: exact softmax over m (columns of s_s, conflict-free via pad 33) ----
    {
        int w = tid >> 5, lane = tid & 31;
        #pragma unroll
        for (int r = 0; r < 4; r++) {
            int row = w * 4 + r;
            float mx = -1e30f;
            for (int t = 0; t < 32; t++)
                mx = fmaxf(mx, s_s[(lane + t * 32) * 33 + row]);
            #pragma unroll
            for (int o = 16; o > 0; o >>= 1)
                mx = fmaxf(mx, __shfl_xor_sync(0xffffffffu, mx, o));
            float sum = 0.f;
            for (int t = 0; t < 32; t++) {
                int idx = (lane + t * 32) * 33 + row;
                float e = __expf(s_s[idx] - mx);
                s_s[idx] = e;
                sum += e;
            }
            #pragma unroll
            for (int o = 16; o > 0; o >>= 1)
                sum += __shfl_xor_sync(0xffffffffu, sum, o);
            if (lane == 0) rinv[row] = 1.f / sum;
        }
    }

    // ---- Phase 3: O = P V^T (V tile XOR-swizzled -> conflict-free reads) ----
    const int dl = tid & 31, ng2 = tid >> 5;
    float oacc[4][4] = {};
    for (int mt = 0; mt < 16; mt++) {
        const int m0 = mt * 64;
        __syncthreads();
        {   // V tile stored as vs[m][ d ^ (m&31) ], stride 128
            int c4 = (tid & 15) * 4, dr = tid >> 4;
            #pragma unroll
            for (int p = 0; p < 8; p++) {
                int d = dr + p * 16;
                float4 vv = *(const float4*)&V[(size_t)d * HWN + m0 + c4];
                const float* vf = (const float*)&vv;
                #pragma unroll
                for (int j = 0; j < 4; j++) {
                    int m = c4 + j;
                    kv[m * 128 + (d ^ (m & 31))] = vf[j];
                }
            }
        }
        __syncthreads();

        #pragma unroll 4
        for (int m = 0; m < 64; m++) {
            float pv[4];
            #pragma unroll
            for (int i = 0; i < 4; i++)
                pv[i] = s_s[(m0 + m) * 33 + ng2 * 4 + i];
            #pragma unroll
            for (int j = 0; j < 4; j++) {
                float vvv = kv[m * 128 + ((dl + 32 * j) ^ (m & 31))];
                #pragma unroll
                for (int i = 0; i < 4; i++)
                    oacc[i][j] += pv[i] * vvv;
            }
        }
    }

    // ---- Epilogue: scale by 1/rowsum, write with reference reshape ----
    #pragma unroll
    for (int i = 0; i < 4; i++) {
        int n = n0 + ng2 * 4 + i;
        float rs = rinv[ng2 * 4 + i];
        size_t obase = ((size_t)b * EXPD + h * CDIM + (n >> 3)) * HWN
                     + (size_t)(n & 7) * CDIM;
        #pragma unroll
        for (int j = 0; j < 4; j++)
            gwsv[obase + dl + 32 * j] = oacc[i][j] * rs;
    }
}

// ---------------------------------------------------------------------------
extern "C" void kernel_launch(void* const* d_in, const int* in_sizes, int n_in,
                              void* d_out, int out_size)
{
    const float* x  = (const float*)d_in[0];
    const float* Wq = (const float*)d_in[1];
    const float* Wk = (const float*)d_in[2];
    const float* Wv = (const float*)d_in[3];
    const float* bv = (const float*)d_in[4];
    const float* Wt = (const float*)d_in[5];
    const float* bt = (const float*)d_in[6];
    float* out = (float*)d_out;

    float *pq, *pk, *pv, *pw;
    cudaGetSymbolAddress((void**)&pq, g_q);
    cudaGetSymbolAddress((void**)&pk, g_k);
    cudaGetSymbolAddress((void**)&pv, g_v);
    cudaGetSymbolAddress((void**)&pw, g_wsv);

    dim3 blk(256);

    // QKV projections: [512,128] @ [128,1024] per batch
    dim3 gqkv(HWN / 64, EXPD / 64, NB);
    gemm_k<<<gqkv, blk>>>(Wq, x, nullptr, nullptr, pq, EXPD, CDIM);
    gemm_k<<<gqkv, blk>>>(Wk, x, nullptr, nullptr, pk, EXPD, CDIM);
    gemm_k<<<gqkv, blk>>>(Wv, x, bv,      nullptr, pv, EXPD, CDIM);

    // Fused attention: 32 row-blocks x 4 heads x 16 batches
    size_t smem = (size_t)(32 * 132 + 1024 * 33 + 8192 + 32) * sizeof(float);
    cudaFuncSetAttribute(attn_k, cudaFuncAttributeMaxDynamicSharedMemorySize,
                         (int)smem);
    attn_k<<<dim3(32, 4, NB), blk, smem>>>(pq, pk, pv, pw);

    // Output projection + bias + residual: [128,512] @ [512,1024] per batch
    dim3 gproj(HWN / 64, CDIM / 64, NB);
    gemm_k<<<gproj, blk>>>(Wt, pw, bt, x, out, CDIM, EXPD);
}

// round 3
// speedup vs baseline: 3.0475x; 3.0475x over previous
#include <cuda_runtime.h>
#include <cstdint>

#define HWN 1024
#define CDIM 128
#define EXPD 512
#define NB   16

// Scratch (allocation-free rule: static __device__ arrays)
__device__ float g_q[NB * EXPD * HWN];   // [b][h][n][d]  (d contiguous)
__device__ float g_k[NB * EXPD * HWN];   // [b][h][m][d]  (d contiguous)
__device__ float g_v[NB * EXPD * HWN];   // [b][h][d][m]  (m contiguous)
__device__ float g_wsv[NB * EXPD * HWN]; // [b][c'][pix]

// ---------------------------------------------------------------------------
__device__ __forceinline__ float tf32r(float x) {
    uint32_t u;
    asm("cvt.rna.tf32.f32 %0, %1;" : "=r"(u) : "f"(x));
    return __uint_as_float(u);
}

__device__ __forceinline__ void mma8(float (&d)[4], const float (&a)[4],
                                     uint32_t b0, uint32_t b1) {
    asm volatile(
        "mma.sync.aligned.m16n8k8.row.col.f32.tf32.tf32.f32 "
        "{%0,%1,%2,%3}, {%4,%5,%6,%7}, {%8,%9}, {%0,%1,%2,%3};"
        : "+f"(d[0]), "+f"(d[1]), "+f"(d[2]), "+f"(d[3])
        : "r"(__float_as_uint(a[0])), "r"(__float_as_uint(a[1])),
          "r"(__float_as_uint(a[2])), "r"(__float_as_uint(a[3])),
          "r"(b0), "r"(b1));
}

// ---------------------------------------------------------------------------
// Channel GEMM (fp32 SIMT): C[z] (M x 1024) = A (M x K) * B[z] (K x 1024)
// mode 0: C[z][o][n] (+bias +resid).
// mode 1: transposed store C[z][o>>7][n][o&127] with lanes along o (coalesced).
// ---------------------------------------------------------------------------
__global__ __launch_bounds__(256) void gemm_k(
    const float* __restrict__ A, const float* __restrict__ Bbase,
    const float* __restrict__ bias, const float* __restrict__ resid,
    float* __restrict__ C, int M, int K, int mode)
{
    __shared__ float As[16 * 64];
    __shared__ float Bs[16 * 64];

    const int z = blockIdx.z;
    const float* B = Bbase + (size_t)z * K * HWN;

    const int n0 = blockIdx.x * 64;
    const int o0 = blockIdx.y * 64;
    const int tid = threadIdx.x;
    const int ty = tid >> 4, tx = tid & 15;
    const int rI = mode ? tx : ty;   // o-index lane
    const int cI = mode ? ty : tx;   // n-index lane

    float acc[4][4] = {};

    for (int k0 = 0; k0 < K; k0 += 16) {
        {
            int r = tid >> 2, c4 = (tid & 3) * 4;
            float4 a4 = *(const float4*)&A[(size_t)(o0 + r) * K + k0 + c4];
            As[(c4 + 0) * 64 + r] = a4.x;
            As[(c4 + 1) * 64 + r] = a4.y;
            As[(c4 + 2) * 64 + r] = a4.z;
            As[(c4 + 3) * 64 + r] = a4.w;
        }
        {
            int r = tid >> 4, c4 = (tid & 15) * 4;
            *(float4*)&Bs[r * 64 + c4] =
                *(const float4*)&B[(size_t)(k0 + r) * HWN + n0 + c4];
        }
        __syncthreads();
#pragma unroll
        for (int kk = 0; kk < 16; kk++) {
            float4 a4 = *(float4*)&As[kk * 64 + rI * 4];
            float4 b4 = *(float4*)&Bs[kk * 64 + cI * 4];
            float av[4] = {a4.x, a4.y, a4.z, a4.w};
            float bv[4] = {b4.x, b4.y, b4.z, b4.w};
#pragma unroll
            for (int i = 0; i < 4; i++)
#pragma unroll
                for (int j = 0; j < 4; j++)
                    acc[i][j] += av[i] * bv[j];
        }
        __syncthreads();
    }

    if (mode == 0) {
#pragma unroll
        for (int i = 0; i < 4; i++) {
            int o = o0 + rI * 4 + i;
            float bi = bias ? bias[o] : 0.f;
            size_t base = (size_t)z * M * HWN + (size_t)o * HWN + n0 + cI * 4;
            float4 add = make_float4(bi, bi, bi, bi);
            if (resid) {
                float4 x4 = *(const float4*)&resid[base];
                add.x += x4.x; add.y += x4.y; add.z += x4.z; add.w += x4.w;
            }
            float4 o4 = make_float4(acc[i][0] + add.x, acc[i][1] + add.y,
                                    acc[i][2] + add.z, acc[i][3] + add.w);
            *(float4*)&C[base] = o4;
        }
    } else {
        // lanes (tx) run along o -> contiguous float4 stores in d
        int o = o0 + rI * 4;         // o..o+3 via acc[i][*]
#pragma unroll
        for (int j = 0; j < 4; j++) {
            int n = n0 + cI * 4 + j;
            size_t idx = (((size_t)z * 4 + (o >> 7)) * HWN + n) * CDIM + (o & 127);
            float4 v = make_float4(acc[0][j], acc[1][j], acc[2][j], acc[3][j]);
            *(float4*)&C[idx] = v;
        }
    }
}

// ---------------------------------------------------------------------------
// Attention with mma.sync tf32. One CTA = (b, h, 128-query tile), 8 warps.
// Warp w owns rows n0 + w*16 .. +15. Q fragments + O accumulators in regs.
// m streamed in tiles of 64: Ks[64][132] ([m][d]), Vs[128][68] ([d][m]).
// Exact softmax without max-subtraction; 1/rowsum in epilogue.
// ---------------------------------------------------------------------------
__global__ __launch_bounds__(256, 1) void attn_mma(
    const float* __restrict__ gq, const float* __restrict__ gk,
    const float* __restrict__ gv, float* __restrict__ gwsv)
{
    extern __shared__ float sm[];
    float* Ks = sm;               // [64][132]  = 8448 floats
    float* Vs = sm + 64 * 132;    // [128][68]  = 8704 floats
    // Q staging reuses both regions: 128*132 = 16896 <= 17152 floats

    const int tid = threadIdx.x;
    const int w = tid >> 5, lane = tid & 31;
    const int g = lane >> 2, t = lane & 3;
    const int b = blockIdx.z, h = blockIdx.y;
    const int bh = b * 4 + h;
    const int n0 = blockIdx.x * 128;
    const float scale = 0.08838834764831843f;

    const float* Qg = gq + ((size_t)bh * HWN + n0) * CDIM;
    const float* Kg = gk + (size_t)bh * HWN * CDIM;
    const float* Vg = gv + (size_t)bh * CDIM * HWN;

    // ---- stage Q (scaled, tf32-rounded) into smem [n][132] ----
    for (int i = tid; i < 128 * 32; i += 256) {
        int r = i >> 5, c4 = (i & 31) * 4;
        float4 v = *(const float4*)&Qg[r * CDIM + c4];
        v.x = tf32r(v.x * scale); v.y = tf32r(v.y * scale);
        v.z = tf32r(v.z * scale); v.w = tf32r(v.w * scale);
        *(float4*)&sm[r * 132 + c4] = v;
    }
    __syncthreads();

    // ---- extract persistent Q fragments (16 k-chunks x 4 regs) ----
    float qa[16][4];
    {
        const float* q0 = &sm[(w * 16 + g) * 132];
        const float* q8 = &sm[(w * 16 + g + 8) * 132];
#pragma unroll
        for (int k = 0; k < 16; k++) {
            qa[k][0] = q0[k * 8 + t];
            qa[k][1] = q8[k * 8 + t];
            qa[k][2] = q0[k * 8 + t + 4];
            qa[k][3] = q8[k * 8 + t + 4];
        }
    }
    __syncthreads();

    float oacc[16][4] = {};
    float rs0 = 0.f, rs1 = 0.f;
    const int srcA = (g << 2) + (t >> 1);
    const bool odd = (t & 1);

    for (int mt = 0; mt < 16; mt++) {
        const int m0 = mt * 64;

        // K tile [m][d], stride 132 (tf32-rounded)
        for (int i = tid; i < 64 * 32; i += 256) {
            int r = i >> 5, c4 = (i & 31) * 4;
            float4 v = *(const float4*)&Kg[(size_t)(m0 + r) * CDIM + c4];
            v.x = tf32r(v.x); v.y = tf32r(v.y);
            v.z = tf32r(v.z); v.w = tf32r(v.w);
            *(float4*)&Ks[r * 132 + c4] = v;
        }
        // V tile [d][m], stride 68 (tf32-rounded)
        for (int i = tid; i < 128 * 16; i += 256) {
            int r = i >> 4, c4 = (i & 15) * 4;
            float4 v = *(const float4*)&Vg[(size_t)r * HWN + m0 + c4];
            v.x = tf32r(v.x); v.y = tf32r(v.y);
            v.z = tf32r(v.z); v.w = tf32r(v.w);
            *(float4*)&Vs[r * 68 + c4] = v;
        }
        __syncthreads();

        // ---- S = Q K^T (per 16x8 m-subtile), exp, convert to A-frags ----
        float pa[8][4];
#pragma unroll
        for (int m8 = 0; m8 < 8; m8++) {
            float s[4] = {0.f, 0.f, 0.f, 0.f};
            const float* Kb = &Ks[(m8 * 8 + g) * 132];
#pragma unroll
            for (int k = 0; k < 16; k++) {
                uint32_t b0 = __float_as_uint(Kb[k * 8 + t]);
                uint32_t b1 = __float_as_uint(Kb[k * 8 + t + 4]);
                mma8(s, qa[k], b0, b1);
            }
            // exp (tf32-rounded so P used by MMA == P summed in rowsum)
            float e0 = tf32r(__expf(s[0])), e1 = tf32r(__expf(s[1]));
            float e2 = tf32r(__expf(s[2])), e3 = tf32r(__expf(s[3]));
            rs0 += e0 + e1;
            rs1 += e2 + e3;
            // accum layout -> A-frag layout (quad shuffles)
            float u0 = __shfl_sync(~0u, e0, srcA);
            float u1 = __shfl_sync(~0u, e1, srcA);
            float u2 = __shfl_sync(~0u, e2, srcA);
            float u3 = __shfl_sync(~0u, e3, srcA);
            float v0 = __shfl_sync(~0u, e0, srcA + 2);
            float v1 = __shfl_sync(~0u, e1, srcA + 2);
            float v2 = __shfl_sync(~0u, e2, srcA + 2);
            float v3 = __shfl_sync(~0u, e3, srcA + 2);
            pa[m8][0] = odd ? u1 : u0;
            pa[m8][1] = odd ? u3 : u2;
            pa[m8][2] = odd ? v1 : v0;
            pa[m8][3] = odd ? v3 : v2;
        }

        // ---- O += P V^T ----
#pragma unroll
        for (int d8 = 0; d8 < 16; d8++) {
            const float* Vb = &Vs[(d8 * 8 + g) * 68];
#pragma unroll
            for (int km = 0; km < 8; km++) {
                uint32_t b0 = __float_as_uint(Vb[km * 8 + t]);
                uint32_t b1 = __float_as_uint(Vb[km * 8 + t + 4]);
                mma8(oacc[d8], pa[km], b0, b1);
            }
        }
        __syncthreads();
    }

    // ---- rowsum quad reduction ----
    rs0 += __shfl_xor_sync(~0u, rs0, 1);
    rs0 += __shfl_xor_sync(~0u, rs0, 2);
    rs1 += __shfl_xor_sync(~0u, rs1, 1);
    rs1 += __shfl_xor_sync(~0u, rs1, 2);
    const float ri0 = 1.f / rs0, ri1 = 1.f / rs1;

    // ---- epilogue: write wsv[b, h*128 + n>>3, (n&7)*128 + d] ----
    const int nA = n0 + w * 16 + g;
    const int nB = nA + 8;
    const size_t obA = ((size_t)b * EXPD + h * CDIM + (nA >> 3)) * HWN
                     + (size_t)(nA & 7) * CDIM;
    const size_t obB = ((size_t)b * EXPD + h * CDIM + (nB >> 3)) * HWN
                     + (size_t)(nB & 7) * CDIM;
#pragma unroll
    for (int d8 = 0; d8 < 16; d8++) {
        int d = d8 * 8 + 2 * t;
        *(float2*)&gwsv[obA + d] = make_float2(oacc[d8][0] * ri0,
                                               oacc[d8][1] * ri0);
        *(float2*)&gwsv[obB + d] = make_float2(oacc[d8][2] * ri1,
                                               oacc[d8][3] * ri1);
    }
}

// ---------------------------------------------------------------------------
extern "C" void kernel_launch(void* const* d_in, const int* in_sizes, int n_in,
                              void* d_out, int out_size)
{
    const float* x  = (const float*)d_in[0];
    const float* Wq = (const float*)d_in[1];
    const float* Wk = (const float*)d_in[2];
    const float* Wv = (const float*)d_in[3];
    const float* bv = (const float*)d_in[4];
    const float* Wt = (const float*)d_in[5];
    const float* bt = (const float*)d_in[6];
    float* out = (float*)d_out;

    float *pq, *pk, *pv, *pw;
    cudaGetSymbolAddress((void**)&pq, g_q);
    cudaGetSymbolAddress((void**)&pk, g_k);
    cudaGetSymbolAddress((void**)&pv, g_v);
    cudaGetSymbolAddress((void**)&pw, g_wsv);

    dim3 blk(256);

    // QKV projections: Q,K transposed-store [b,h,n,d]; V natural [b,h,d,m]
    dim3 gqkv(HWN / 64, EXPD / 64, NB);
    gemm_k<<<gqkv, blk>>>(Wq, x, nullptr, nullptr, pq, EXPD, CDIM, 1);
    gemm_k<<<gqkv, blk>>>(Wk, x, nullptr, nullptr, pk, EXPD, CDIM, 1);
    gemm_k<<<gqkv, blk>>>(Wv, x, bv,      nullptr, pv, EXPD, CDIM, 0);

    // tf32 mma.sync attention: 8 n-tiles x 4 heads x 16 batches
    int smem = 17152 * 4;   // 68608 B
    cudaFuncSetAttribute(attn_mma, cudaFuncAttributeMaxDynamicSharedMemorySize,
                         smem);
    attn_mma<<<dim3(8, 4, NB), 256, smem>>>(pq, pk, pv, pw);

    // Output projection + bias + residual (fp32 SIMT)
    dim3 gproj(HWN / 64, CDIM / 64, NB);
    gemm_k<<<gproj, blk>>>(Wt, pw, bt, x, out, CDIM, EXPD, 0);
}

// round 4
// speedup vs baseline: 3.8639x; 1.2679x over previous
#include <cuda_runtime.h>
#include <cstdint>

#define HWN 1024
#define CDIM 128
#define EXPD 512
#define NB   16

// Scratch (allocation-free rule: static __device__ arrays)
__device__ float g_q[NB * EXPD * HWN];   // [b][h][n][d]  (d contiguous)
__device__ float g_k[NB * EXPD * HWN];   // [b][h][m][d]  (d contiguous)
__device__ float g_v[NB * EXPD * HWN];   // [b][h][d][m]  (m contiguous)
__device__ float g_wsv[NB * EXPD * HWN]; // [b][c'][pix]

// ---------------------------------------------------------------------------
__device__ __forceinline__ float tf32r(float x) {
    uint32_t u;
    asm("cvt.rna.tf32.f32 %0, %1;" : "=r"(u) : "f"(x));
    return __uint_as_float(u);
}

__device__ __forceinline__ void mma8(float (&d)[4], const float (&a)[4],
                                     uint32_t b0, uint32_t b1) {
    asm volatile(
        "mma.sync.aligned.m16n8k8.row.col.f32.tf32.tf32.f32 "
        "{%0,%1,%2,%3}, {%4,%5,%6,%7}, {%8,%9}, {%0,%1,%2,%3};"
        : "+f"(d[0]), "+f"(d[1]), "+f"(d[2]), "+f"(d[3])
        : "r"(__float_as_uint(a[0])), "r"(__float_as_uint(a[1])),
          "r"(__float_as_uint(a[2])), "r"(__float_as_uint(a[3])),
          "r"(b0), "r"(b1));
}

// ---------------------------------------------------------------------------
// tf32 mma GEMM: C[z] (M x 1024) = A (M x K) * B[z] (K x 1024)
// CTA tile 64(o) x 64(n), K in chunks of 128. 8 warps = 2(o) x 4(n),
// warp tile 32x16 = 2x2 grid of m16n8k8.
// mode 0: C[z][o][n] (+bias +resid).
// mode 1: transposed store C[z][o>>7][n][o&127] via smem transpose stage.
// ---------------------------------------------------------------------------
__global__ __launch_bounds__(256) void gemm_mma(
    const float* __restrict__ A, const float* __restrict__ Bbase,
    const float* __restrict__ bias, const float* __restrict__ resid,
    float* __restrict__ C, int M, int K, int mode)
{
    extern __shared__ float sh[];
    float* Ws = sh;              // [64][132]
    float* Xs = sh + 64 * 132;   // [128][72]

    const int z = blockIdx.z;
    const float* B = Bbase + (size_t)z * K * HWN;
    const int n0 = blockIdx.x * 64;
    const int o0 = blockIdx.y * 64;
    const int tid = threadIdx.x;
    const int w = tid >> 5, lane = tid & 31;
    const int g = lane >> 2, t = lane & 3;
    const int wo = w >> 2, wn = w & 3;

    float acc[2][2][4] = {};

    for (int k0 = 0; k0 < K; k0 += 128) {
        // Ws tile: 64 o-rows x 128 k (tf32-rounded)
#pragma unroll
        for (int p = 0; p < 8; p++) {
            int idx = tid + p * 256;
            int r = idx >> 5, c4 = (idx & 31) * 4;
            float4 v = *(const float4*)&A[(size_t)(o0 + r) * K + k0 + c4];
            v.x = tf32r(v.x); v.y = tf32r(v.y);
            v.z = tf32r(v.z); v.w = tf32r(v.w);
            *(float4*)&Ws[r * 132 + c4] = v;
        }
        // Xs tile: 128 k-rows x 64 n (tf32-rounded)
#pragma unroll
        for (int p = 0; p < 8; p++) {
            int idx = tid + p * 256;
            int k = idx >> 4, n4 = (idx & 15) * 4;
            float4 v = *(const float4*)&B[(size_t)(k0 + k) * HWN + n0 + n4];
            v.x = tf32r(v.x); v.y = tf32r(v.y);
            v.z = tf32r(v.z); v.w = tf32r(v.w);
            *(float4*)&Xs[k * 72 + n4] = v;
        }
        __syncthreads();

#pragma unroll
        for (int kk = 0; kk < 16; kk++) {
            float a[2][4];
            uint32_t bf[2][2];
#pragma unroll
            for (int i = 0; i < 2; i++) {
                const float* wr = &Ws[(wo * 32 + i * 16 + g) * 132 + kk * 8];
                a[i][0] = wr[t];
                a[i][1] = wr[8 * 132 + t];
                a[i][2] = wr[t + 4];
                a[i][3] = wr[8 * 132 + t + 4];
            }
#pragma unroll
            for (int j = 0; j < 2; j++) {
                bf[j][0] = __float_as_uint(Xs[(kk * 8 + t) * 72 + wn * 16 + j * 8 + g]);
                bf[j][1] = __float_as_uint(Xs[(kk * 8 + t + 4) * 72 + wn * 16 + j * 8 + g]);
            }
#pragma unroll
            for (int i = 0; i < 2; i++)
#pragma unroll
                for (int j = 0; j < 2; j++)
                    mma8(acc[i][j], a[i], bf[j][0], bf[j][1]);
        }
        __syncthreads();
    }

    if (mode == 0) {
#pragma unroll
        for (int i = 0; i < 2; i++) {
            int ob = o0 + wo * 32 + i * 16 + g;
#pragma unroll
            for (int rr = 0; rr < 2; rr++) {
                int orow = ob + rr * 8;
                float bi = bias ? bias[orow] : 0.f;
#pragma unroll
                for (int j = 0; j < 2; j++) {
                    int n = n0 + wn * 16 + j * 8 + 2 * t;
                    size_t addr = (size_t)z * M * HWN + (size_t)orow * HWN + n;
                    float2 v = make_float2(acc[i][j][rr * 2 + 0] + bi,
                                           acc[i][j][rr * 2 + 1] + bi);
                    if (resid) {
                        float2 x2 = *(const float2*)&resid[addr];
                        v.x += x2.x; v.y += x2.y;
                    }
                    *(float2*)&C[addr] = v;
                }
            }
        }
    } else {
        // transpose stage: Cs[n 64][o 68]
        float* Cs = sh;
#pragma unroll
        for (int i = 0; i < 2; i++) {
            int ol = wo * 32 + i * 16 + g;
#pragma unroll
            for (int j = 0; j < 2; j++) {
                int nl = wn * 16 + j * 8 + 2 * t;
                Cs[nl * 68 + ol]           = acc[i][j][0];
                Cs[(nl + 1) * 68 + ol]     = acc[i][j][1];
                Cs[nl * 68 + ol + 8]       = acc[i][j][2];
                Cs[(nl + 1) * 68 + ol + 8] = acc[i][j][3];
            }
        }
        __syncthreads();
        const int head = o0 >> 7, d0 = o0 & 127;
#pragma unroll
        for (int p = 0; p < 4; p++) {
            int idx = p * 256 + tid;
            int nl = idx >> 4, o4 = (idx & 15) * 4;
            float4 v = *(float4*)&Cs[nl * 68 + o4];
            *(float4*)&C[(((size_t)z * 4 + head) * HWN + n0 + nl) * CDIM + d0 + o4] = v;
        }
    }
}

// ---------------------------------------------------------------------------
// Attention with mma.sync tf32. One CTA = (b, h, 128-query tile), 8 warps.
// Warp w owns rows n0 + w*16 .. +15. Q fragments + O accumulators in regs.
// m streamed in tiles of 64: Ks[64][132] ([m][d]), Vs[128][68] ([d][m]).
// Exact softmax without max-subtraction; 1/rowsum in epilogue.
// ---------------------------------------------------------------------------
__global__ __launch_bounds__(256, 1) void attn_mma(
    const float* __restrict__ gq, const float* __restrict__ gk,
    const float* __restrict__ gv, float* __restrict__ gwsv)
{
    extern __shared__ float sm[];
    float* Ks = sm;               // [64][132]  = 8448 floats
    float* Vs = sm + 64 * 132;    // [128][68]  = 8704 floats

    const int tid = threadIdx.x;
    const int w = tid >> 5, lane = tid & 31;
    const int g = lane >> 2, t = lane & 3;
    const int b = blockIdx.z, h = blockIdx.y;
    const int bh = b * 4 + h;
    const int n0 = blockIdx.x * 128;
    const float scale = 0.08838834764831843f;

    const float* Qg = gq + ((size_t)bh * HWN + n0) * CDIM;
    const float* Kg = gk + (size_t)bh * HWN * CDIM;
    const float* Vg = gv + (size_t)bh * CDIM * HWN;

    // ---- stage Q (scaled, tf32-rounded) into smem [n][132] ----
    for (int i = tid; i < 128 * 32; i += 256) {
        int r = i >> 5, c4 = (i & 31) * 4;
        float4 v = *(const float4*)&Qg[r * CDIM + c4];
        v.x = tf32r(v.x * scale); v.y = tf32r(v.y * scale);
        v.z = tf32r(v.z * scale); v.w = tf32r(v.w * scale);
        *(float4*)&sm[r * 132 + c4] = v;
    }
    __syncthreads();

    // ---- extract persistent Q fragments (16 k-chunks x 4 regs) ----
    float qa[16][4];
    {
        const float* q0 = &sm[(w * 16 + g) * 132];
        const float* q8 = &sm[(w * 16 + g + 8) * 132];
#pragma unroll
        for (int k = 0; k < 16; k++) {
            qa[k][0] = q0[k * 8 + t];
            qa[k][1] = q8[k * 8 + t];
            qa[k][2] = q0[k * 8 + t + 4];
            qa[k][3] = q8[k * 8 + t + 4];
        }
    }
    __syncthreads();

    float oacc[16][4] = {};
    float rs0 = 0.f, rs1 = 0.f;
    const int srcA = (g << 2) + (t >> 1);
    const bool odd = (t & 1);

    for (int mt = 0; mt < 16; mt++) {
        const int m0 = mt * 64;

        // K tile [m][d], stride 132 (tf32-rounded)
        for (int i = tid; i < 64 * 32; i += 256) {
            int r = i >> 5, c4 = (i & 31) * 4;
            float4 v = *(const float4*)&Kg[(size_t)(m0 + r) * CDIM + c4];
            v.x = tf32r(v.x); v.y = tf32r(v.y);
            v.z = tf32r(v.z); v.w = tf32r(v.w);
            *(float4*)&Ks[r * 132 + c4] = v;
        }
        // V tile [d][m], stride 68 (tf32-rounded)
        for (int i = tid; i < 128 * 16; i += 256) {
            int r = i >> 4, c4 = (i & 15) * 4;
            float4 v = *(const float4*)&Vg[(size_t)r * HWN + m0 + c4];
            v.x = tf32r(v.x); v.y = tf32r(v.y);
            v.z = tf32r(v.z); v.w = tf32r(v.w);
            *(float4*)&Vs[r * 68 + c4] = v;
        }
        __syncthreads();

        // ---- S = Q K^T (per 16x8 m-subtile), exp, convert to A-frags ----
        float pa[8][4];
#pragma unroll
        for (int m8 = 0; m8 < 8; m8++) {
            float s[4] = {0.f, 0.f, 0.f, 0.f};
            const float* Kb = &Ks[(m8 * 8 + g) * 132];
#pragma unroll
            for (int k = 0; k < 16; k++) {
                uint32_t b0 = __float_as_uint(Kb[k * 8 + t]);
                uint32_t b1 = __float_as_uint(Kb[k * 8 + t + 4]);
                mma8(s, qa[k], b0, b1);
            }
            float e0 = tf32r(__expf(s[0])), e1 = tf32r(__expf(s[1]));
            float e2 = tf32r(__expf(s[2])), e3 = tf32r(__expf(s[3]));
            rs0 += e0 + e1;
            rs1 += e2 + e3;
            float u0 = __shfl_sync(~0u, e0, srcA);
            float u1 = __shfl_sync(~0u, e1, srcA);
            float u2 = __shfl_sync(~0u, e2, srcA);
            float u3 = __shfl_sync(~0u, e3, srcA);
            float v0 = __shfl_sync(~0u, e0, srcA + 2);
            float v1 = __shfl_sync(~0u, e1, srcA + 2);
            float v2 = __shfl_sync(~0u, e2, srcA + 2);
            float v3 = __shfl_sync(~0u, e3, srcA + 2);
            pa[m8][0] = odd ? u1 : u0;
            pa[m8][1] = odd ? u3 : u2;
            pa[m8][2] = odd ? v1 : v0;
            pa[m8][3] = odd ? v3 : v2;
        }

        // ---- O += P V^T ----
#pragma unroll
        for (int d8 = 0; d8 < 16; d8++) {
            const float* Vb = &Vs[(d8 * 8 + g) * 68];
#pragma unroll
            for (int km = 0; km < 8; km++) {
                uint32_t b0 = __float_as_uint(Vb[km * 8 + t]);
                uint32_t b1 = __float_as_uint(Vb[km * 8 + t + 4]);
                mma8(oacc[d8], pa[km], b0, b1);
            }
        }
        __syncthreads();
    }

    // ---- rowsum quad reduction ----
    rs0 += __shfl_xor_sync(~0u, rs0, 1);
    rs0 += __shfl_xor_sync(~0u, rs0, 2);
    rs1 += __shfl_xor_sync(~0u, rs1, 1);
    rs1 += __shfl_xor_sync(~0u, rs1, 2);
    const float ri0 = 1.f / rs0, ri1 = 1.f / rs1;

    // ---- epilogue: write wsv[b, h*128 + n>>3, (n&7)*128 + d] ----
    const int nA = n0 + w * 16 + g;
    const int nB = nA + 8;
    const size_t obA = ((size_t)b * EXPD + h * CDIM + (nA >> 3)) * HWN
                     + (size_t)(nA & 7) * CDIM;
    const size_t obB = ((size_t)b * EXPD + h * CDIM + (nB >> 3)) * HWN
                     + (size_t)(nB & 7) * CDIM;
#pragma unroll
    for (int d8 = 0; d8 < 16; d8++) {
        int d = d8 * 8 + 2 * t;
        *(float2*)&gwsv[obA + d] = make_float2(oacc[d8][0] * ri0,
                                               oacc[d8][1] * ri0);
        *(float2*)&gwsv[obB + d] = make_float2(oacc[d8][2] * ri1,
                                               oacc[d8][3] * ri1);
    }
}

// ---------------------------------------------------------------------------
extern "C" void kernel_launch(void* const* d_in, const int* in_sizes, int n_in,
                              void* d_out, int out_size)
{
    const float* x  = (const float*)d_in[0];
    const float* Wq = (const float*)d_in[1];
    const float* Wk = (const float*)d_in[2];
    const float* Wv = (const float*)d_in[3];
    const float* bv = (const float*)d_in[4];
    const float* Wt = (const float*)d_in[5];
    const float* bt = (const float*)d_in[6];
    float* out = (float*)d_out;

    float *pq, *pk, *pv, *pw;
    cudaGetSymbolAddress((void**)&pq, g_q);
    cudaGetSymbolAddress((void**)&pk, g_k);
    cudaGetSymbolAddress((void**)&pv, g_v);
    cudaGetSymbolAddress((void**)&pw, g_wsv);

    const int gsmem = (64 * 132 + 128 * 72) * 4;  // 70656 B
    cudaFuncSetAttribute(gemm_mma, cudaFuncAttributeMaxDynamicSharedMemorySize,
                         gsmem);

    // QKV projections (tf32 mma): Q,K transposed-store [b,h,n,d]; V natural
    dim3 gqkv(HWN / 64, EXPD / 64, NB);
    gemm_mma<<<gqkv, 256, gsmem>>>(Wq, x, nullptr, nullptr, pq, EXPD, CDIM, 1);
    gemm_mma<<<gqkv, 256, gsmem>>>(Wk, x, nullptr, nullptr, pk, EXPD, CDIM, 1);
    gemm_mma<<<gqkv, 256, gsmem>>>(Wv, x, bv,      nullptr, pv, EXPD, CDIM, 0);

    // tf32 mma.sync attention: 8 n-tiles x 4 heads x 16 batches
    int smem = 17152 * 4;   // 68608 B
    cudaFuncSetAttribute(attn_mma, cudaFuncAttributeMaxDynamicSharedMemorySize,
                         smem);
    attn_mma<<<dim3(8, 4, NB), 256, smem>>>(pq, pk, pv, pw);

    // Output projection + bias + residual (tf32 mma)
    dim3 gproj(HWN / 64, CDIM / 64, NB);
    gemm_mma<<<gproj, 256, gsmem>>>(Wt, pw, bt, x, out, CDIM, EXPD, 0);
}

// round 5
// speedup vs baseline: 4.2565x; 1.1016x over previous
#include <cuda_runtime.h>
#include <cstdint>

#define HWN 1024
#define CDIM 128
#define EXPD 512
#define NB   16

// Scratch (allocation-free rule: static __device__ arrays)
__device__ float g_q[NB * EXPD * HWN];   // [b][h][n][d]  (d contiguous)
__device__ float g_k[NB * EXPD * HWN];   // [b][h][m][d]  (d contiguous)
__device__ float g_v[NB * EXPD * HWN];   // [b][h][d][m]  (m contiguous)
__device__ float g_wsv[NB * EXPD * HWN]; // [b][c'][pix]

// ---------------------------------------------------------------------------
__device__ __forceinline__ float tf32r(float x) {
    uint32_t u;
    asm("cvt.rna.tf32.f32 %0, %1;" : "=r"(u) : "f"(x));
    return __uint_as_float(u);
}

__device__ __forceinline__ uint32_t smem_u32(const void* p) {
    uint32_t a;
    asm("{ .reg .u64 t; cvta.to.shared.u64 t, %1; cvt.u32.u64 %0, t; }"
        : "=r"(a) : "l"(p));
    return a;
}

__device__ __forceinline__ void cpa16(uint32_t dst, const void* src) {
    asm volatile("cp.async.ca.shared.global [%0], [%1], 16;"
                 :: "r"(dst), "l"(src));
}
#define CP_COMMIT() asm volatile("cp.async.commit_group;")
#define CP_WAIT0()  asm volatile("cp.async.wait_group 0;")
#define CP_WAIT1()  asm volatile("cp.async.wait_group 1;")

__device__ __forceinline__ void mma8(float (&d)[4], const float (&a)[4],
                                     uint32_t b0, uint32_t b1) {
    asm volatile(
        "mma.sync.aligned.m16n8k8.row.col.f32.tf32.tf32.f32 "
        "{%0,%1,%2,%3}, {%4,%5,%6,%7}, {%8,%9}, {%0,%1,%2,%3};"
        : "+f"(d[0]), "+f"(d[1]), "+f"(d[2]), "+f"(d[3])
        : "r"(__float_as_uint(a[0])), "r"(__float_as_uint(a[1])),
          "r"(__float_as_uint(a[2])), "r"(__float_as_uint(a[3])),
          "r"(b0), "r"(b1));
}

// ---------------------------------------------------------------------------
// tf32 mma GEMM: C[z] (M x 1024) = A (M x K) * B[z] (K x 1024)
// CTA tile 64(o) x 64(n), K chunks of 128. 8 warps = 2(o) x 4(n).
// cp.async staging (HW truncates operands to tf32 in the MMA).
// mode 0: C[z][o][n] (+bias +resid).
// mode 1: transposed store C[z][o>>7][n][o&127] via smem transpose stage.
// ---------------------------------------------------------------------------
__global__ __launch_bounds__(256) void gemm_mma(
    const float* __restrict__ A, const float* __restrict__ Bbase,
    const float* __restrict__ bias, const float* __restrict__ resid,
    float* __restrict__ C, int M, int K, int mode)
{
    extern __shared__ float sh[];
    float* Ws = sh;              // [64][132]
    float* Xs = sh + 64 * 132;   // [128][72]
    const uint32_t ws_a = smem_u32(Ws), xs_a = smem_u32(Xs);

    const int z = blockIdx.z;
    const float* B = Bbase + (size_t)z * K * HWN;
    const int n0 = blockIdx.x * 64;
    const int o0 = blockIdx.y * 64;
    const int tid = threadIdx.x;
    const int w = tid >> 5, lane = tid & 31;
    const int g = lane >> 2, t = lane & 3;
    const int wo = w >> 2, wn = w & 3;

    float acc[2][2][4] = {};

    for (int k0 = 0; k0 < K; k0 += 128) {
        // Ws: 64 o-rows x 128 k (2048 16B chunks)
#pragma unroll
        for (int p = 0; p < 8; p++) {
            int idx = tid + p * 256;
            int r = idx >> 5, c = (idx & 31) << 2;
            cpa16(ws_a + (uint32_t)(r * 132 + c) * 4,
                  &A[(size_t)(o0 + r) * K + k0 + c]);
        }
        // Xs: 128 k-rows x 64 n
#pragma unroll
        for (int p = 0; p < 8; p++) {
            int idx = tid + p * 256;
            int k = idx >> 4, n4 = (idx & 15) << 2;
            cpa16(xs_a + (uint32_t)(k * 72 + n4) * 4,
                  &B[(size_t)(k0 + k) * HWN + n0 + n4]);
        }
        CP_COMMIT();
        CP_WAIT0();
        __syncthreads();

#pragma unroll
        for (int kk = 0; kk < 16; kk++) {
            float a[2][4];
            uint32_t bf[2][2];
#pragma unroll
            for (int i = 0; i < 2; i++) {
                const float* wr = &Ws[(wo * 32 + i * 16 + g) * 132 + kk * 8];
                a[i][0] = wr[t];
                a[i][1] = wr[8 * 132 + t];
                a[i][2] = wr[t + 4];
                a[i][3] = wr[8 * 132 + t + 4];
            }
#pragma unroll
            for (int j = 0; j < 2; j++) {
                bf[j][0] = __float_as_uint(Xs[(kk * 8 + t) * 72 + wn * 16 + j * 8 + g]);
                bf[j][1] = __float_as_uint(Xs[(kk * 8 + t + 4) * 72 + wn * 16 + j * 8 + g]);
            }
#pragma unroll
            for (int i = 0; i < 2; i++)
#pragma unroll
                for (int j = 0; j < 2; j++)
                    mma8(acc[i][j], a[i], bf[j][0], bf[j][1]);
        }
        __syncthreads();
    }

    if (mode == 0) {
#pragma unroll
        for (int i = 0; i < 2; i++) {
            int ob = o0 + wo * 32 + i * 16 + g;
#pragma unroll
            for (int rr = 0; rr < 2; rr++) {
                int orow = ob + rr * 8;
                float bi = bias ? bias[orow] : 0.f;
#pragma unroll
                for (int j = 0; j < 2; j++) {
                    int n = n0 + wn * 16 + j * 8 + 2 * t;
                    size_t addr = (size_t)z * M * HWN + (size_t)orow * HWN + n;
                    float2 v = make_float2(acc[i][j][rr * 2 + 0] + bi,
                                           acc[i][j][rr * 2 + 1] + bi);
                    if (resid) {
                        float2 x2 = *(const float2*)&resid[addr];
                        v.x += x2.x; v.y += x2.y;
                    }
                    *(float2*)&C[addr] = v;
                }
            }
        }
    } else {
        // transpose stage: Cs[n 64][o 68]
        float* Cs = sh;
#pragma unroll
        for (int i = 0; i < 2; i++) {
            int ol = wo * 32 + i * 16 + g;
#pragma unroll
            for (int j = 0; j < 2; j++) {
                int nl = wn * 16 + j * 8 + 2 * t;
                Cs[nl * 68 + ol]           = acc[i][j][0];
                Cs[(nl + 1) * 68 + ol]     = acc[i][j][1];
                Cs[nl * 68 + ol + 8]       = acc[i][j][2];
                Cs[(nl + 1) * 68 + ol + 8] = acc[i][j][3];
            }
        }
        __syncthreads();
        const int head = o0 >> 7, d0 = o0 & 127;
#pragma unroll
        for (int p = 0; p < 4; p++) {
            int idx = p * 256 + tid;
            int nl = idx >> 4, o4 = (idx & 15) * 4;
            float4 v = *(float4*)&Cs[nl * 68 + o4];
            *(float4*)&C[(((size_t)z * 4 + head) * HWN + n0 + nl) * CDIM + d0 + o4] = v;
        }
    }
}

// ---------------------------------------------------------------------------
// Attention, tf32 mma, cp.async double-buffered K/V pipeline.
// One CTA = (b, h, 128-query tile), 8 warps; warp owns 16 q-rows.
// Q fragments + O accumulators register-resident.
// Exact softmax without max-subtraction (scale folded into exp);
// 1/rowsum in epilogue.
// ---------------------------------------------------------------------------
__global__ __launch_bounds__(256, 1) void attn_mma(
    const float* __restrict__ gq, const float* __restrict__ gk,
    const float* __restrict__ gv, float* __restrict__ gwsv)
{
    extern __shared__ float sm[];
    float* Kb0 = sm;                 // [64][132]
    float* Kb1 = sm + 8448;
    float* Vb0 = sm + 16896;         // [128][68]
    float* Vb1 = sm + 16896 + 8704;
    float* Kbuf[2] = {Kb0, Kb1};
    float* Vbuf[2] = {Vb0, Vb1};
    const uint32_t ka[2] = {smem_u32(Kb0), smem_u32(Kb1)};
    const uint32_t va[2] = {smem_u32(Vb0), smem_u32(Vb1)};

    const int tid = threadIdx.x;
    const int w = tid >> 5, lane = tid & 31;
    const int g = lane >> 2, t = lane & 3;
    const int b = blockIdx.z, h = blockIdx.y;
    const int bh = b * 4 + h;
    const int n0 = blockIdx.x * 128;
    const float scale = 0.08838834764831843f;  // 1/sqrt(128)

    const float* Qg = gq + ((size_t)bh * HWN + n0) * CDIM;
    const float* Kg = gk + (size_t)bh * HWN * CDIM;
    const float* Vg = gv + (size_t)bh * CDIM * HWN;

    // ---- stage Q into smem [n][132] via cp.async (reuses K double-buffer) ----
#pragma unroll
    for (int p = 0; p < 16; p++) {
        int idx = tid + p * 256;
        int r = idx >> 5, c = (idx & 31) << 2;
        cpa16(ka[0] + (uint32_t)(r * 132 + c) * 4, &Qg[(size_t)r * CDIM + c]);
    }
    CP_COMMIT();
    CP_WAIT0();
    __syncthreads();

    // ---- extract persistent Q fragments (16 k-chunks x 4 regs) ----
    float qa[16][4];
    {
        const float* q0 = &sm[(w * 16 + g) * 132];
        const float* q8 = &sm[(w * 16 + g + 8) * 132];
#pragma unroll
        for (int k = 0; k < 16; k++) {
            qa[k][0] = q0[k * 8 + t];
            qa[k][1] = q8[k * 8 + t];
            qa[k][2] = q0[k * 8 + t + 4];
            qa[k][3] = q8[k * 8 + t + 4];
        }
    }
    __syncthreads();

    // ---- prefetch tiles 0 and 1 ----
#pragma unroll
    for (int mt = 0; mt < 2; mt++) {
        const int m0 = mt * 64;
#pragma unroll
        for (int p = 0; p < 8; p++) {
            int idx = tid + p * 256;
            int r = idx >> 5, c = (idx & 31) << 2;
            cpa16(ka[mt] + (uint32_t)(r * 132 + c) * 4,
                  &Kg[(size_t)(m0 + r) * CDIM + c]);
        }
#pragma unroll
        for (int p = 0; p < 8; p++) {
            int idx = tid + p * 256;
            int r = idx >> 4, c = (idx & 15) << 2;
            cpa16(va[mt] + (uint32_t)(r * 68 + c) * 4,
                  &Vg[(size_t)r * HWN + m0 + c]);
        }
        CP_COMMIT();
    }

    float oacc[16][4] = {};
    float rs0 = 0.f, rs1 = 0.f;
    const int srcA = (g << 2) + (t >> 1);
    const bool odd = (t & 1);

    for (int mt = 0; mt < 16; mt++) {
        const int bsel = mt & 1;
        if (mt < 15) { CP_WAIT1(); } else { CP_WAIT0(); }
        __syncthreads();

        const float* Ks = Kbuf[bsel];
        const float* Vs = Vbuf[bsel];

        // ---- S = Q K^T (per 16x8 m-subtile), exp, convert to A-frags ----
        float pa[8][4];
#pragma unroll
        for (int m8 = 0; m8 < 8; m8++) {
            float s[4] = {0.f, 0.f, 0.f, 0.f};
            const float* Kb = &Ks[(m8 * 8 + g) * 132];
#pragma unroll
            for (int k = 0; k < 16; k++) {
                uint32_t b0 = __float_as_uint(Kb[k * 8 + t]);
                uint32_t b1 = __float_as_uint(Kb[k * 8 + t + 4]);
                mma8(s, qa[k], b0, b1);
            }
            // scale folded into exp; tf32-round e so rowsum == P operand
            float e0 = tf32r(__expf(s[0] * scale));
            float e1 = tf32r(__expf(s[1] * scale));
            float e2 = tf32r(__expf(s[2] * scale));
            float e3 = tf32r(__expf(s[3] * scale));
            rs0 += e0 + e1;
            rs1 += e2 + e3;
            float u0 = __shfl_sync(~0u, e0, srcA);
            float u1 = __shfl_sync(~0u, e1, srcA);
            float u2 = __shfl_sync(~0u, e2, srcA);
            float u3 = __shfl_sync(~0u, e3, srcA);
            float v0 = __shfl_sync(~0u, e0, srcA + 2);
            float v1 = __shfl_sync(~0u, e1, srcA + 2);
            float v2 = __shfl_sync(~0u, e2, srcA + 2);
            float v3 = __shfl_sync(~0u, e3, srcA + 2);
            pa[m8][0] = odd ? u1 : u0;
            pa[m8][1] = odd ? u3 : u2;
            pa[m8][2] = odd ? v1 : v0;
            pa[m8][3] = odd ? v3 : v2;
        }

        // ---- O += P V^T ----
#pragma unroll
        for (int d8 = 0; d8 < 16; d8++) {
            const float* Vb = &Vs[(d8 * 8 + g) * 68];
#pragma unroll
            for (int km = 0; km < 8; km++) {
                uint32_t b0 = __float_as_uint(Vb[km * 8 + t]);
                uint32_t b1 = __float_as_uint(Vb[km * 8 + t + 4]);
                mma8(oacc[d8], pa[km], b0, b1);
            }
        }
        __syncthreads();

        // ---- prefetch tile mt+2 into this buffer ----
        if (mt + 2 < 16) {
            const int m0 = (mt + 2) * 64;
#pragma unroll
            for (int p = 0; p < 8; p++) {
                int idx = tid + p * 256;
                int r = idx >> 5, c = (idx & 31) << 2;
                cpa16(ka[bsel] + (uint32_t)(r * 132 + c) * 4,
                      &Kg[(size_t)(m0 + r) * CDIM + c]);
            }
#pragma unroll
            for (int p = 0; p < 8; p++) {
                int idx = tid + p * 256;
                int r = idx >> 4, c = (idx & 15) << 2;
                cpa16(va[bsel] + (uint32_t)(r * 68 + c) * 4,
                      &Vg[(size_t)r * HWN + m0 + c]);
            }
        }
        CP_COMMIT();   // commit even if empty: keeps group accounting uniform
    }

    // ---- rowsum quad reduction ----
    rs0 += __shfl_xor_sync(~0u, rs0, 1);
    rs0 += __shfl_xor_sync(~0u, rs0, 2);
    rs1 += __shfl_xor_sync(~0u, rs1, 1);
    rs1 += __shfl_xor_sync(~0u, rs1, 2);
    const float ri0 = 1.f / rs0, ri1 = 1.f / rs1;

    // ---- epilogue: write wsv[b, h*128 + n>>3, (n&7)*128 + d] ----
    const int nA = n0 + w * 16 + g;
    const int nB = nA + 8;
    const size_t obA = ((size_t)b * EXPD + h * CDIM + (nA >> 3)) * HWN
                     + (size_t)(nA & 7) * CDIM;
    const size_t obB = ((size_t)b * EXPD + h * CDIM + (nB >> 3)) * HWN
                     + (size_t)(nB & 7) * CDIM;
#pragma unroll
    for (int d8 = 0; d8 < 16; d8++) {
        int d = d8 * 8 + 2 * t;
        *(float2*)&gwsv[obA + d] = make_float2(oacc[d8][0] * ri0,
                                               oacc[d8][1] * ri0);
        *(float2*)&gwsv[obB + d] = make_float2(oacc[d8][2] * ri1,
                                               oacc[d8][3] * ri1);
    }
}

// ---------------------------------------------------------------------------
extern "C" void kernel_launch(void* const* d_in, const int* in_sizes, int n_in,
                              void* d_out, int out_size)
{
    const float* x  = (const float*)d_in[0];
    const float* Wq = (const float*)d_in[1];
    const float* Wk = (const float*)d_in[2];
    const float* Wv = (const float*)d_in[3];
    const float* bv = (const float*)d_in[4];
    const float* Wt = (const float*)d_in[5];
    const float* bt = (const float*)d_in[6];
    float* out = (float*)d_out;

    float *pq, *pk, *pv, *pw;
    cudaGetSymbolAddress((void**)&pq, g_q);
    cudaGetSymbolAddress((void**)&pk, g_k);
    cudaGetSymbolAddress((void**)&pv, g_v);
    cudaGetSymbolAddress((void**)&pw, g_wsv);

    const int gsmem = (64 * 132 + 128 * 72) * 4;  // 70656 B
    cudaFuncSetAttribute(gemm_mma, cudaFuncAttributeMaxDynamicSharedMemorySize,
                         gsmem);

    // QKV projections (tf32 mma): Q,K transposed-store [b,h,n,d]; V natural
    dim3 gqkv(HWN / 64, EXPD / 64, NB);
    gemm_mma<<<gqkv, 256, gsmem>>>(Wq, x, nullptr, nullptr, pq, EXPD, CDIM, 1);
    gemm_mma<<<gqkv, 256, gsmem>>>(Wk, x, nullptr, nullptr, pk, EXPD, CDIM, 1);
    gemm_mma<<<gqkv, 256, gsmem>>>(Wv, x, bv,      nullptr, pv, EXPD, CDIM, 0);

    // tf32 mma.sync attention, double-buffered cp.async
    const int asmem = (2 * 8448 + 2 * 8704) * 4;  // 137216 B
    cudaFuncSetAttribute(attn_mma, cudaFuncAttributeMaxDynamicSharedMemorySize,
                         asmem);
    attn_mma<<<dim3(8, 4, NB), 256, asmem>>>(pq, pk, pv, pw);

    // Output projection + bias + residual (tf32 mma)
    dim3 gproj(HWN / 64, CDIM / 64, NB);
    gemm_mma<<<gproj, 256, gsmem>>>(Wt, pw, bt, x, out, CDIM, EXPD, 0);
}

// round 6
// speedup vs baseline: 6.9048x; 1.6222x over previous
#include <cuda_runtime.h>
#include <cuda_bf16.h>
#include <cstdint>

#define HWN 1024
#define CDIM 128
#define EXPD 512
#define NB   16

// Scratch (allocation-free rule: static __device__ arrays)
__device__ __align__(128) __nv_bfloat16 g_q[NB * EXPD * HWN]; // [b][h][n][d]
__device__ __align__(128) __nv_bfloat16 g_k[NB * EXPD * HWN]; // [b][h][m][d]
__device__ __align__(128) __nv_bfloat16 g_v[NB * EXPD * HWN]; // [b][h][d][m]
__device__ __align__(128) float         g_wsv[NB * EXPD * HWN]; // [b][c'][pix]

// ---------------------------------------------------------------------------
__device__ __forceinline__ uint32_t smem_u32(const void* p) {
    uint32_t a;
    asm("{ .reg .u64 t; cvta.to.shared.u64 t, %1; cvt.u32.u64 %0, t; }"
        : "=r"(a) : "l"(p));
    return a;
}

__device__ __forceinline__ void cpa16(uint32_t dst, const void* src) {
    asm volatile("cp.async.ca.shared.global [%0], [%1], 16;"
                 :: "r"(dst), "l"(src));
}
#define CP_COMMIT() asm volatile("cp.async.commit_group;")
#define CP_WAIT0()  asm volatile("cp.async.wait_group 0;")
#define CP_WAIT1()  asm volatile("cp.async.wait_group 1;")

// f32 accum tf32 mma (GEMMs)
__device__ __forceinline__ void mma8(float (&d)[4], const float (&a)[4],
                                     uint32_t b0, uint32_t b1) {
    asm volatile(
        "mma.sync.aligned.m16n8k8.row.col.f32.tf32.tf32.f32 "
        "{%0,%1,%2,%3}, {%4,%5,%6,%7}, {%8,%9}, {%0,%1,%2,%3};"
        : "+f"(d[0]), "+f"(d[1]), "+f"(d[2]), "+f"(d[3])
        : "r"(__float_as_uint(a[0])), "r"(__float_as_uint(a[1])),
          "r"(__float_as_uint(a[2])), "r"(__float_as_uint(a[3])),
          "r"(b0), "r"(b1));
}

// bf16 m16n8k16 mma (attention)
__device__ __forceinline__ void mma16(float (&d)[4], const uint32_t (&a)[4],
                                      uint32_t b0, uint32_t b1) {
    asm volatile(
        "mma.sync.aligned.m16n8k16.row.col.f32.bf16.bf16.f32 "
        "{%0,%1,%2,%3}, {%4,%5,%6,%7}, {%8,%9}, {%0,%1,%2,%3};"
        : "+f"(d[0]), "+f"(d[1]), "+f"(d[2]), "+f"(d[3])
        : "r"(a[0]), "r"(a[1]), "r"(a[2]), "r"(a[3]), "r"(b0), "r"(b1));
}

__device__ __forceinline__ uint32_t packbf(float lo, float hi) {
    uint32_t d;
    asm("cvt.rn.bf16x2.f32 %0, %1, %2;" : "=r"(d) : "f"(hi), "f"(lo));
    return d;
}

__device__ __forceinline__ float ex2a(float x) {
    float r;
    asm("ex2.approx.ftz.f32 %0, %1;" : "=f"(r) : "f"(x));
    return r;
}

// ---------------------------------------------------------------------------
// tf32 mma GEMM: C[z] (M x 1024) = A (M x K) * B[z] (K x 1024)
// CTA tile 64x64, K chunks of 128, 8 warps = 2(o) x 4(n).
// mode 0: f32 C[z][o][n] (+bias +resid)           -> final projection
// mode 1: bf16 transposed C[z][o>>7][n][o&127]    -> q, k
// mode 2: bf16 C[z][o][n] (+bias)                 -> v
// ---------------------------------------------------------------------------
__global__ __launch_bounds__(256) void gemm_mma(
    const float* __restrict__ A, const float* __restrict__ Bbase,
    const float* __restrict__ bias, const float* __restrict__ resid,
    void* __restrict__ Cout, int M, int K, int mode)
{
    extern __shared__ float sh[];
    float* Ws = sh;              // [64][132]
    float* Xs = sh + 64 * 132;   // [128][72]
    const uint32_t ws_a = smem_u32(Ws), xs_a = smem_u32(Xs);

    const int z = blockIdx.z;
    const float* B = Bbase + (size_t)z * K * HWN;
    const int n0 = blockIdx.x * 64;
    const int o0 = blockIdx.y * 64;
    const int tid = threadIdx.x;
    const int w = tid >> 5, lane = tid & 31;
    const int g = lane >> 2, t = lane & 3;
    const int wo = w >> 2, wn = w & 3;

    float acc[2][2][4] = {};

    for (int k0 = 0; k0 < K; k0 += 128) {
#pragma unroll
        for (int p = 0; p < 8; p++) {
            int idx = tid + p * 256;
            int r = idx >> 5, c = (idx & 31) << 2;
            cpa16(ws_a + (uint32_t)(r * 132 + c) * 4,
                  &A[(size_t)(o0 + r) * K + k0 + c]);
        }
#pragma unroll
        for (int p = 0; p < 8; p++) {
            int idx = tid + p * 256;
            int k = idx >> 4, n4 = (idx & 15) << 2;
            cpa16(xs_a + (uint32_t)(k * 72 + n4) * 4,
                  &B[(size_t)(k0 + k) * HWN + n0 + n4]);
        }
        CP_COMMIT();
        CP_WAIT0();
        __syncthreads();

#pragma unroll
        for (int kk = 0; kk < 16; kk++) {
            float a[2][4];
            uint32_t bf[2][2];
#pragma unroll
            for (int i = 0; i < 2; i++) {
                const float* wr = &Ws[(wo * 32 + i * 16 + g) * 132 + kk * 8];
                a[i][0] = wr[t];
                a[i][1] = wr[8 * 132 + t];
                a[i][2] = wr[t + 4];
                a[i][3] = wr[8 * 132 + t + 4];
            }
#pragma unroll
            for (int j = 0; j < 2; j++) {
                bf[j][0] = __float_as_uint(Xs[(kk * 8 + t) * 72 + wn * 16 + j * 8 + g]);
                bf[j][1] = __float_as_uint(Xs[(kk * 8 + t + 4) * 72 + wn * 16 + j * 8 + g]);
            }
#pragma unroll
            for (int i = 0; i < 2; i++)
#pragma unroll
                for (int j = 0; j < 2; j++)
                    mma8(acc[i][j], a[i], bf[j][0], bf[j][1]);
        }
        __syncthreads();
    }

    if (mode == 0) {
        float* C = (float*)Cout;
#pragma unroll
        for (int i = 0; i < 2; i++) {
            int ob = o0 + wo * 32 + i * 16 + g;
#pragma unroll
            for (int rr = 0; rr < 2; rr++) {
                int orow = ob + rr * 8;
                float bi = bias ? bias[orow] : 0.f;
#pragma unroll
                for (int j = 0; j < 2; j++) {
                    int n = n0 + wn * 16 + j * 8 + 2 * t;
                    size_t addr = (size_t)z * M * HWN + (size_t)orow * HWN + n;
                    float2 v = make_float2(acc[i][j][rr * 2 + 0] + bi,
                                           acc[i][j][rr * 2 + 1] + bi);
                    float2 x2 = *(const float2*)&resid[addr];
                    v.x += x2.x; v.y += x2.y;
                    *(float2*)&C[addr] = v;
                }
            }
        }
    } else if (mode == 2) {
        __nv_bfloat16* C = (__nv_bfloat16*)Cout;
#pragma unroll
        for (int i = 0; i < 2; i++) {
            int ob = o0 + wo * 32 + i * 16 + g;
#pragma unroll
            for (int rr = 0; rr < 2; rr++) {
                int orow = ob + rr * 8;
                float bi = bias ? bias[orow] : 0.f;
#pragma unroll
                for (int j = 0; j < 2; j++) {
                    int n = n0 + wn * 16 + j * 8 + 2 * t;
                    size_t addr = (size_t)z * M * HWN + (size_t)orow * HWN + n;
                    *(uint32_t*)&C[addr] = packbf(acc[i][j][rr * 2 + 0] + bi,
                                                  acc[i][j][rr * 2 + 1] + bi);
                }
            }
        }
    } else {
        // transpose stage: Cs[n 64][o 68]
        float* Cs = sh;
#pragma unroll
        for (int i = 0; i < 2; i++) {
            int ol = wo * 32 + i * 16 + g;
#pragma unroll
            for (int j = 0; j < 2; j++) {
                int nl = wn * 16 + j * 8 + 2 * t;
                Cs[nl * 68 + ol]           = acc[i][j][0];
                Cs[(nl + 1) * 68 + ol]     = acc[i][j][1];
                Cs[nl * 68 + ol + 8]       = acc[i][j][2];
                Cs[(nl + 1) * 68 + ol + 8] = acc[i][j][3];
            }
        }
        __syncthreads();
        __nv_bfloat16* C = (__nv_bfloat16*)Cout;
        const int head = o0 >> 7, d0 = o0 & 127;
#pragma unroll
        for (int p = 0; p < 4; p++) {
            int idx = p * 256 + tid;
            int nl = idx >> 4, o4 = (idx & 15) * 4;
            float4 v = *(float4*)&Cs[nl * 68 + o4];
            uint2 pk = make_uint2(packbf(v.x, v.y), packbf(v.z, v.w));
            *(uint2*)&C[(((size_t)z * 4 + head) * HWN + n0 + nl) * CDIM + d0 + o4] = pk;
        }
    }
}

// ---------------------------------------------------------------------------
// Attention, bf16 m16n8k16 mma, cp.async double-buffered K/V.
// One CTA = (b, h, 128-query tile), 8 warps; warp owns 16 q-rows.
// S-accumulator layout == P A-fragment layout => zero-shuffle P conversion.
// Exact softmax w/o max-subtraction (scale*log2e folded into ex2);
// 1/rowsum folded into epilogue.
// ---------------------------------------------------------------------------
__global__ __launch_bounds__(256, 1) void attn_mma(
    const __nv_bfloat16* __restrict__ gq, const __nv_bfloat16* __restrict__ gk,
    const __nv_bfloat16* __restrict__ gv, float* __restrict__ gwsv)
{
    extern __shared__ __nv_bfloat16 smb[];
    __nv_bfloat16* Kb[2] = {smb, smb + 8704};            // [64][136] each
    __nv_bfloat16* Vb[2] = {smb + 17408, smb + 26624};   // [128][72] each
    const uint32_t ka[2] = {smem_u32(Kb[0]), smem_u32(Kb[1])};
    const uint32_t va[2] = {smem_u32(Vb[0]), smem_u32(Vb[1])};

    const int tid = threadIdx.x;
    const int w = tid >> 5, lane = tid & 31;
    const int g = lane >> 2, t = lane & 3;
    const int b = blockIdx.z, h = blockIdx.y;
    const int bh = b * 4 + h;
    const int n0 = blockIdx.x * 128;
    // 1/sqrt(128) * log2(e)
    const float CEXP = 0.08838834764831843f * 1.4426950408889634f;

    const __nv_bfloat16* Qg = gq + ((size_t)bh * HWN + n0) * CDIM;
    const __nv_bfloat16* Kg = gk + (size_t)bh * HWN * CDIM;
    const __nv_bfloat16* Vg = gv + (size_t)bh * CDIM * HWN;

    // ---- stage Q [128][136] bf16 across both K buffers (contiguous) ----
#pragma unroll
    for (int p = 0; p < 8; p++) {
        int idx = tid + p * 256;
        int r = idx >> 4, c = idx & 15;
        cpa16(ka[0] + (uint32_t)(r * 272 + c * 16), &Qg[(size_t)r * CDIM + c * 8]);
    }
    CP_COMMIT();
    CP_WAIT0();
    __syncthreads();

    // ---- persistent Q A-fragments: 8 k16-chunks x 4 bf16x2 regs ----
    uint32_t qa[8][4];
    {
        const __nv_bfloat16* q0 = smb + (w * 16 + g) * 136;
        const __nv_bfloat16* q8 = q0 + 8 * 136;
#pragma unroll
        for (int k = 0; k < 8; k++) {
            qa[k][0] = *(const uint32_t*)&q0[k * 16 + 2 * t];
            qa[k][1] = *(const uint32_t*)&q8[k * 16 + 2 * t];
            qa[k][2] = *(const uint32_t*)&q0[k * 16 + 8 + 2 * t];
            qa[k][3] = *(const uint32_t*)&q8[k * 16 + 8 + 2 * t];
        }
    }
    __syncthreads();

    // ---- prefetch tiles 0,1 ----
#pragma unroll
    for (int mt = 0; mt < 2; mt++) {
        const int m0 = mt * 64;
#pragma unroll
        for (int p = 0; p < 4; p++) {
            int idx = tid + p * 256;
            int r = idx >> 4, c = idx & 15;
            cpa16(ka[mt] + (uint32_t)(r * 272 + c * 16),
                  &Kg[(size_t)(m0 + r) * CDIM + c * 8]);
        }
#pragma unroll
        for (int p = 0; p < 4; p++) {
            int idx = tid + p * 256;
            int r = idx >> 3, c = idx & 7;
            cpa16(va[mt] + (uint32_t)(r * 144 + c * 16),
                  &Vg[(size_t)r * HWN + m0 + c * 8]);
        }
        CP_COMMIT();
    }

    float oacc[16][4] = {};
    float rs0 = 0.f, rs1 = 0.f;

    for (int mt = 0; mt < 16; mt++) {
        const int bsel = mt & 1;
        if (mt < 15) { CP_WAIT1(); } else { CP_WAIT0(); }
        __syncthreads();

        const __nv_bfloat16* Ks = Kb[bsel];
        const __nv_bfloat16* Vs = Vb[bsel];

        // ---- S = Q K^T, exp, pack straight into P A-fragments ----
        uint32_t pa[4][4];   // [km][areg]
#pragma unroll
        for (int m8 = 0; m8 < 8; m8++) {
            float s[4] = {0.f, 0.f, 0.f, 0.f};
            const __nv_bfloat16* Kr = &Ks[(m8 * 8 + g) * 136];
#pragma unroll
            for (int k = 0; k < 8; k++) {
                uint32_t b0 = *(const uint32_t*)&Kr[k * 16 + 2 * t];
                uint32_t b1 = *(const uint32_t*)&Kr[k * 16 + 8 + 2 * t];
                mma16(s, qa[k], b0, b1);
            }
            float e0 = ex2a(s[0] * CEXP), e1 = ex2a(s[1] * CEXP);
            float e2 = ex2a(s[2] * CEXP), e3 = ex2a(s[3] * CEXP);
            rs0 += e0 + e1;
            rs1 += e2 + e3;
            int km = m8 >> 1, hi = (m8 & 1) * 2;
            pa[km][hi + 0] = packbf(e0, e1);   // rows g
            pa[km][hi + 1] = packbf(e2, e3);   // rows g+8
        }
        // reorder pa to PTX A-frag order {a0,a1,a2,a3} = {g/lo, g+8/lo, g/hi, g+8/hi}
        // pa as filled: [0]=g lo-half, [1]=g+8 lo-half, [2]=g hi-half, [3]=g+8 hi-half
        // (hi offset 2 gives exactly a2,a3) -> already correct.

        // ---- O += P V^T ----
#pragma unroll
        for (int d8 = 0; d8 < 16; d8++) {
            const __nv_bfloat16* Vr = &Vs[(d8 * 8 + g) * 72];
#pragma unroll
            for (int km = 0; km < 4; km++) {
                uint32_t b0 = *(const uint32_t*)&Vr[km * 16 + 2 * t];
                uint32_t b1 = *(const uint32_t*)&Vr[km * 16 + 8 + 2 * t];
                mma16(oacc[d8], pa[km], b0, b1);
            }
        }
        __syncthreads();

        // ---- prefetch tile mt+2 ----
        if (mt + 2 < 16) {
            const int m0 = (mt + 2) * 64;
#pragma unroll
            for (int p = 0; p < 4; p++) {
                int idx = tid + p * 256;
                int r = idx >> 4, c = idx & 15;
                cpa16(ka[bsel] + (uint32_t)(r * 272 + c * 16),
                      &Kg[(size_t)(m0 + r) * CDIM + c * 8]);
            }
#pragma unroll
            for (int p = 0; p < 4; p++) {
                int idx = tid + p * 256;
                int r = idx >> 3, c = idx & 7;
                cpa16(va[bsel] + (uint32_t)(r * 144 + c * 16),
                      &Vg[(size_t)r * HWN + m0 + c * 8]);
            }
        }
        CP_COMMIT();
    }

    // ---- rowsum quad reduction ----
    rs0 += __shfl_xor_sync(~0u, rs0, 1);
    rs0 += __shfl_xor_sync(~0u, rs0, 2);
    rs1 += __shfl_xor_sync(~0u, rs1, 1);
    rs1 += __shfl_xor_sync(~0u, rs1, 2);
    const float ri0 = 1.f / rs0, ri1 = 1.f / rs1;

    // ---- epilogue: wsv[b, h*128 + n>>3, (n&7)*128 + d] ----
    const int nA = n0 + w * 16 + g;
    const int nB = nA + 8;
    const size_t obA = ((size_t)b * EXPD + h * CDIM + (nA >> 3)) * HWN
                     + (size_t)(nA & 7) * CDIM;
    const size_t obB = ((size_t)b * EXPD + h * CDIM + (nB >> 3)) * HWN
                     + (size_t)(nB & 7) * CDIM;
#pragma unroll
    for (int d8 = 0; d8 < 16; d8++) {
        int d = d8 * 8 + 2 * t;
        *(float2*)&gwsv[obA + d] = make_float2(oacc[d8][0] * ri0,
                                               oacc[d8][1] * ri0);
        *(float2*)&gwsv[obB + d] = make_float2(oacc[d8][2] * ri1,
                                               oacc[d8][3] * ri1);
    }
}

// ---------------------------------------------------------------------------
extern "C" void kernel_launch(void* const* d_in, const int* in_sizes, int n_in,
                              void* d_out, int out_size)
{
    const float* x  = (const float*)d_in[0];
    const float* Wq = (const float*)d_in[1];
    const float* Wk = (const float*)d_in[2];
    const float* Wv = (const float*)d_in[3];
    const float* bv = (const float*)d_in[4];
    const float* Wt = (const float*)d_in[5];
    const float* bt = (const float*)d_in[6];
    float* out = (float*)d_out;

    __nv_bfloat16 *pq, *pk, *pv;
    float* pw;
    cudaGetSymbolAddress((void**)&pq, g_q);
    cudaGetSymbolAddress((void**)&pk, g_k);
    cudaGetSymbolAddress((void**)&pv, g_v);
    cudaGetSymbolAddress((void**)&pw, g_wsv);

    const int gsmem = (64 * 132 + 128 * 72) * 4;  // 70656 B
    cudaFuncSetAttribute(gemm_mma, cudaFuncAttributeMaxDynamicSharedMemorySize,
                         gsmem);

    // QKV projections (tf32 mma, bf16 out): Q,K transposed [b,h,n,d]; V [b,h,d,m]
    dim3 gqkv(HWN / 64, EXPD / 64, NB);
    gemm_mma<<<gqkv, 256, gsmem>>>(Wq, x, nullptr, nullptr, pq, EXPD, CDIM, 1);
    gemm_mma<<<gqkv, 256, gsmem>>>(Wk, x, nullptr, nullptr, pk, EXPD, CDIM, 1);
    gemm_mma<<<gqkv, 256, gsmem>>>(Wv, x, bv,      nullptr, pv, EXPD, CDIM, 2);

    // bf16 mma.sync attention, double-buffered cp.async
    const int asmem = (2 * 8704 + 2 * 9216) * 2;  // 71680 B
    cudaFuncSetAttribute(attn_mma, cudaFuncAttributeMaxDynamicSharedMemorySize,
                         asmem);
    attn_mma<<<dim3(8, 4, NB), 256, asmem>>>(pq, pk, pv, pw);

    // Output projection + bias + residual (tf32 mma, f32 out)
    dim3 gproj(HWN / 64, CDIM / 64, NB);
    gemm_mma<<<gproj, 256, gsmem>>>(Wt, pw, bt, x, out, CDIM, EXPD, 0);
}

// round 7
// speedup vs baseline: 7.6978x; 1.1148x over previous
#include <cuda_runtime.h>
#include <cuda_bf16.h>
#include <cstdint>

#define HWN 1024
#define CDIM 128
#define EXPD 512
#define NB   16

// Scratch (allocation-free rule: static __device__ arrays)
__device__ __align__(128) __nv_bfloat16 g_q[NB * EXPD * HWN]; // [b][h][n][d]
__device__ __align__(128) __nv_bfloat16 g_k[NB * EXPD * HWN]; // [b][h][m][d]
__device__ __align__(128) __nv_bfloat16 g_v[NB * EXPD * HWN]; // [b][h][d][m]
__device__ __align__(128) float         g_wsv[NB * EXPD * HWN]; // [b][c'][pix]

// ---------------------------------------------------------------------------
__device__ __forceinline__ uint32_t smem_u32(const void* p) {
    uint32_t a;
    asm("{ .reg .u64 t; cvta.to.shared.u64 t, %1; cvt.u32.u64 %0, t; }"
        : "=r"(a) : "l"(p));
    return a;
}

__device__ __forceinline__ void cpa16(uint32_t dst, const void* src) {
    asm volatile("cp.async.ca.shared.global [%0], [%1], 16;"
                 :: "r"(dst), "l"(src));
}
#define CP_COMMIT() asm volatile("cp.async.commit_group;")
#define CP_WAIT0()  asm volatile("cp.async.wait_group 0;")
#define CP_WAIT1()  asm volatile("cp.async.wait_group 1;")
#define BARX()      asm volatile("bar.sync 0, 512;" ::: "memory")

// f32 accum tf32 mma (GEMMs)
__device__ __forceinline__ void mma8(float (&d)[4], const float (&a)[4],
                                     uint32_t b0, uint32_t b1) {
    asm volatile(
        "mma.sync.aligned.m16n8k8.row.col.f32.tf32.tf32.f32 "
        "{%0,%1,%2,%3}, {%4,%5,%6,%7}, {%8,%9}, {%0,%1,%2,%3};"
        : "+f"(d[0]), "+f"(d[1]), "+f"(d[2]), "+f"(d[3])
        : "r"(__float_as_uint(a[0])), "r"(__float_as_uint(a[1])),
          "r"(__float_as_uint(a[2])), "r"(__float_as_uint(a[3])),
          "r"(b0), "r"(b1));
}

// bf16 m16n8k16 mma (attention)
__device__ __forceinline__ void mma16(float (&d)[4], const uint32_t (&a)[4],
                                      uint32_t b0, uint32_t b1) {
    asm volatile(
        "mma.sync.aligned.m16n8k16.row.col.f32.bf16.bf16.f32 "
        "{%0,%1,%2,%3}, {%4,%5,%6,%7}, {%8,%9}, {%0,%1,%2,%3};"
        : "+f"(d[0]), "+f"(d[1]), "+f"(d[2]), "+f"(d[3])
        : "r"(a[0]), "r"(a[1]), "r"(a[2]), "r"(a[3]), "r"(b0), "r"(b1));
}

__device__ __forceinline__ uint32_t packbf(float lo, float hi) {
    uint32_t d;
    asm("cvt.rn.bf16x2.f32 %0, %1, %2;" : "=r"(d) : "f"(hi), "f"(lo));
    return d;
}

__device__ __forceinline__ float ex2a(float x) {
    float r;
    asm("ex2.approx.ftz.f32 %0, %1;" : "=f"(r) : "f"(x));
    return r;
}

// ---------------------------------------------------------------------------
// Fused QKV GEMM (tf32 mma): loads each x tile once, runs Wq/Wk/Wv against it
// with a double-buffered weight pipeline.
//   q,k: bf16 transposed store [z][o>>7][n][o&127]
//   v  : bf16 natural [z][o][n] + bias
// CTA tile 64(o) x 64(n), K=128 (one chunk). 8 warps = 2(o) x 4(n).
// ---------------------------------------------------------------------------
__global__ __launch_bounds__(256) void gemm_qkv(
    const float* __restrict__ x,
    const float* __restrict__ Wq, const float* __restrict__ Wk,
    const float* __restrict__ Wv, const float* __restrict__ bv,
    __nv_bfloat16* __restrict__ qo, __nv_bfloat16* __restrict__ ko,
    __nv_bfloat16* __restrict__ vo)
{
    extern __shared__ float sh[];
    float* Xs = sh;                       // [128][72] = 9216 floats
    float* WsA[2] = {sh + 9216, sh + 9216 + 8448};  // [64][132] each
    const uint32_t xs_a = smem_u32(Xs);
    const uint32_t ws_a[2] = {smem_u32(WsA[0]), smem_u32(WsA[1])};

    const int z = blockIdx.z;
    const int n0 = blockIdx.x * 64;
    const int o0 = blockIdx.y * 64;
    const int tid = threadIdx.x;
    const int w = tid >> 5, lane = tid & 31;
    const int g = lane >> 2, t = lane & 3;
    const int wo = w >> 2, wn = w & 3;

    const float* Wmat[3] = {Wq, Wk, Wv};
    const float* xb = x + (size_t)z * CDIM * HWN;

    // initial loads: Xs (x tile 128k x 64n) + Ws[0] (Wq tile)  -> group 0
#pragma unroll
    for (int p = 0; p < 8; p++) {
        int idx = tid + p * 256;
        int kk = idx >> 4, c = (idx & 15) << 2;
        cpa16(xs_a + (uint32_t)(kk * 72 + c) * 4, &xb[(size_t)kk * HWN + n0 + c]);
    }
#pragma unroll
    for (int p = 0; p < 8; p++) {
        int idx = tid + p * 256;
        int r = idx >> 5, c = (idx & 31) << 2;
        cpa16(ws_a[0] + (uint32_t)(r * 132 + c) * 4, &Wq[(size_t)(o0 + r) * CDIM + c]);
    }
    CP_COMMIT();

    for (int mat = 0; mat < 3; mat++) {
        if (mat < 2) {
            const float* Wn = Wmat[mat + 1];
#pragma unroll
            for (int p = 0; p < 8; p++) {
                int idx = tid + p * 256;
                int r = idx >> 5, c = (idx & 31) << 2;
                cpa16(ws_a[(mat + 1) & 1] + (uint32_t)(r * 132 + c) * 4,
                      &Wn[(size_t)(o0 + r) * CDIM + c]);
            }
            CP_COMMIT();
            CP_WAIT1();
        } else {
            CP_WAIT0();
        }
        __syncthreads();

        const float* Wcur = WsA[mat & 1];
        float acc[2][2][4] = {};
#pragma unroll
        for (int kk = 0; kk < 16; kk++) {
            float a[2][4];
            uint32_t bf[2][2];
#pragma unroll
            for (int i = 0; i < 2; i++) {
                const float* wr = &Wcur[(wo * 32 + i * 16 + g) * 132 + kk * 8];
                a[i][0] = wr[t];
                a[i][1] = wr[8 * 132 + t];
                a[i][2] = wr[t + 4];
                a[i][3] = wr[8 * 132 + t + 4];
            }
#pragma unroll
            for (int j = 0; j < 2; j++) {
                bf[j][0] = __float_as_uint(Xs[(kk * 8 + t) * 72 + wn * 16 + j * 8 + g]);
                bf[j][1] = __float_as_uint(Xs[(kk * 8 + t + 4) * 72 + wn * 16 + j * 8 + g]);
            }
#pragma unroll
            for (int i = 0; i < 2; i++)
#pragma unroll
                for (int j = 0; j < 2; j++)
                    mma8(acc[i][j], a[i], bf[j][0], bf[j][1]);
        }
        __syncthreads();   // done reading Wcur (about to reuse it as Cs)

        if (mat < 2) {
            // transposed bf16 store via smem transpose stage Cs[n 64][o 68]
            float* Cs = WsA[mat & 1];
#pragma unroll
            for (int i = 0; i < 2; i++) {
                int ol = wo * 32 + i * 16 + g;
#pragma unroll
                for (int j = 0; j < 2; j++) {
                    int nl = wn * 16 + j * 8 + 2 * t;
                    Cs[nl * 68 + ol]           = acc[i][j][0];
                    Cs[(nl + 1) * 68 + ol]     = acc[i][j][1];
                    Cs[nl * 68 + ol + 8]       = acc[i][j][2];
                    Cs[(nl + 1) * 68 + ol + 8] = acc[i][j][3];
                }
            }
            __syncthreads();
            __nv_bfloat16* C = (mat == 0) ? qo : ko;
            const int head = o0 >> 7, d0 = o0 & 127;
#pragma unroll
            for (int p = 0; p < 4; p++) {
                int idx = p * 256 + tid;
                int nl = idx >> 4, o4 = (idx & 15) * 4;
                float4 vv = *(float4*)&Cs[nl * 68 + o4];
                uint2 pk = make_uint2(packbf(vv.x, vv.y), packbf(vv.z, vv.w));
                *(uint2*)&C[(((size_t)z * 4 + head) * HWN + n0 + nl) * CDIM + d0 + o4] = pk;
            }
            __syncthreads();   // Cs reads done before next mat's cp.async overwrites
        } else {
            // v: bf16 natural + bias
#pragma unroll
            for (int i = 0; i < 2; i++) {
                int ob = o0 + wo * 32 + i * 16 + g;
#pragma unroll
                for (int rr = 0; rr < 2; rr++) {
                    int orow = ob + rr * 8;
                    float bi = bv[orow];
#pragma unroll
                    for (int j = 0; j < 2; j++) {
                        int n = n0 + wn * 16 + j * 8 + 2 * t;
                        size_t addr = (size_t)z * EXPD * HWN + (size_t)orow * HWN + n;
                        *(uint32_t*)&vo[addr] = packbf(acc[i][j][rr * 2 + 0] + bi,
                                                       acc[i][j][rr * 2 + 1] + bi);
                    }
                }
            }
        }
    }
}

// ---------------------------------------------------------------------------
// Projection GEMM (tf32 mma): out = Wt @ wsv + bt + x.  (mode-0 of old kernel)
// ---------------------------------------------------------------------------
__global__ __launch_bounds__(256) void gemm_proj(
    const float* __restrict__ A, const float* __restrict__ Bbase,
    const float* __restrict__ bias, const float* __restrict__ resid,
    float* __restrict__ C, int M, int K)
{
    extern __shared__ float sh[];
    float* Ws = sh;              // [64][132]
    float* Xs = sh + 64 * 132;   // [128][72]
    const uint32_t ws_a = smem_u32(Ws), xs_a = smem_u32(Xs);

    const int z = blockIdx.z;
    const float* B = Bbase + (size_t)z * K * HWN;
    const int n0 = blockIdx.x * 64;
    const int o0 = blockIdx.y * 64;
    const int tid = threadIdx.x;
    const int w = tid >> 5, lane = tid & 31;
    const int g = lane >> 2, t = lane & 3;
    const int wo = w >> 2, wn = w & 3;

    float acc[2][2][4] = {};

    for (int k0 = 0; k0 < K; k0 += 128) {
#pragma unroll
        for (int p = 0; p < 8; p++) {
            int idx = tid + p * 256;
            int r = idx >> 5, c = (idx & 31) << 2;
            cpa16(ws_a + (uint32_t)(r * 132 + c) * 4,
                  &A[(size_t)(o0 + r) * K + k0 + c]);
        }
#pragma unroll
        for (int p = 0; p < 8; p++) {
            int idx = tid + p * 256;
            int k = idx >> 4, n4 = (idx & 15) << 2;
            cpa16(xs_a + (uint32_t)(k * 72 + n4) * 4,
                  &B[(size_t)(k0 + k) * HWN + n0 + n4]);
        }
        CP_COMMIT();
        CP_WAIT0();
        __syncthreads();

#pragma unroll
        for (int kk = 0; kk < 16; kk++) {
            float a[2][4];
            uint32_t bf[2][2];
#pragma unroll
            for (int i = 0; i < 2; i++) {
                const float* wr = &Ws[(wo * 32 + i * 16 + g) * 132 + kk * 8];
                a[i][0] = wr[t];
                a[i][1] = wr[8 * 132 + t];
                a[i][2] = wr[t + 4];
                a[i][3] = wr[8 * 132 + t + 4];
            }
#pragma unroll
            for (int j = 0; j < 2; j++) {
                bf[j][0] = __float_as_uint(Xs[(kk * 8 + t) * 72 + wn * 16 + j * 8 + g]);
                bf[j][1] = __float_as_uint(Xs[(kk * 8 + t + 4) * 72 + wn * 16 + j * 8 + g]);
            }
#pragma unroll
            for (int i = 0; i < 2; i++)
#pragma unroll
                for (int j = 0; j < 2; j++)
                    mma8(acc[i][j], a[i], bf[j][0], bf[j][1]);
        }
        __syncthreads();
    }

#pragma unroll
    for (int i = 0; i < 2; i++) {
        int ob = o0 + wo * 32 + i * 16 + g;
#pragma unroll
        for (int rr = 0; rr < 2; rr++) {
            int orow = ob + rr * 8;
            float bi = bias[orow];
#pragma unroll
            for (int j = 0; j < 2; j++) {
                int n = n0 + wn * 16 + j * 8 + 2 * t;
                size_t addr = (size_t)z * M * HWN + (size_t)orow * HWN + n;
                float2 v = make_float2(acc[i][j][rr * 2 + 0] + bi,
                                       acc[i][j][rr * 2 + 1] + bi);
                float2 x2 = *(const float2*)&resid[addr];
                v.x += x2.x; v.y += x2.y;
                *(float2*)&C[addr] = v;
            }
        }
    }
}

// ---------------------------------------------------------------------------
// Warp-specialized attention (bf16 m16n8k16), 512 threads, 1 CTA = (b,h,128 q).
//   S-warps 0-7:  S = Q K^T -> exp -> packed P A-frags -> SMEM ring (per mt)
//   V-warps 8-15: O += P V^T one tile behind (skewed pipeline)
// K/V: 4-deep cp.async ring. P: double-buffered reg-major u32 [16][256].
// SMEM layout (bytes):
//   Kbuf[i] @ i*17408         (i<4, [64][136] bf16)   -> 69632
//   Vbuf[i] @ 69632+i*18432   (i<4, [128][72] bf16)   -> 143360
//   Pbuf    @ 143360          (2 x 16384 u32 bytes)   -> 176128
//   rinv    @ 176128          (128 f32)               -> 176640
// ---------------------------------------------------------------------------
__device__ __forceinline__ void pv_tile(float (&oacc)[16][4],
                                        const __nv_bfloat16* Vs,
                                        const uint32_t* Pr, int g, int t) {
    uint32_t pa[4][4];
#pragma unroll
    for (int r = 0; r < 16; r++)
        pa[r >> 2][r & 3] = Pr[r * 256];
#pragma unroll
    for (int d8 = 0; d8 < 16; d8++) {
        const __nv_bfloat16* Vr = &Vs[(d8 * 8 + g) * 72];
#pragma unroll
        for (int km = 0; km < 4; km++) {
            uint32_t b0 = *(const uint32_t*)&Vr[km * 16 + 2 * t];
            uint32_t b1 = *(const uint32_t*)&Vr[km * 16 + 8 + 2 * t];
            mma16(oacc[d8], pa[km], b0, b1);
        }
    }
}

__global__ __launch_bounds__(512, 1) void attn_mma(
    const __nv_bfloat16* __restrict__ gq, const __nv_bfloat16* __restrict__ gk,
    const __nv_bfloat16* __restrict__ gv, float* __restrict__ gwsv)
{
    extern __shared__ __nv_bfloat16 smb[];
    char* base = (char*)smb;
    const uint32_t sm_a = smem_u32(base);
    uint32_t* Pbuf = (uint32_t*)(base + 143360);
    float* rinv_s = (float*)(base + 176128);

    const int tid = threadIdx.x;
    const int w = tid >> 5, lane = tid & 31;
    const int g = lane >> 2, t = lane & 3;
    const int b = blockIdx.z, h = blockIdx.y;
    const int bh = b * 4 + h;
    const int n0 = blockIdx.x * 128;
    const float CEXP = 0.08838834764831843f * 1.4426950408889634f;

    const __nv_bfloat16* Qg = gq + ((size_t)bh * HWN + n0) * CDIM;
    const __nv_bfloat16* Kg = gk + (size_t)bh * HWN * CDIM;
    const __nv_bfloat16* Vg = gv + (size_t)bh * CDIM * HWN;

    // ---- stage Q [128][136] bf16 into Kbuf[0..1] region (all 512 threads) ----
#pragma unroll
    for (int p = 0; p < 4; p++) {
        int idx = tid + p * 512;
        int r = idx >> 4, c = idx & 15;
        cpa16(sm_a + (uint32_t)(r * 272 + c * 16), &Qg[(size_t)r * CDIM + c * 8]);
    }
    CP_COMMIT();
    CP_WAIT0();
    BARX();

    if (w < 8) {
        // ================= S-warps =================
        uint32_t qa[8][4];
        {
            const __nv_bfloat16* q0 = smb + (w * 16 + g) * 136;
            const __nv_bfloat16* q8 = q0 + 8 * 136;
#pragma unroll
            for (int k = 0; k < 8; k++) {
                qa[k][0] = *(const uint32_t*)&q0[k * 16 + 2 * t];
                qa[k][1] = *(const uint32_t*)&q8[k * 16 + 2 * t];
                qa[k][2] = *(const uint32_t*)&q0[k * 16 + 8 + 2 * t];
                qa[k][3] = *(const uint32_t*)&q8[k * 16 + 8 + 2 * t];
            }
        }
        BARX();

        // prefetch K tiles 0,1 (S threads: tid 0..255)
#pragma unroll
        for (int tt = 0; tt < 2; tt++) {
#pragma unroll
            for (int p = 0; p < 4; p++) {
                int idx = tid + p * 256;
                int r = idx >> 4, c = idx & 15;
                cpa16(sm_a + (uint32_t)(tt * 17408 + r * 272 + c * 16),
                      &Kg[(size_t)(tt * 64 + r) * CDIM + c * 8]);
            }
            CP_COMMIT();
        }

        float rs0 = 0.f, rs1 = 0.f;
        for (int mt = 0; mt < 16; mt++) {
            if (mt < 15) { CP_WAIT1(); } else { CP_WAIT0(); }
            BARX();

            const __nv_bfloat16* Ks =
                (const __nv_bfloat16*)(base + (mt & 3) * 17408);
            uint32_t* Pw = Pbuf + (mt & 1) * 4096 + w * 32 + lane;
#pragma unroll
            for (int m8 = 0; m8 < 8; m8++) {
                float s[4] = {0.f, 0.f, 0.f, 0.f};
                const __nv_bfloat16* Kr = &Ks[(m8 * 8 + g) * 136];
#pragma unroll
                for (int k = 0; k < 8; k++) {
                    uint32_t b0 = *(const uint32_t*)&Kr[k * 16 + 2 * t];
                    uint32_t b1 = *(const uint32_t*)&Kr[k * 16 + 8 + 2 * t];
                    mma16(s, qa[k], b0, b1);
                }
                float e0 = ex2a(s[0] * CEXP), e1 = ex2a(s[1] * CEXP);
                float e2 = ex2a(s[2] * CEXP), e3 = ex2a(s[3] * CEXP);
                rs0 += e0 + e1;
                rs1 += e2 + e3;
                int r = (m8 >> 1) * 4 + (m8 & 1) * 2;
                Pw[(r + 0) * 256] = packbf(e0, e1);   // rows g
                Pw[(r + 1) * 256] = packbf(e2, e3);   // rows g+8
            }

            if (mt + 2 < 16) {
                const int m0 = (mt + 2) * 64;
#pragma unroll
                for (int p = 0; p < 4; p++) {
                    int idx = tid + p * 256;
                    int r = idx >> 4, c = idx & 15;
                    cpa16(sm_a + (uint32_t)(((mt + 2) & 3) * 17408 + r * 272 + c * 16),
                          &Kg[(size_t)(m0 + r) * CDIM + c * 8]);
                }
            }
            CP_COMMIT();
        }
        BARX();   // V-warps do final PV(15); S-warps reduce rowsums
        rs0 += __shfl_xor_sync(~0u, rs0, 1);
        rs0 += __shfl_xor_sync(~0u, rs0, 2);
        rs1 += __shfl_xor_sync(~0u, rs1, 1);
        rs1 += __shfl_xor_sync(~0u, rs1, 2);
        if (t == 0) {
            rinv_s[w * 16 + g]     = 1.f / rs0;
            rinv_s[w * 16 + g + 8] = 1.f / rs1;
        }
        BARX();
    } else {
        // ================= V-warps =================
        const int v = w - 8;
        const int vt = tid - 256;
        BARX();   // matches S qa-extraction barrier

        // prefetch V tiles 0,1
#pragma unroll
        for (int tt = 0; tt < 2; tt++) {
#pragma unroll
            for (int p = 0; p < 4; p++) {
                int idx = vt + p * 256;
                int r = idx >> 3, c = idx & 7;
                cpa16(sm_a + (uint32_t)(69632 + tt * 18432 + r * 144 + c * 16),
                      &Vg[(size_t)r * HWN + tt * 64 + c * 8]);
            }
            CP_COMMIT();
        }

        float oacc[16][4] = {};
        for (int mt = 0; mt < 16; mt++) {
            if (mt < 15) { CP_WAIT1(); } else { CP_WAIT0(); }
            BARX();

            if (mt >= 1) {
                const __nv_bfloat16* Vs =
                    (const __nv_bfloat16*)(base + 69632 + ((mt - 1) & 3) * 18432);
                const uint32_t* Pr = Pbuf + ((mt - 1) & 1) * 4096 + v * 32 + lane;
                pv_tile(oacc, Vs, Pr, g, t);
            }

            if (mt + 2 < 16) {
                const int m0 = (mt + 2) * 64;
#pragma unroll
                for (int p = 0; p < 4; p++) {
                    int idx = vt + p * 256;
                    int r = idx >> 3, c = idx & 7;
                    cpa16(sm_a + (uint32_t)(69632 + ((mt + 2) & 3) * 18432 + r * 144 + c * 16),
                          &Vg[(size_t)r * HWN + m0 + c * 8]);
                }
            }
            CP_COMMIT();
        }
        BARX();
        {   // final PV(15)
            const __nv_bfloat16* Vs =
                (const __nv_bfloat16*)(base + 69632 + 3 * 18432);
            const uint32_t* Pr = Pbuf + 4096 + v * 32 + lane;
            pv_tile(oacc, Vs, Pr, g, t);
        }
        BARX();   // rinv ready

        const float ri0 = rinv_s[v * 16 + g];
        const float ri1 = rinv_s[v * 16 + g + 8];
        const int nA = n0 + v * 16 + g;
        const int nB = nA + 8;
        const size_t obA = ((size_t)b * EXPD + h * CDIM + (nA >> 3)) * HWN
                         + (size_t)(nA & 7) * CDIM;
        const size_t obB = ((size_t)b * EXPD + h * CDIM + (nB >> 3)) * HWN
                         + (size_t)(nB & 7) * CDIM;
#pragma unroll
        for (int d8 = 0; d8 < 16; d8++) {
            int d = d8 * 8 + 2 * t;
            *(float2*)&gwsv[obA + d] = make_float2(oacc[d8][0] * ri0,
                                                   oacc[d8][1] * ri0);
            *(float2*)&gwsv[obB + d] = make_float2(oacc[d8][2] * ri1,
                                                   oacc[d8][3] * ri1);
        }
    }
}

// ---------------------------------------------------------------------------
extern "C" void kernel_launch(void* const* d_in, const int* in_sizes, int n_in,
                              void* d_out, int out_size)
{
    const float* x  = (const float*)d_in[0];
    const float* Wq = (const float*)d_in[1];
    const float* Wk = (const float*)d_in[2];
    const float* Wv = (const float*)d_in[3];
    const float* bv = (const float*)d_in[4];
    const float* Wt = (const float*)d_in[5];
    const float* bt = (const float*)d_in[6];
    float* out = (float*)d_out;

    __nv_bfloat16 *pq, *pk, *pv;
    float* pw;
    cudaGetSymbolAddress((void**)&pq, g_q);
    cudaGetSymbolAddress((void**)&pk, g_k);
    cudaGetSymbolAddress((void**)&pv, g_v);
    cudaGetSymbolAddress((void**)&pw, g_wsv);

    // Fused QKV projections
    const int qkvsmem = (9216 + 2 * 8448) * 4;   // 104448 B
    cudaFuncSetAttribute(gemm_qkv, cudaFuncAttributeMaxDynamicSharedMemorySize,
                         qkvsmem);
    gemm_qkv<<<dim3(HWN / 64, EXPD / 64, NB), 256, qkvsmem>>>(
        x, Wq, Wk, Wv, bv, pq, pk, pv);

    // Warp-specialized bf16 attention
    const int asmem = 176640;
    cudaFuncSetAttribute(attn_mma, cudaFuncAttributeMaxDynamicSharedMemorySize,
                         asmem);
    attn_mma<<<dim3(8, 4, NB), 512, asmem>>>(pq, pk, pv, pw);

    // Output projection + bias + residual
    const int psmem = (64 * 132 + 128 * 72) * 4; // 70656 B
    cudaFuncSetAttribute(gemm_proj, cudaFuncAttributeMaxDynamicSharedMemorySize,
                         psmem);
    gemm_proj<<<dim3(HWN / 64, CDIM / 64, NB), 256, psmem>>>(
        Wt, pw, bt, x, out, CDIM, EXPD);
}

// round 8
// speedup vs baseline: 8.6188x; 1.1196x over previous
#include <cuda_runtime.h>
#include <cuda_bf16.h>
#include <cstdint>

#define HWN 1024
#define CDIM 128
#define EXPD 512
#define NB   16

// Scratch (allocation-free rule: static __device__ arrays)
__device__ __align__(128) __nv_bfloat16 g_q[NB * EXPD * HWN]; // [b][h][n][d]
__device__ __align__(128) __nv_bfloat16 g_k[NB * EXPD * HWN]; // [b][h][m][d]
__device__ __align__(128) __nv_bfloat16 g_v[NB * EXPD * HWN]; // [b][h][d][m]
__device__ __align__(128) float         g_wsv[NB * EXPD * HWN]; // [b][c'][pix]
__device__ __align__(128) __nv_bfloat16 g_xb[NB * HWN * CDIM];  // x^T bf16 [b][n][c]
__device__ __align__(128) __nv_bfloat16 g_wqb[EXPD * CDIM];
__device__ __align__(128) __nv_bfloat16 g_wkb[EXPD * CDIM];
__device__ __align__(128) __nv_bfloat16 g_wvb[EXPD * CDIM];

// ---------------------------------------------------------------------------
__device__ __forceinline__ uint32_t smem_u32(const void* p) {
    uint32_t a;
    asm("{ .reg .u64 t; cvta.to.shared.u64 t, %1; cvt.u32.u64 %0, t; }"
        : "=r"(a) : "l"(p));
    return a;
}

__device__ __forceinline__ void cpa16(uint32_t dst, const void* src) {
    asm volatile("cp.async.ca.shared.global [%0], [%1], 16;"
                 :: "r"(dst), "l"(src));
}
#define CP_COMMIT() asm volatile("cp.async.commit_group;")
#define CP_WAIT0()  asm volatile("cp.async.wait_group 0;")
#define CP_WAIT1()  asm volatile("cp.async.wait_group 1;")
#define BARX()      asm volatile("bar.sync 0, 512;" ::: "memory")

// f32 accum tf32 mma (proj GEMM)
__device__ __forceinline__ void mma8(float (&d)[4], const float (&a)[4],
                                     uint32_t b0, uint32_t b1) {
    asm volatile(
        "mma.sync.aligned.m16n8k8.row.col.f32.tf32.tf32.f32 "
        "{%0,%1,%2,%3}, {%4,%5,%6,%7}, {%8,%9}, {%0,%1,%2,%3};"
        : "+f"(d[0]), "+f"(d[1]), "+f"(d[2]), "+f"(d[3])
        : "r"(__float_as_uint(a[0])), "r"(__float_as_uint(a[1])),
          "r"(__float_as_uint(a[2])), "r"(__float_as_uint(a[3])),
          "r"(b0), "r"(b1));
}

// bf16 m16n8k16 mma
__device__ __forceinline__ void mma16(float (&d)[4], const uint32_t (&a)[4],
                                      uint32_t b0, uint32_t b1) {
    asm volatile(
        "mma.sync.aligned.m16n8k16.row.col.f32.bf16.bf16.f32 "
        "{%0,%1,%2,%3}, {%4,%5,%6,%7}, {%8,%9}, {%0,%1,%2,%3};"
        : "+f"(d[0]), "+f"(d[1]), "+f"(d[2]), "+f"(d[3])
        : "r"(a[0]), "r"(a[1]), "r"(a[2]), "r"(a[3]), "r"(b0), "r"(b1));
}

__device__ __forceinline__ uint32_t packbf(float lo, float hi) {
    uint32_t d;
    asm("cvt.rn.bf16x2.f32 %0, %1, %2;" : "=r"(d) : "f"(hi), "f"(lo));
    return d;
}

__device__ __forceinline__ float ex2a(float x) {
    float r;
    asm("ex2.approx.ftz.f32 %0, %1;" : "=f"(r) : "f"(x));
    return r;
}

// ---------------------------------------------------------------------------
// f32 -> bf16 convert (weights)
__global__ __launch_bounds__(256) void cvt_bf16(
    const float* __restrict__ s, __nv_bfloat16* __restrict__ d, int n)
{
    int i = (blockIdx.x * 256 + threadIdx.x) * 2;
    if (i < n) {
        float2 v = *(const float2*)&s[i];
        *(uint32_t*)&d[i] = packbf(v.x, v.y);
    }
}

// x[z][c][n] f32 -> xb[z][n][c] bf16 (32x32 smem-tile transpose)
__global__ __launch_bounds__(256) void xpose(
    const float* __restrict__ x, __nv_bfloat16* __restrict__ xb)
{
    __shared__ float ts[32][33];
    const int z = blockIdx.z;
    const int nx = blockIdx.x * 32, cy = blockIdx.y * 32;
    const int tx = threadIdx.x & 31, ty = threadIdx.x >> 5;
#pragma unroll
    for (int i = 0; i < 4; i++) {
        int c = cy + ty + i * 8;
        ts[ty + i * 8][tx] = x[((size_t)z * CDIM + c) * HWN + nx + tx];
    }
    __syncthreads();
#pragma unroll
    for (int i = 0; i < 4; i++) {
        int n = nx + ty + i * 8;
        xb[((size_t)z * HWN + n) * CDIM + cy + tx] =
            __float2bfloat16(ts[tx][ty + i * 8]);
    }
}

// ---------------------------------------------------------------------------
// Fused QKV GEMM, bf16 m16n8k16. Both operands K-major bf16.
// CTA tile 64(o) x 64(n), K=128 (8 k16 chunks). 8 warps = 2(o) x 4(n).
//   q,k: bf16 transposed store [z][o>>7][n][o&127] via smem f32 stage
//   v  : bf16 natural [z][o][n] + bias
// SMEM: Xs [64][136]bf16 @0; Ws[2] [64][136]bf16 @8704,@17408 (units: bf16)
// ---------------------------------------------------------------------------
__global__ __launch_bounds__(256) void gemm_qkv(
    const __nv_bfloat16* __restrict__ xb,
    const __nv_bfloat16* __restrict__ Wqb, const __nv_bfloat16* __restrict__ Wkb,
    const __nv_bfloat16* __restrict__ Wvb, const float* __restrict__ bv,
    __nv_bfloat16* __restrict__ qo, __nv_bfloat16* __restrict__ ko,
    __nv_bfloat16* __restrict__ vo)
{
    extern __shared__ __nv_bfloat16 sb[];
    __nv_bfloat16* Xs = sb;                       // [64][136]
    __nv_bfloat16* WsA[2] = {sb + 8704, sb + 17408};
    const uint32_t xs_a = smem_u32(Xs);
    const uint32_t ws_a[2] = {smem_u32(WsA[0]), smem_u32(WsA[1])};

    const int z = blockIdx.z;
    const int n0 = blockIdx.x * 64;
    const int o0 = blockIdx.y * 64;
    const int tid = threadIdx.x;
    const int w = tid >> 5, lane = tid & 31;
    const int g = lane >> 2, t = lane & 3;
    const int wo = w >> 2, wn = w & 3;

    const __nv_bfloat16* Wmat[3] = {Wqb, Wkb, Wvb};
    const __nv_bfloat16* xrow = xb + ((size_t)z * HWN + n0) * CDIM;

    // initial: Xs (64 n-rows x 128 k) + Ws[0] (Wq) -> group 0
#pragma unroll
    for (int p = 0; p < 4; p++) {
        int idx = tid + p * 256;
        int r = idx >> 4, c = idx & 15;
        cpa16(xs_a + (uint32_t)(r * 272 + c * 16), &xrow[(size_t)r * CDIM + c * 8]);
    }
#pragma unroll
    for (int p = 0; p < 4; p++) {
        int idx = tid + p * 256;
        int r = idx >> 4, c = idx & 15;
        cpa16(ws_a[0] + (uint32_t)(r * 272 + c * 16),
              &Wqb[(size_t)(o0 + r) * CDIM + c * 8]);
    }
    CP_COMMIT();

    for (int mat = 0; mat < 3; mat++) {
        if (mat < 2) {
            const __nv_bfloat16* Wn = Wmat[mat + 1];
#pragma unroll
            for (int p = 0; p < 4; p++) {
                int idx = tid + p * 256;
                int r = idx >> 4, c = idx & 15;
                cpa16(ws_a[(mat + 1) & 1] + (uint32_t)(r * 272 + c * 16),
                      &Wn[(size_t)(o0 + r) * CDIM + c * 8]);
            }
            CP_COMMIT();
            CP_WAIT1();
        } else {
            CP_WAIT0();
        }
        __syncthreads();

        const __nv_bfloat16* Wcur = WsA[mat & 1];
        float acc[2][2][4] = {};
#pragma unroll
        for (int kk = 0; kk < 8; kk++) {
            uint32_t a[2][4], bf[2][2];
#pragma unroll
            for (int i = 0; i < 2; i++) {
                const __nv_bfloat16* w0 = &Wcur[(wo * 32 + i * 16 + g) * 136 + kk * 16];
                a[i][0] = *(const uint32_t*)&w0[2 * t];
                a[i][1] = *(const uint32_t*)&w0[8 * 136 + 2 * t];
                a[i][2] = *(const uint32_t*)&w0[8 + 2 * t];
                a[i][3] = *(const uint32_t*)&w0[8 * 136 + 8 + 2 * t];
            }
#pragma unroll
            for (int j = 0; j < 2; j++) {
                const __nv_bfloat16* x0 = &Xs[(wn * 16 + j * 8 + g) * 136 + kk * 16];
                bf[j][0] = *(const uint32_t*)&x0[2 * t];
                bf[j][1] = *(const uint32_t*)&x0[8 + 2 * t];
            }
#pragma unroll
            for (int i = 0; i < 2; i++)
#pragma unroll
                for (int j = 0; j < 2; j++)
                    mma16(acc[i][j], a[i], bf[j][0], bf[j][1]);
        }
        __syncthreads();   // done reading Wcur (reused as f32 Cs below)

        if (mat < 2) {
            // transposed bf16 store via f32 smem stage Cs[n 64][o 68]
            float* Cs = (float*)WsA[mat & 1];   // 17408 B = 4352 f32 exactly
#pragma unroll
            for (int i = 0; i < 2; i++) {
                int ol = wo * 32 + i * 16 + g;
#pragma unroll
                for (int j = 0; j < 2; j++) {
                    int nl = wn * 16 + j * 8 + 2 * t;
                    Cs[nl * 68 + ol]           = acc[i][j][0];
                    Cs[(nl + 1) * 68 + ol]     = acc[i][j][1];
                    Cs[nl * 68 + ol + 8]       = acc[i][j][2];
                    Cs[(nl + 1) * 68 + ol + 8] = acc[i][j][3];
                }
            }
            __syncthreads();
            __nv_bfloat16* C = (mat == 0) ? qo : ko;
            const int head = o0 >> 7, d0 = o0 & 127;
#pragma unroll
            for (int p = 0; p < 4; p++) {
                int idx = p * 256 + tid;
                int nl = idx >> 4, o4 = (idx & 15) * 4;
                float4 vv = *(float4*)&Cs[nl * 68 + o4];
                uint2 pk = make_uint2(packbf(vv.x, vv.y), packbf(vv.z, vv.w));
                *(uint2*)&C[(((size_t)z * 4 + head) * HWN + n0 + nl) * CDIM + d0 + o4] = pk;
            }
            __syncthreads();   // Cs reads done before next mat's cp.async overwrites
        } else {
            // v: bf16 natural + bias
#pragma unroll
            for (int i = 0; i < 2; i++) {
                int ob = o0 + wo * 32 + i * 16 + g;
#pragma unroll
                for (int rr = 0; rr < 2; rr++) {
                    int orow = ob + rr * 8;
                    float bi = bv[orow];
#pragma unroll
                    for (int j = 0; j < 2; j++) {
                        int n = n0 + wn * 16 + j * 8 + 2 * t;
                        size_t addr = (size_t)z * EXPD * HWN + (size_t)orow * HWN + n;
                        *(uint32_t*)&vo[addr] = packbf(acc[i][j][rr * 2 + 0] + bi,
                                                       acc[i][j][rr * 2 + 1] + bi);
                    }
                }
            }
        }
    }
}

// ---------------------------------------------------------------------------
// Projection GEMM (tf32 mma): out = Wt @ wsv + bt + x.
// ---------------------------------------------------------------------------
__global__ __launch_bounds__(256) void gemm_proj(
    const float* __restrict__ A, const float* __restrict__ Bbase,
    const float* __restrict__ bias, const float* __restrict__ resid,
    float* __restrict__ C, int M, int K)
{
    extern __shared__ float sh[];
    float* Ws = sh;              // [64][132]
    float* Xs = sh + 64 * 132;   // [128][72]
    const uint32_t ws_a = smem_u32(Ws), xs_a = smem_u32(Xs);

    const int z = blockIdx.z;
    const float* B = Bbase + (size_t)z * K * HWN;
    const int n0 = blockIdx.x * 64;
    const int o0 = blockIdx.y * 64;
    const int tid = threadIdx.x;
    const int w = tid >> 5, lane = tid & 31;
    const int g = lane >> 2, t = lane & 3;
    const int wo = w >> 2, wn = w & 3;

    float acc[2][2][4] = {};

    for (int k0 = 0; k0 < K; k0 += 128) {
#pragma unroll
        for (int p = 0; p < 8; p++) {
            int idx = tid + p * 256;
            int r = idx >> 5, c = (idx & 31) << 2;
            cpa16(ws_a + (uint32_t)(r * 132 + c) * 4,
                  &A[(size_t)(o0 + r) * K + k0 + c]);
        }
#pragma unroll
        for (int p = 0; p < 8; p++) {
            int idx = tid + p * 256;
            int k = idx >> 4, n4 = (idx & 15) << 2;
            cpa16(xs_a + (uint32_t)(k * 72 + n4) * 4,
                  &B[(size_t)(k0 + k) * HWN + n0 + n4]);
        }
        CP_COMMIT();
        CP_WAIT0();
        __syncthreads();

#pragma unroll
        for (int kk = 0; kk < 16; kk++) {
            float a[2][4];
            uint32_t bf[2][2];
#pragma unroll
            for (int i = 0; i < 2; i++) {
                const float* wr = &Ws[(wo * 32 + i * 16 + g) * 132 + kk * 8];
                a[i][0] = wr[t];
                a[i][1] = wr[8 * 132 + t];
                a[i][2] = wr[t + 4];
                a[i][3] = wr[8 * 132 + t + 4];
            }
#pragma unroll
            for (int j = 0; j < 2; j++) {
                bf[j][0] = __float_as_uint(Xs[(kk * 8 + t) * 72 + wn * 16 + j * 8 + g]);
                bf[j][1] = __float_as_uint(Xs[(kk * 8 + t + 4) * 72 + wn * 16 + j * 8 + g]);
            }
#pragma unroll
            for (int i = 0; i < 2; i++)
#pragma unroll
                for (int j = 0; j < 2; j++)
                    mma8(acc[i][j], a[i], bf[j][0], bf[j][1]);
        }
        __syncthreads();
    }

#pragma unroll
    for (int i = 0; i < 2; i++) {
        int ob = o0 + wo * 32 + i * 16 + g;
#pragma unroll
        for (int rr = 0; rr < 2; rr++) {
            int orow = ob + rr * 8;
            float bi = bias[orow];
#pragma unroll
            for (int j = 0; j < 2; j++) {
                int n = n0 + wn * 16 + j * 8 + 2 * t;
                size_t addr = (size_t)z * M * HWN + (size_t)orow * HWN + n;
                float2 v = make_float2(acc[i][j][rr * 2 + 0] + bi,
                                       acc[i][j][rr * 2 + 1] + bi);
                float2 x2 = *(const float2*)&resid[addr];
                v.x += x2.x; v.y += x2.y;
                *(float2*)&C[addr] = v;
            }
        }
    }
}

// ---------------------------------------------------------------------------
// Warp-specialized attention (bf16 m16n8k16), 512 threads, 1 CTA = (b,h,128 q).
// (unchanged from R7 — S-warps produce P to SMEM ring, V-warps consume skewed)
// ---------------------------------------------------------------------------
__device__ __forceinline__ void pv_tile(float (&oacc)[16][4],
                                        const __nv_bfloat16* Vs,
                                        const uint32_t* Pr, int g, int t) {
    uint32_t pa[4][4];
#pragma unroll
    for (int r = 0; r < 16; r++)
        pa[r >> 2][r & 3] = Pr[r * 256];
#pragma unroll
    for (int d8 = 0; d8 < 16; d8++) {
        const __nv_bfloat16* Vr = &Vs[(d8 * 8 + g) * 72];
#pragma unroll
        for (int km = 0; km < 4; km++) {
            uint32_t b0 = *(const uint32_t*)&Vr[km * 16 + 2 * t];
            uint32_t b1 = *(const uint32_t*)&Vr[km * 16 + 8 + 2 * t];
            mma16(oacc[d8], pa[km], b0, b1);
        }
    }
}

__global__ __launch_bounds__(512, 1) void attn_mma(
    const __nv_bfloat16* __restrict__ gq, const __nv_bfloat16* __restrict__ gk,
    const __nv_bfloat16* __restrict__ gv, float* __restrict__ gwsv)
{
    extern __shared__ __nv_bfloat16 smb[];
    char* base = (char*)smb;
    const uint32_t sm_a = smem_u32(base);
    uint32_t* Pbuf = (uint32_t*)(base + 143360);
    float* rinv_s = (float*)(base + 176128);

    const int tid = threadIdx.x;
    const int w = tid >> 5, lane = tid & 31;
    const int g = lane >> 2, t = lane & 3;
    const int b = blockIdx.z, h = blockIdx.y;
    const int bh = b * 4 + h;
    const int n0 = blockIdx.x * 128;
    const float CEXP = 0.08838834764831843f * 1.4426950408889634f;

    const __nv_bfloat16* Qg = gq + ((size_t)bh * HWN + n0) * CDIM;
    const __nv_bfloat16* Kg = gk + (size_t)bh * HWN * CDIM;
    const __nv_bfloat16* Vg = gv + (size_t)bh * CDIM * HWN;

#pragma unroll
    for (int p = 0; p < 4; p++) {
        int idx = tid + p * 512;
        int r = idx >> 4, c = idx & 15;
        cpa16(sm_a + (uint32_t)(r * 272 + c * 16), &Qg[(size_t)r * CDIM + c * 8]);
    }
    CP_COMMIT();
    CP_WAIT0();
    BARX();

    if (w < 8) {
        // ================= S-warps =================
        uint32_t qa[8][4];
        {
            const __nv_bfloat16* q0 = smb + (w * 16 + g) * 136;
            const __nv_bfloat16* q8 = q0 + 8 * 136;
#pragma unroll
            for (int k = 0; k < 8; k++) {
                qa[k][0] = *(const uint32_t*)&q0[k * 16 + 2 * t];
                qa[k][1] = *(const uint32_t*)&q8[k * 16 + 2 * t];
                qa[k][2] = *(const uint32_t*)&q0[k * 16 + 8 + 2 * t];
                qa[k][3] = *(const uint32_t*)&q8[k * 16 + 8 + 2 * t];
            }
        }
        BARX();

#pragma unroll
        for (int tt = 0; tt < 2; tt++) {
#pragma unroll
            for (int p = 0; p < 4; p++) {
                int idx = tid + p * 256;
                int r = idx >> 4, c = idx & 15;
                cpa16(sm_a + (uint32_t)(tt * 17408 + r * 272 + c * 16),
                      &Kg[(size_t)(tt * 64 + r) * CDIM + c * 8]);
            }
            CP_COMMIT();
        }

        float rs0 = 0.f, rs1 = 0.f;
        for (int mt = 0; mt < 16; mt++) {
            if (mt < 15) { CP_WAIT1(); } else { CP_WAIT0(); }
            BARX();

            const __nv_bfloat16* Ks =
                (const __nv_bfloat16*)(base + (mt & 3) * 17408);
            uint32_t* Pw = Pbuf + (mt & 1) * 4096 + w * 32 + lane;
#pragma unroll
            for (int m8 = 0; m8 < 8; m8++) {
                float s[4] = {0.f, 0.f, 0.f, 0.f};
                const __nv_bfloat16* Kr = &Ks[(m8 * 8 + g) * 136];
#pragma unroll
                for (int k = 0; k < 8; k++) {
                    uint32_t b0 = *(const uint32_t*)&Kr[k * 16 + 2 * t];
                    uint32_t b1 = *(const uint32_t*)&Kr[k * 16 + 8 + 2 * t];
                    mma16(s, qa[k], b0, b1);
                }
                float e0 = ex2a(s[0] * CEXP), e1 = ex2a(s[1] * CEXP);
                float e2 = ex2a(s[2] * CEXP), e3 = ex2a(s[3] * CEXP);
                rs0 += e0 + e1;
                rs1 += e2 + e3;
                int r = (m8 >> 1) * 4 + (m8 & 1) * 2;
                Pw[(r + 0) * 256] = packbf(e0, e1);
                Pw[(r + 1) * 256] = packbf(e2, e3);
            }

            if (mt + 2 < 16) {
                const int m0 = (mt + 2) * 64;
#pragma unroll
                for (int p = 0; p < 4; p++) {
                    int idx = tid + p * 256;
                    int r = idx >> 4, c = idx & 15;
                    cpa16(sm_a + (uint32_t)(((mt + 2) & 3) * 17408 + r * 272 + c * 16),
                          &Kg[(size_t)(m0 + r) * CDIM + c * 8]);
                }
            }
            CP_COMMIT();
        }
        BARX();
        rs0 += __shfl_xor_sync(~0u, rs0, 1);
        rs0 += __shfl_xor_sync(~0u, rs0, 2);
        rs1 += __shfl_xor_sync(~0u, rs1, 1);
        rs1 += __shfl_xor_sync(~0u, rs1, 2);
        if (t == 0) {
            rinv_s[w * 16 + g]     = 1.f / rs0;
            rinv_s[w * 16 + g + 8] = 1.f / rs1;
        }
        BARX();
    } else {
        // ================= V-warps =================
        const int v = w - 8;
        const int vt = tid - 256;
        BARX();

#pragma unroll
        for (int tt = 0; tt < 2; tt++) {
#pragma unroll
            for (int p = 0; p < 4; p++) {
                int idx = vt + p * 256;
                int r = idx >> 3, c = idx & 7;
                cpa16(sm_a + (uint32_t)(69632 + tt * 18432 + r * 144 + c * 16),
                      &Vg[(size_t)r * HWN + tt * 64 + c * 8]);
            }
            CP_COMMIT();
        }

        float oacc[16][4] = {};
        for (int mt = 0; mt < 16; mt++) {
            if (mt < 15) { CP_WAIT1(); } else { CP_WAIT0(); }
            BARX();

            if (mt >= 1) {
                const __nv_bfloat16* Vs =
                    (const __nv_bfloat16*)(base + 69632 + ((mt - 1) & 3) * 18432);
                const uint32_t* Pr = Pbuf + ((mt - 1) & 1) * 4096 + v * 32 + lane;
                pv_tile(oacc, Vs, Pr, g, t);
            }

            if (mt + 2 < 16) {
                const int m0 = (mt + 2) * 64;
#pragma unroll
                for (int p = 0; p < 4; p++) {
                    int idx = vt + p * 256;
                    int r = idx >> 3, c = idx & 7;
                    cpa16(sm_a + (uint32_t)(69632 + ((mt + 2) & 3) * 18432 + r * 144 + c * 16),
                          &Vg[(size_t)r * HWN + m0 + c * 8]);
                }
            }
            CP_COMMIT();
        }
        BARX();
        {
            const __nv_bfloat16* Vs =
                (const __nv_bfloat16*)(base + 69632 + 3 * 18432);
            const uint32_t* Pr = Pbuf + 4096 + v * 32 + lane;
            pv_tile(oacc, Vs, Pr, g, t);
        }
        BARX();

        const float ri0 = rinv_s[v * 16 + g];
        const float ri1 = rinv_s[v * 16 + g + 8];
        const int nA = n0 + v * 16 + g;
        const int nB = nA + 8;
        const size_t obA = ((size_t)b * EXPD + h * CDIM + (nA >> 3)) * HWN
                         + (size_t)(nA & 7) * CDIM;
        const size_t obB = ((size_t)b * EXPD + h * CDIM + (nB >> 3)) * HWN
                         + (size_t)(nB & 7) * CDIM;
#pragma unroll
        for (int d8 = 0; d8 < 16; d8++) {
            int d = d8 * 8 + 2 * t;
            *(float2*)&gwsv[obA + d] = make_float2(oacc[d8][0] * ri0,
                                                   oacc[d8][1] * ri0);
            *(float2*)&gwsv[obB + d] = make_float2(oacc[d8][2] * ri1,
                                                   oacc[d8][3] * ri1);
        }
    }
}

// ---------------------------------------------------------------------------
extern "C" void kernel_launch(void* const* d_in, const int* in_sizes, int n_in,
                              void* d_out, int out_size)
{
    const float* x  = (const float*)d_in[0];
    const float* Wq = (const float*)d_in[1];
    const float* Wk = (const float*)d_in[2];
    const float* Wv = (const float*)d_in[3];
    const float* bv = (const float*)d_in[4];
    const float* Wt = (const float*)d_in[5];
    const float* bt = (const float*)d_in[6];
    float* out = (float*)d_out;

    __nv_bfloat16 *pq, *pk, *pv, *pxb, *pwq, *pwk, *pwv;
    float* pw;
    cudaGetSymbolAddress((void**)&pq, g_q);
    cudaGetSymbolAddress((void**)&pk, g_k);
    cudaGetSymbolAddress((void**)&pv, g_v);
    cudaGetSymbolAddress((void**)&pw, g_wsv);
    cudaGetSymbolAddress((void**)&pxb, g_xb);
    cudaGetSymbolAddress((void**)&pwq, g_wqb);
    cudaGetSymbolAddress((void**)&pwk, g_wkb);
    cudaGetSymbolAddress((void**)&pwv, g_wvb);

    // Conversions: weights -> bf16; x -> transposed bf16 [b][n][c]
    cvt_bf16<<<EXPD * CDIM / 512, 256>>>(Wq, pwq, EXPD * CDIM);
    cvt_bf16<<<EXPD * CDIM / 512, 256>>>(Wk, pwk, EXPD * CDIM);
    cvt_bf16<<<EXPD * CDIM / 512, 256>>>(Wv, pwv, EXPD * CDIM);
    xpose<<<dim3(HWN / 32, CDIM / 32, NB), 256>>>(x, pxb);

    // Fused QKV projections (bf16 mma)
    const int qkvsmem = 3 * 17408;   // 52224 B
    cudaFuncSetAttribute(gemm_qkv, cudaFuncAttributeMaxDynamicSharedMemorySize,
                         qkvsmem);
    gemm_qkv<<<dim3(HWN / 64, EXPD / 64, NB), 256, qkvsmem>>>(
        pxb, pwq, pwk, pwv, bv, pq, pk, pv);

    // Warp-specialized bf16 attention
    const int asmem = 176640;
    cudaFuncSetAttribute(attn_mma, cudaFuncAttributeMaxDynamicSharedMemorySize,
                         asmem);
    attn_mma<<<dim3(8, 4, NB), 512, asmem>>>(pq, pk, pv, pw);

    // Output projection + bias + residual (tf32 mma)
    const int psmem = (64 * 132 + 128 * 72) * 4; // 70656 B
    cudaFuncSetAttribute(gemm_proj, cudaFuncAttributeMaxDynamicSharedMemorySize,
                         psmem);
    gemm_proj<<<dim3(HWN / 64, CDIM / 64, NB), 256, psmem>>>(
        Wt, pw, bt, x, out, CDIM, EXPD);
}

// round 9
// speedup vs baseline: 9.3558x; 1.0855x over previous
#include <cuda_runtime.h>
#include <cuda_bf16.h>
#include <cstdint>

#define HWN 1024
#define CDIM 128
#define EXPD 512
#define NB   16

// Scratch (allocation-free rule: static __device__ arrays)
__device__ __align__(128) __nv_bfloat16 g_q[NB * EXPD * HWN]; // [b][h][n][d]
__device__ __align__(128) __nv_bfloat16 g_k[NB * EXPD * HWN]; // [b][h][m][d]
__device__ __align__(128) __nv_bfloat16 g_v[NB * EXPD * HWN]; // [b][h][d][m]
__device__ __align__(128) __nv_bfloat16 g_wsv[NB * EXPD * HWN]; // bf16 [b][c'][pix]
__device__ __align__(128) __nv_bfloat16 g_xb[NB * HWN * CDIM];  // x^T bf16 [b][n][c]
__device__ __align__(128) __nv_bfloat16 g_wqb[EXPD * CDIM];
__device__ __align__(128) __nv_bfloat16 g_wkb[EXPD * CDIM];
__device__ __align__(128) __nv_bfloat16 g_wvb[EXPD * CDIM];
__device__ __align__(128) __nv_bfloat16 g_wtb[CDIM * EXPD];

// ---------------------------------------------------------------------------
__device__ __forceinline__ uint32_t smem_u32(const void* p) {
    uint32_t a;
    asm("{ .reg .u64 t; cvta.to.shared.u64 t, %1; cvt.u32.u64 %0, t; }"
        : "=r"(a) : "l"(p));
    return a;
}

__device__ __forceinline__ void cpa16(uint32_t dst, const void* src) {
    asm volatile("cp.async.ca.shared.global [%0], [%1], 16;"
                 :: "r"(dst), "l"(src));
}
#define CP_COMMIT() asm volatile("cp.async.commit_group;")
#define CP_WAIT0()  asm volatile("cp.async.wait_group 0;")
#define CP_WAIT1()  asm volatile("cp.async.wait_group 1;")
#define BARX()      asm volatile("bar.sync 0, 512;" ::: "memory")

// bf16 m16n8k16 mma
__device__ __forceinline__ void mma16(float (&d)[4], const uint32_t (&a)[4],
                                      uint32_t b0, uint32_t b1) {
    asm volatile(
        "mma.sync.aligned.m16n8k16.row.col.f32.bf16.bf16.f32 "
        "{%0,%1,%2,%3}, {%4,%5,%6,%7}, {%8,%9}, {%0,%1,%2,%3};"
        : "+f"(d[0]), "+f"(d[1]), "+f"(d[2]), "+f"(d[3])
        : "r"(a[0]), "r"(a[1]), "r"(a[2]), "r"(a[3]), "r"(b0), "r"(b1));
}

__device__ __forceinline__ void ldsm4(uint32_t (&r)[4], uint32_t addr) {
    asm volatile("ldmatrix.sync.aligned.m8n8.x4.shared.b16 {%0,%1,%2,%3}, [%4];"
                 : "=r"(r[0]), "=r"(r[1]), "=r"(r[2]), "=r"(r[3]) : "r"(addr));
}
__device__ __forceinline__ void ldsm4t(uint32_t (&r)[4], uint32_t addr) {
    asm volatile("ldmatrix.sync.aligned.m8n8.x4.trans.shared.b16 {%0,%1,%2,%3}, [%4];"
                 : "=r"(r[0]), "=r"(r[1]), "=r"(r[2]), "=r"(r[3]) : "r"(addr));
}

__device__ __forceinline__ uint32_t packbf(float lo, float hi) {
    uint32_t d;
    asm("cvt.rn.bf16x2.f32 %0, %1, %2;" : "=r"(d) : "f"(hi), "f"(lo));
    return d;
}

__device__ __forceinline__ float ex2a(float x) {
    float r;
    asm("ex2.approx.ftz.f32 %0, %1;" : "=f"(r) : "f"(x));
    return r;
}

// ---------------------------------------------------------------------------
// f32 -> bf16 convert (weights)
__global__ __launch_bounds__(256) void cvt_bf16(
    const float* __restrict__ s, __nv_bfloat16* __restrict__ d, int n)
{
    int i = (blockIdx.x * 256 + threadIdx.x) * 2;
    if (i < n) {
        float2 v = *(const float2*)&s[i];
        *(uint32_t*)&d[i] = packbf(v.x, v.y);
    }
}

// x[z][c][n] f32 -> xb[z][n][c] bf16 (32x32 smem-tile transpose)
__global__ __launch_bounds__(256) void xpose(
    const float* __restrict__ x, __nv_bfloat16* __restrict__ xb)
{
    __shared__ float ts[32][33];
    const int z = blockIdx.z;
    const int nx = blockIdx.x * 32, cy = blockIdx.y * 32;
    const int tx = threadIdx.x & 31, ty = threadIdx.x >> 5;
#pragma unroll
    for (int i = 0; i < 4; i++) {
        int c = cy + ty + i * 8;
        ts[ty + i * 8][tx] = x[((size_t)z * CDIM + c) * HWN + nx + tx];
    }
    __syncthreads();
#pragma unroll
    for (int i = 0; i < 4; i++) {
        int n = nx + ty + i * 8;
        xb[((size_t)z * HWN + n) * CDIM + cy + tx] =
            __float2bfloat16(ts[tx][ty + i * 8]);
    }
}

// ---------------------------------------------------------------------------
// Fused QKV GEMM, bf16 m16n8k16, ldmatrix fragment feeding.
// CTA tile 64(o) x 64(n), K=128 (8 k16 chunks). 8 warps = 2(o) x 4(n).
// SMEM: Xs [64][136]bf16 @0; Ws[2] [64][136]bf16 @8704,@17408 (bf16 units)
// ---------------------------------------------------------------------------
__global__ __launch_bounds__(256) void gemm_qkv(
    const __nv_bfloat16* __restrict__ xb,
    const __nv_bfloat16* __restrict__ Wqb, const __nv_bfloat16* __restrict__ Wkb,
    const __nv_bfloat16* __restrict__ Wvb, const float* __restrict__ bv,
    __nv_bfloat16* __restrict__ qo, __nv_bfloat16* __restrict__ ko,
    __nv_bfloat16* __restrict__ vo)
{
    extern __shared__ __nv_bfloat16 sb[];
    __nv_bfloat16* Xs = sb;                       // [64][136]
    __nv_bfloat16* WsA[2] = {sb + 8704, sb + 17408};
    const uint32_t xs_a = smem_u32(Xs);
    const uint32_t ws_a[2] = {smem_u32(WsA[0]), smem_u32(WsA[1])};

    const int z = blockIdx.z;
    const int n0 = blockIdx.x * 64;
    const int o0 = blockIdx.y * 64;
    const int tid = threadIdx.x;
    const int w = tid >> 5, lane = tid & 31;
    const int g = lane >> 2, t = lane & 3;
    const int wo = w >> 2, wn = w & 3;
    const int l7 = lane & 7, mi = lane >> 3;

    // ldmatrix per-thread offsets (bytes; row stride 272 = 136 bf16)
    uint32_t a_off[2], b_off;
#pragma unroll
    for (int i = 0; i < 2; i++)
        a_off[i] = (uint32_t)((wo * 32 + i * 16 + (mi & 1) * 8 + l7) * 272
                              + (mi >> 1) * 16);
    b_off = (uint32_t)((wn * 16 + (mi >> 1) * 8 + l7) * 272 + (mi & 1) * 16);

    const __nv_bfloat16* Wmat[3] = {Wqb, Wkb, Wvb};
    const __nv_bfloat16* xrow = xb + ((size_t)z * HWN + n0) * CDIM;

#pragma unroll
    for (int p = 0; p < 4; p++) {
        int idx = tid + p * 256;
        int r = idx >> 4, c = idx & 15;
        cpa16(xs_a + (uint32_t)(r * 272 + c * 16), &xrow[(size_t)r * CDIM + c * 8]);
    }
#pragma unroll
    for (int p = 0; p < 4; p++) {
        int idx = tid + p * 256;
        int r = idx >> 4, c = idx & 15;
        cpa16(ws_a[0] + (uint32_t)(r * 272 + c * 16),
              &Wqb[(size_t)(o0 + r) * CDIM + c * 8]);
    }
    CP_COMMIT();

    for (int mat = 0; mat < 3; mat++) {
        if (mat < 2) {
            const __nv_bfloat16* Wn = Wmat[mat + 1];
#pragma unroll
            for (int p = 0; p < 4; p++) {
                int idx = tid + p * 256;
                int r = idx >> 4, c = idx & 15;
                cpa16(ws_a[(mat + 1) & 1] + (uint32_t)(r * 272 + c * 16),
                      &Wn[(size_t)(o0 + r) * CDIM + c * 8]);
            }
            CP_COMMIT();
            CP_WAIT1();
        } else {
            CP_WAIT0();
        }
        __syncthreads();

        const uint32_t wcur = ws_a[mat & 1];
        float acc[2][2][4] = {};
#pragma unroll
        for (int kk = 0; kk < 8; kk++) {
            uint32_t a0[4], a1[4], bb[4];
            ldsm4(a0, wcur + a_off[0] + kk * 32);
            ldsm4(a1, wcur + a_off[1] + kk * 32);
            ldsm4(bb, xs_a + b_off + kk * 32);
            mma16(acc[0][0], a0, bb[0], bb[1]);
            mma16(acc[0][1], a0, bb[2], bb[3]);
            mma16(acc[1][0], a1, bb[0], bb[1]);
            mma16(acc[1][1], a1, bb[2], bb[3]);
        }
        __syncthreads();   // done reading Wcur (reused as f32 Cs below)

        if (mat < 2) {
            // transposed bf16 store via f32 smem stage Cs[n 64][o 68]
            float* Cs = (float*)WsA[mat & 1];
#pragma unroll
            for (int i = 0; i < 2; i++) {
                int ol = wo * 32 + i * 16 + g;
#pragma unroll
                for (int j = 0; j < 2; j++) {
                    int nl = wn * 16 + j * 8 + 2 * t;
                    Cs[nl * 68 + ol]           = acc[i][j][0];
                    Cs[(nl + 1) * 68 + ol]     = acc[i][j][1];
                    Cs[nl * 68 + ol + 8]       = acc[i][j][2];
                    Cs[(nl + 1) * 68 + ol + 8] = acc[i][j][3];
                }
            }
            __syncthreads();
            __nv_bfloat16* C = (mat == 0) ? qo : ko;
            const int head = o0 >> 7, d0 = o0 & 127;
#pragma unroll
            for (int p = 0; p < 4; p++) {
                int idx = p * 256 + tid;
                int nl = idx >> 4, o4 = (idx & 15) * 4;
                float4 vv = *(float4*)&Cs[nl * 68 + o4];
                uint2 pk = make_uint2(packbf(vv.x, vv.y), packbf(vv.z, vv.w));
                *(uint2*)&C[(((size_t)z * 4 + head) * HWN + n0 + nl) * CDIM + d0 + o4] = pk;
            }
            __syncthreads();
        } else {
            // v: bf16 natural + bias
#pragma unroll
            for (int i = 0; i < 2; i++) {
                int ob = o0 + wo * 32 + i * 16 + g;
#pragma unroll
                for (int rr = 0; rr < 2; rr++) {
                    int orow = ob + rr * 8;
                    float bi = bv[orow];
#pragma unroll
                    for (int j = 0; j < 2; j++) {
                        int n = n0 + wn * 16 + j * 8 + 2 * t;
                        size_t addr = (size_t)z * EXPD * HWN + (size_t)orow * HWN + n;
                        *(uint32_t*)&vo[addr] = packbf(acc[i][j][rr * 2 + 0] + bi,
                                                       acc[i][j][rr * 2 + 1] + bi);
                    }
                }
            }
        }
    }
}

// ---------------------------------------------------------------------------
// Projection GEMM, bf16 m16n8k16: out = Wt @ wsv + bt + x (f32 out).
// A = Wtb [128][512] k-major; B = wsv bf16 [k=512][n=1024] via ldmatrix.trans.
// CTA 64(o) x 64(n), K chunks of 128.
// SMEM: Ws [64][136]bf16 (17408 B) @0; Xs [128][72]bf16 (18432 B) @17408.
// ---------------------------------------------------------------------------
__global__ __launch_bounds__(256) void gemm_proj(
    const __nv_bfloat16* __restrict__ A, const __nv_bfloat16* __restrict__ Bbase,
    const float* __restrict__ bias, const float* __restrict__ resid,
    float* __restrict__ C)
{
    extern __shared__ __nv_bfloat16 sb[];
    __nv_bfloat16* Ws = sb;            // [64][136]
    __nv_bfloat16* Xs = sb + 8704;     // [128][72]
    const uint32_t ws_a = smem_u32(Ws), xs_a = smem_u32(Xs);

    const int z = blockIdx.z;
    const __nv_bfloat16* B = Bbase + (size_t)z * EXPD * HWN;
    const int n0 = blockIdx.x * 64;
    const int o0 = blockIdx.y * 64;
    const int tid = threadIdx.x;
    const int w = tid >> 5, lane = tid & 31;
    const int g = lane >> 2, t = lane & 3;
    const int wo = w >> 2, wn = w & 3;
    const int l7 = lane & 7, mi = lane >> 3;

    uint32_t a_off[2];
#pragma unroll
    for (int i = 0; i < 2; i++)
        a_off[i] = (uint32_t)((wo * 32 + i * 16 + (mi & 1) * 8 + l7) * 272
                              + (mi >> 1) * 16);
    // trans B: row = kk*16 + (mi&1)*8 + l7 (stride 144 B), col = wn*16 + (mi>>1)*8
    const uint32_t b_off = (uint32_t)(((mi & 1) * 8 + l7) * 144
                                      + (wn * 16 + (mi >> 1) * 8) * 2);

    float acc[2][2][4] = {};

    for (int k0 = 0; k0 < EXPD; k0 += 128) {
#pragma unroll
        for (int p = 0; p < 4; p++) {
            int idx = tid + p * 256;
            int r = idx >> 4, c = idx & 15;
            cpa16(ws_a + (uint32_t)(r * 272 + c * 16),
                  &A[(size_t)(o0 + r) * EXPD + k0 + c * 8]);
        }
#pragma unroll
        for (int p = 0; p < 4; p++) {
            int idx = tid + p * 256;
            int r = idx >> 3, c = idx & 7;
            cpa16(xs_a + (uint32_t)(r * 144 + c * 16),
                  &B[(size_t)(k0 + r) * HWN + n0 + c * 8]);
        }
        CP_COMMIT();
        CP_WAIT0();
        __syncthreads();

#pragma unroll
        for (int kk = 0; kk < 8; kk++) {
            uint32_t a0[4], a1[4], bb[4];
            ldsm4(a0, ws_a + a_off[0] + kk * 32);
            ldsm4(a1, ws_a + a_off[1] + kk * 32);
            ldsm4t(bb, xs_a + b_off + (uint32_t)kk * 2304);   // 16 rows * 144 B
            mma16(acc[0][0], a0, bb[0], bb[1]);
            mma16(acc[0][1], a0, bb[2], bb[3]);
            mma16(acc[1][0], a1, bb[0], bb[1]);
            mma16(acc[1][1], a1, bb[2], bb[3]);
        }
        __syncthreads();
    }

#pragma unroll
    for (int i = 0; i < 2; i++) {
        int ob = o0 + wo * 32 + i * 16 + g;
#pragma unroll
        for (int rr = 0; rr < 2; rr++) {
            int orow = ob + rr * 8;
            float bi = bias[orow];
#pragma unroll
            for (int j = 0; j < 2; j++) {
                int n = n0 + wn * 16 + j * 8 + 2 * t;
                size_t addr = (size_t)z * CDIM * HWN + (size_t)orow * HWN + n;
                float2 v = make_float2(acc[i][j][rr * 2 + 0] + bi,
                                       acc[i][j][rr * 2 + 1] + bi);
                float2 x2 = *(const float2*)&resid[addr];
                v.x += x2.x; v.y += x2.y;
                *(float2*)&C[addr] = v;
            }
        }
    }
}

// ---------------------------------------------------------------------------
// Warp-specialized attention (bf16 m16n8k16 + ldmatrix), 512 threads.
// S-warps 0-7 produce P to SMEM ring; V-warps 8-15 consume one tile behind.
// SMEM layout (bytes): Kbuf[4] @ i*17408; Vbuf[4] @ 69632+i*18432;
//                      Pbuf @ 143360 (2x16384); rinv @ 176128 (128 f32).
// ---------------------------------------------------------------------------
__device__ __forceinline__ void pv_tile(float (&oacc)[16][4], uint32_t vs_a,
                                        const uint32_t* Pr, int l7, int mi) {
    uint32_t pa[4][4];
#pragma unroll
    for (int r = 0; r < 16; r++)
        pa[r >> 2][r & 3] = Pr[r * 256];
#pragma unroll
    for (int d8 = 0; d8 < 16; d8++) {
        uint32_t base = vs_a + (uint32_t)((d8 * 8 + l7) * 144 + mi * 16);
        uint32_t v0[4], v1[4];
        ldsm4(v0, base);
        ldsm4(v1, base + 64);
        mma16(oacc[d8], pa[0], v0[0], v0[1]);
        mma16(oacc[d8], pa[1], v0[2], v0[3]);
        mma16(oacc[d8], pa[2], v1[0], v1[1]);
        mma16(oacc[d8], pa[3], v1[2], v1[3]);
    }
}

__global__ __launch_bounds__(512, 1) void attn_mma(
    const __nv_bfloat16* __restrict__ gq, const __nv_bfloat16* __restrict__ gk,
    const __nv_bfloat16* __restrict__ gv, __nv_bfloat16* __restrict__ gwsv)
{
    extern __shared__ __nv_bfloat16 smb[];
    char* base = (char*)smb;
    const uint32_t sm_a = smem_u32(base);
    uint32_t* Pbuf = (uint32_t*)(base + 143360);
    float* rinv_s = (float*)(base + 176128);

    const int tid = threadIdx.x;
    const int w = tid >> 5, lane = tid & 31;
    const int g = lane >> 2, t = lane & 3;
    const int l7 = lane & 7, mi = lane >> 3;
    const int b = blockIdx.z, h = blockIdx.y;
    const int bh = b * 4 + h;
    const int n0 = blockIdx.x * 128;
    const float CEXP = 0.08838834764831843f * 1.4426950408889634f;

    const __nv_bfloat16* Qg = gq + ((size_t)bh * HWN + n0) * CDIM;
    const __nv_bfloat16* Kg = gk + (size_t)bh * HWN * CDIM;
    const __nv_bfloat16* Vg = gv + (size_t)bh * CDIM * HWN;

#pragma unroll
    for (int p = 0; p < 4; p++) {
        int idx = tid + p * 512;
        int r = idx >> 4, c = idx & 15;
        cpa16(sm_a + (uint32_t)(r * 272 + c * 16), &Qg[(size_t)r * CDIM + c * 8]);
    }
    CP_COMMIT();
    CP_WAIT0();
    BARX();

    if (w < 8) {
        // ================= S-warps =================
        uint32_t qa[8][4];
        {
            uint32_t qoff = sm_a + (uint32_t)((w * 16 + (mi & 1) * 8 + l7) * 272
                                              + (mi >> 1) * 16);
#pragma unroll
            for (int k = 0; k < 8; k++)
                ldsm4(qa[k], qoff + k * 32);
        }
        BARX();

#pragma unroll
        for (int tt = 0; tt < 2; tt++) {
#pragma unroll
            for (int p = 0; p < 4; p++) {
                int idx = tid + p * 256;
                int r = idx >> 4, c = idx & 15;
                cpa16(sm_a + (uint32_t)(tt * 17408 + r * 272 + c * 16),
                      &Kg[(size_t)(tt * 64 + r) * CDIM + c * 8]);
            }
            CP_COMMIT();
        }

        float rs0 = 0.f, rs1 = 0.f;
        for (int mt = 0; mt < 16; mt++) {
            if (mt < 15) { CP_WAIT1(); } else { CP_WAIT0(); }
            BARX();

            const uint32_t ks_a = sm_a + (uint32_t)((mt & 3) * 17408);
            uint32_t* Pw = Pbuf + (mt & 1) * 4096 + w * 32 + lane;
#pragma unroll
            for (int m8 = 0; m8 < 8; m8++) {
                uint32_t kb0[4], kb1[4], kb2[4], kb3[4];
                uint32_t kbase = ks_a + (uint32_t)((m8 * 8 + l7) * 272 + mi * 16);
                ldsm4(kb0, kbase);
                ldsm4(kb1, kbase + 64);
                ldsm4(kb2, kbase + 128);
                ldsm4(kb3, kbase + 192);
                float s[4] = {0.f, 0.f, 0.f, 0.f};
                mma16(s, qa[0], kb0[0], kb0[1]);
                mma16(s, qa[1], kb0[2], kb0[3]);
                mma16(s, qa[2], kb1[0], kb1[1]);
                mma16(s, qa[3], kb1[2], kb1[3]);
                mma16(s, qa[4], kb2[0], kb2[1]);
                mma16(s, qa[5], kb2[2], kb2[3]);
                mma16(s, qa[6], kb3[0], kb3[1]);
                mma16(s, qa[7], kb3[2], kb3[3]);
                float e0 = ex2a(s[0] * CEXP), e1 = ex2a(s[1] * CEXP);
                float e2 = ex2a(s[2] * CEXP), e3 = ex2a(s[3] * CEXP);
                rs0 += e0 + e1;
                rs1 += e2 + e3;
                int r = (m8 >> 1) * 4 + (m8 & 1) * 2;
                Pw[(r + 0) * 256] = packbf(e0, e1);
                Pw[(r + 1) * 256] = packbf(e2, e3);
            }

            if (mt + 2 < 16) {
                const int m0 = (mt + 2) * 64;
#pragma unroll
                for (int p = 0; p < 4; p++) {
                    int idx = tid + p * 256;
                    int r = idx >> 4, c = idx & 15;
                    cpa16(sm_a + (uint32_t)(((mt + 2) & 3) * 17408 + r * 272 + c * 16),
                          &Kg[(size_t)(m0 + r) * CDIM + c * 8]);
                }
            }
            CP_COMMIT();
        }
        BARX();
        rs0 += __shfl_xor_sync(~0u, rs0, 1);
        rs0 += __shfl_xor_sync(~0u, rs0, 2);
        rs1 += __shfl_xor_sync(~0u, rs1, 1);
        rs1 += __shfl_xor_sync(~0u, rs1, 2);
        if (t == 0) {
            rinv_s[w * 16 + g]     = 1.f / rs0;
            rinv_s[w * 16 + g + 8] = 1.f / rs1;
        }
        BARX();
    } else {
        // ================= V-warps =================
        const int v = w - 8;
        const int vt = tid - 256;
        BARX();

#pragma unroll
        for (int tt = 0; tt < 2; tt++) {
#pragma unroll
            for (int p = 0; p < 4; p++) {
                int idx = vt + p * 256;
                int r = idx >> 3, c = idx & 7;
                cpa16(sm_a + (uint32_t)(69632 + tt * 18432 + r * 144 + c * 16),
                      &Vg[(size_t)r * HWN + tt * 64 + c * 8]);
            }
            CP_COMMIT();
        }

        float oacc[16][4] = {};
        for (int mt = 0; mt < 16; mt++) {
            if (mt < 15) { CP_WAIT1(); } else { CP_WAIT0(); }
            BARX();

            if (mt >= 1) {
                uint32_t vs_a = sm_a + (uint32_t)(69632 + ((mt - 1) & 3) * 18432);
                const uint32_t* Pr = Pbuf + ((mt - 1) & 1) * 4096 + v * 32 + lane;
                pv_tile(oacc, vs_a, Pr, l7, mi);
            }

            if (mt + 2 < 16) {
                const int m0 = (mt + 2) * 64;
#pragma unroll
                for (int p = 0; p < 4; p++) {
                    int idx = vt + p * 256;
                    int r = idx >> 3, c = idx & 7;
                    cpa16(sm_a + (uint32_t)(69632 + ((mt + 2) & 3) * 18432 + r * 144 + c * 16),
                          &Vg[(size_t)r * HWN + m0 + c * 8]);
                }
            }
            CP_COMMIT();
        }
        BARX();
        {
            uint32_t vs_a = sm_a + (uint32_t)(69632 + 3 * 18432);
            const uint32_t* Pr = Pbuf + 4096 + v * 32 + lane;
            pv_tile(oacc, vs_a, Pr, l7, mi);
        }
        BARX();

        const float ri0 = rinv_s[v * 16 + g];
        const float ri1 = rinv_s[v * 16 + g + 8];
        const int nA = n0 + v * 16 + g;
        const int nB = nA + 8;
        const size_t obA = ((size_t)b * EXPD + h * CDIM + (nA >> 3)) * HWN
                         + (size_t)(nA & 7) * CDIM;
        const size_t obB = ((size_t)b * EXPD + h * CDIM + (nB >> 3)) * HWN
                         + (size_t)(nB & 7) * CDIM;
#pragma unroll
        for (int d8 = 0; d8 < 16; d8++) {
            int d = d8 * 8 + 2 * t;
            *(uint32_t*)&gwsv[obA + d] = packbf(oacc[d8][0] * ri0,
                                                oacc[d8][1] * ri0);
            *(uint32_t*)&gwsv[obB + d] = packbf(oacc[d8][2] * ri1,
                                                oacc[d8][3] * ri1);
        }
    }
}

// ---------------------------------------------------------------------------
extern "C" void kernel_launch(void* const* d_in, const int* in_sizes, int n_in,
                              void* d_out, int out_size)
{
    const float* x  = (const float*)d_in[0];
    const float* Wq = (const float*)d_in[1];
    const float* Wk = (const float*)d_in[2];
    const float* Wv = (const float*)d_in[3];
    const float* bv = (const float*)d_in[4];
    const float* Wt = (const float*)d_in[5];
    const float* bt = (const float*)d_in[6];
    float* out = (float*)d_out;

    __nv_bfloat16 *pq, *pk, *pv, *pw, *pxb, *pwq, *pwk, *pwv, *pwt;
    cudaGetSymbolAddress((void**)&pq, g_q);
    cudaGetSymbolAddress((void**)&pk, g_k);
    cudaGetSymbolAddress((void**)&pv, g_v);
    cudaGetSymbolAddress((void**)&pw, g_wsv);
    cudaGetSymbolAddress((void**)&pxb, g_xb);
    cudaGetSymbolAddress((void**)&pwq, g_wqb);
    cudaGetSymbolAddress((void**)&pwk, g_wkb);
    cudaGetSymbolAddress((void**)&pwv, g_wvb);
    cudaGetSymbolAddress((void**)&pwt, g_wtb);

    // Conversions: weights -> bf16; x -> transposed bf16 [b][n][c]
    cvt_bf16<<<EXPD * CDIM / 512, 256>>>(Wq, pwq, EXPD * CDIM);
    cvt_bf16<<<EXPD * CDIM / 512, 256>>>(Wk, pwk, EXPD * CDIM);
    cvt_bf16<<<EXPD * CDIM / 512, 256>>>(Wv, pwv, EXPD * CDIM);
    cvt_bf16<<<CDIM * EXPD / 512, 256>>>(Wt, pwt, CDIM * EXPD);
    xpose<<<dim3(HWN / 32, CDIM / 32, NB), 256>>>(x, pxb);

    // Fused QKV projections (bf16 mma + ldmatrix)
    const int qkvsmem = 3 * 17408;   // 52224 B
    cudaFuncSetAttribute(gemm_qkv, cudaFuncAttributeMaxDynamicSharedMemorySize,
                         qkvsmem);
    gemm_qkv<<<dim3(HWN / 64, EXPD / 64, NB), 256, qkvsmem>>>(
        pxb, pwq, pwk, pwv, bv, pq, pk, pv);

    // Warp-specialized bf16 attention (ldmatrix)
    const int asmem = 176640;
    cudaFuncSetAttribute(attn_mma, cudaFuncAttributeMaxDynamicSharedMemorySize,
                         asmem);
    attn_mma<<<dim3(8, 4, NB), 512, asmem>>>(pq, pk, pv, pw);

    // Output projection + bias + residual (bf16 mma + ldmatrix, f32 out)
    const int psmem = 17408 + 18432;  // 35840 B
    cudaFuncSetAttribute(gemm_proj, cudaFuncAttributeMaxDynamicSharedMemorySize,
                         psmem);
    gemm_proj<<<dim3(HWN / 64, CDIM / 64, NB), 256, psmem>>>(
        pwt, pw, bt, x, out);
}

// round 10
// speedup vs baseline: 9.6036x; 1.0265x over previous
#include <cuda_runtime.h>
#include <cuda_bf16.h>
#include <cstdint>

#define HWN 1024
#define CDIM 128
#define EXPD 512
#define NB   16

// Scratch (allocation-free rule: static __device__ arrays)
__device__ __align__(128) __nv_bfloat16 g_q[NB * EXPD * HWN]; // [b][h][n][d]
__device__ __align__(128) __nv_bfloat16 g_k[NB * EXPD * HWN]; // [b][h][m][d]
__device__ __align__(128) __nv_bfloat16 g_v[NB * EXPD * HWN]; // [b][h][d][m]
__device__ __align__(128) __nv_bfloat16 g_wsv[NB * EXPD * HWN]; // bf16 [b][c'][pix]
__device__ __align__(128) __nv_bfloat16 g_xb[NB * HWN * CDIM];  // x^T bf16 [b][n][c]
__device__ __align__(128) __nv_bfloat16 g_wqb[EXPD * CDIM];
__device__ __align__(128) __nv_bfloat16 g_wkb[EXPD * CDIM];
__device__ __align__(128) __nv_bfloat16 g_wvb[EXPD * CDIM];
__device__ __align__(128) __nv_bfloat16 g_wtb[CDIM * EXPD];

// ---------------------------------------------------------------------------
__device__ __forceinline__ uint32_t smem_u32(const void* p) {
    uint32_t a;
    asm("{ .reg .u64 t; cvta.to.shared.u64 t, %1; cvt.u32.u64 %0, t; }"
        : "=r"(a) : "l"(p));
    return a;
}

__device__ __forceinline__ void cpa16(uint32_t dst, const void* src) {
    asm volatile("cp.async.ca.shared.global [%0], [%1], 16;"
                 :: "r"(dst), "l"(src));
}
#define CP_COMMIT() asm volatile("cp.async.commit_group;")
#define CP_WAIT0()  asm volatile("cp.async.wait_group 0;")
#define CP_WAIT1()  asm volatile("cp.async.wait_group 1;")
#define BARX()      asm volatile("bar.sync 0, 512;" ::: "memory")

// bf16 m16n8k16 mma
__device__ __forceinline__ void mma16(float (&d)[4], const uint32_t (&a)[4],
                                      uint32_t b0, uint32_t b1) {
    asm volatile(
        "mma.sync.aligned.m16n8k16.row.col.f32.bf16.bf16.f32 "
        "{%0,%1,%2,%3}, {%4,%5,%6,%7}, {%8,%9}, {%0,%1,%2,%3};"
        : "+f"(d[0]), "+f"(d[1]), "+f"(d[2]), "+f"(d[3])
        : "r"(a[0]), "r"(a[1]), "r"(a[2]), "r"(a[3]), "r"(b0), "r"(b1));
}

__device__ __forceinline__ void ldsm4(uint32_t (&r)[4], uint32_t addr) {
    asm volatile("ldmatrix.sync.aligned.m8n8.x4.shared.b16 {%0,%1,%2,%3}, [%4];"
                 : "=r"(r[0]), "=r"(r[1]), "=r"(r[2]), "=r"(r[3]) : "r"(addr));
}
__device__ __forceinline__ void ldsm4t(uint32_t (&r)[4], uint32_t addr) {
    asm volatile("ldmatrix.sync.aligned.m8n8.x4.trans.shared.b16 {%0,%1,%2,%3}, [%4];"
                 : "=r"(r[0]), "=r"(r[1]), "=r"(r[2]), "=r"(r[3]) : "r"(addr));
}

__device__ __forceinline__ uint32_t packbf(float lo, float hi) {
    uint32_t d;
    asm("cvt.rn.bf16x2.f32 %0, %1, %2;" : "=r"(d) : "f"(hi), "f"(lo));
    return d;
}

__device__ __forceinline__ float ex2a(float x) {
    float r;
    asm("ex2.approx.ftz.f32 %0, %1;" : "=f"(r) : "f"(x));
    return r;
}

// ---------------------------------------------------------------------------
// All four weight conversions in ONE launch. 4 segments x 65536 elems,
// 128 blocks per segment.
__global__ __launch_bounds__(256) void cvt_all(
    const float* __restrict__ s0, const float* __restrict__ s1,
    const float* __restrict__ s2, const float* __restrict__ s3,
    __nv_bfloat16* __restrict__ d0, __nv_bfloat16* __restrict__ d1,
    __nv_bfloat16* __restrict__ d2, __nv_bfloat16* __restrict__ d3)
{
    const int seg = blockIdx.x >> 7;
    const int i = ((blockIdx.x & 127) * 256 + threadIdx.x) * 2;
    const float* s = (seg == 0) ? s0 : (seg == 1) ? s1 : (seg == 2) ? s2 : s3;
    __nv_bfloat16* d = (seg == 0) ? d0 : (seg == 1) ? d1 : (seg == 2) ? d2 : d3;
    float2 v = *(const float2*)&s[i];
    *(uint32_t*)&d[i] = packbf(v.x, v.y);
}

// x[z][c][n] f32 -> xb[z][n][c] bf16 (32x32 smem-tile transpose)
__global__ __launch_bounds__(256) void xpose(
    const float* __restrict__ x, __nv_bfloat16* __restrict__ xb)
{
    __shared__ float ts[32][33];
    const int z = blockIdx.z;
    const int nx = blockIdx.x * 32, cy = blockIdx.y * 32;
    const int tx = threadIdx.x & 31, ty = threadIdx.x >> 5;
#pragma unroll
    for (int i = 0; i < 4; i++) {
        int c = cy + ty + i * 8;
        ts[ty + i * 8][tx] = x[((size_t)z * CDIM + c) * HWN + nx + tx];
    }
    __syncthreads();
#pragma unroll
    for (int i = 0; i < 4; i++) {
        int n = nx + ty + i * 8;
        xb[((size_t)z * HWN + n) * CDIM + cy + tx] =
            __float2bfloat16(ts[tx][ty + i * 8]);
    }
}

// ---------------------------------------------------------------------------
// Fused QKV GEMM, bf16 m16n8k16, ldmatrix fragment feeding (unchanged R9).
// ---------------------------------------------------------------------------
__global__ __launch_bounds__(256) void gemm_qkv(
    const __nv_bfloat16* __restrict__ xb,
    const __nv_bfloat16* __restrict__ Wqb, const __nv_bfloat16* __restrict__ Wkb,
    const __nv_bfloat16* __restrict__ Wvb, const float* __restrict__ bv,
    __nv_bfloat16* __restrict__ qo, __nv_bfloat16* __restrict__ ko,
    __nv_bfloat16* __restrict__ vo)
{
    extern __shared__ __nv_bfloat16 sb[];
    __nv_bfloat16* Xs = sb;                       // [64][136]
    __nv_bfloat16* WsA[2] = {sb + 8704, sb + 17408};
    const uint32_t xs_a = smem_u32(Xs);
    const uint32_t ws_a[2] = {smem_u32(WsA[0]), smem_u32(WsA[1])};

    const int z = blockIdx.z;
    const int n0 = blockIdx.x * 64;
    const int o0 = blockIdx.y * 64;
    const int tid = threadIdx.x;
    const int w = tid >> 5, lane = tid & 31;
    const int g = lane >> 2, t = lane & 3;
    const int wo = w >> 2, wn = w & 3;
    const int l7 = lane & 7, mi = lane >> 3;

    uint32_t a_off[2], b_off;
#pragma unroll
    for (int i = 0; i < 2; i++)
        a_off[i] = (uint32_t)((wo * 32 + i * 16 + (mi & 1) * 8 + l7) * 272
                              + (mi >> 1) * 16);
    b_off = (uint32_t)((wn * 16 + (mi >> 1) * 8 + l7) * 272 + (mi & 1) * 16);

    const __nv_bfloat16* Wmat[3] = {Wqb, Wkb, Wvb};
    const __nv_bfloat16* xrow = xb + ((size_t)z * HWN + n0) * CDIM;

#pragma unroll
    for (int p = 0; p < 4; p++) {
        int idx = tid + p * 256;
        int r = idx >> 4, c = idx & 15;
        cpa16(xs_a + (uint32_t)(r * 272 + c * 16), &xrow[(size_t)r * CDIM + c * 8]);
    }
#pragma unroll
    for (int p = 0; p < 4; p++) {
        int idx = tid + p * 256;
        int r = idx >> 4, c = idx & 15;
        cpa16(ws_a[0] + (uint32_t)(r * 272 + c * 16),
              &Wqb[(size_t)(o0 + r) * CDIM + c * 8]);
    }
    CP_COMMIT();

    for (int mat = 0; mat < 3; mat++) {
        if (mat < 2) {
            const __nv_bfloat16* Wn = Wmat[mat + 1];
#pragma unroll
            for (int p = 0; p < 4; p++) {
                int idx = tid + p * 256;
                int r = idx >> 4, c = idx & 15;
                cpa16(ws_a[(mat + 1) & 1] + (uint32_t)(r * 272 + c * 16),
                      &Wn[(size_t)(o0 + r) * CDIM + c * 8]);
            }
            CP_COMMIT();
            CP_WAIT1();
        } else {
            CP_WAIT0();
        }
        __syncthreads();

        const uint32_t wcur = ws_a[mat & 1];
        float acc[2][2][4] = {};
#pragma unroll
        for (int kk = 0; kk < 8; kk++) {
            uint32_t a0[4], a1[4], bb[4];
            ldsm4(a0, wcur + a_off[0] + kk * 32);
            ldsm4(a1, wcur + a_off[1] + kk * 32);
            ldsm4(bb, xs_a + b_off + kk * 32);
            mma16(acc[0][0], a0, bb[0], bb[1]);
            mma16(acc[0][1], a0, bb[2], bb[3]);
            mma16(acc[1][0], a1, bb[0], bb[1]);
            mma16(acc[1][1], a1, bb[2], bb[3]);
        }
        __syncthreads();

        if (mat < 2) {
            float* Cs = (float*)WsA[mat & 1];
#pragma unroll
            for (int i = 0; i < 2; i++) {
                int ol = wo * 32 + i * 16 + g;
#pragma unroll
                for (int j = 0; j < 2; j++) {
                    int nl = wn * 16 + j * 8 + 2 * t;
                    Cs[nl * 68 + ol]           = acc[i][j][0];
                    Cs[(nl + 1) * 68 + ol]     = acc[i][j][1];
                    Cs[nl * 68 + ol + 8]       = acc[i][j][2];
                    Cs[(nl + 1) * 68 + ol + 8] = acc[i][j][3];
                }
            }
            __syncthreads();
            __nv_bfloat16* C = (mat == 0) ? qo : ko;
            const int head = o0 >> 7, d0 = o0 & 127;
#pragma unroll
            for (int p = 0; p < 4; p++) {
                int idx = p * 256 + tid;
                int nl = idx >> 4, o4 = (idx & 15) * 4;
                float4 vv = *(float4*)&Cs[nl * 68 + o4];
                uint2 pk = make_uint2(packbf(vv.x, vv.y), packbf(vv.z, vv.w));
                *(uint2*)&C[(((size_t)z * 4 + head) * HWN + n0 + nl) * CDIM + d0 + o4] = pk;
            }
            __syncthreads();
        } else {
#pragma unroll
            for (int i = 0; i < 2; i++) {
                int ob = o0 + wo * 32 + i * 16 + g;
#pragma unroll
                for (int rr = 0; rr < 2; rr++) {
                    int orow = ob + rr * 8;
                    float bi = bv[orow];
#pragma unroll
                    for (int j = 0; j < 2; j++) {
                        int n = n0 + wn * 16 + j * 8 + 2 * t;
                        size_t addr = (size_t)z * EXPD * HWN + (size_t)orow * HWN + n;
                        *(uint32_t*)&vo[addr] = packbf(acc[i][j][rr * 2 + 0] + bi,
                                                       acc[i][j][rr * 2 + 1] + bi);
                    }
                }
            }
        }
    }
}

// ---------------------------------------------------------------------------
// Projection GEMM, bf16 m16n8k16 (unchanged R9).
// ---------------------------------------------------------------------------
__global__ __launch_bounds__(256) void gemm_proj(
    const __nv_bfloat16* __restrict__ A, const __nv_bfloat16* __restrict__ Bbase,
    const float* __restrict__ bias, const float* __restrict__ resid,
    float* __restrict__ C)
{
    extern __shared__ __nv_bfloat16 sb[];
    __nv_bfloat16* Ws = sb;            // [64][136]
    __nv_bfloat16* Xs = sb + 8704;     // [128][72]
    const uint32_t ws_a = smem_u32(Ws), xs_a = smem_u32(Xs);

    const int z = blockIdx.z;
    const __nv_bfloat16* B = Bbase + (size_t)z * EXPD * HWN;
    const int n0 = blockIdx.x * 64;
    const int o0 = blockIdx.y * 64;
    const int tid = threadIdx.x;
    const int w = tid >> 5, lane = tid & 31;
    const int g = lane >> 2, t = lane & 3;
    const int wo = w >> 2, wn = w & 3;
    const int l7 = lane & 7, mi = lane >> 3;

    uint32_t a_off[2];
#pragma unroll
    for (int i = 0; i < 2; i++)
        a_off[i] = (uint32_t)((wo * 32 + i * 16 + (mi & 1) * 8 + l7) * 272
                              + (mi >> 1) * 16);
    const uint32_t b_off = (uint32_t)(((mi & 1) * 8 + l7) * 144
                                      + (wn * 16 + (mi >> 1) * 8) * 2);

    float acc[2][2][4] = {};

    for (int k0 = 0; k0 < EXPD; k0 += 128) {
#pragma unroll
        for (int p = 0; p < 4; p++) {
            int idx = tid + p * 256;
            int r = idx >> 4, c = idx & 15;
            cpa16(ws_a + (uint32_t)(r * 272 + c * 16),
                  &A[(size_t)(o0 + r) * EXPD + k0 + c * 8]);
        }
#pragma unroll
        for (int p = 0; p < 4; p++) {
            int idx = tid + p * 256;
            int r = idx >> 3, c = idx & 7;
            cpa16(xs_a + (uint32_t)(r * 144 + c * 16),
                  &B[(size_t)(k0 + r) * HWN + n0 + c * 8]);
        }
        CP_COMMIT();
        CP_WAIT0();
        __syncthreads();

#pragma unroll
        for (int kk = 0; kk < 8; kk++) {
            uint32_t a0[4], a1[4], bb[4];
            ldsm4(a0, ws_a + a_off[0] + kk * 32);
            ldsm4(a1, ws_a + a_off[1] + kk * 32);
            ldsm4t(bb, xs_a + b_off + (uint32_t)kk * 2304);
            mma16(acc[0][0], a0, bb[0], bb[1]);
            mma16(acc[0][1], a0, bb[2], bb[3]);
            mma16(acc[1][0], a1, bb[0], bb[1]);
            mma16(acc[1][1], a1, bb[2], bb[3]);
        }
        __syncthreads();
    }

#pragma unroll
    for (int i = 0; i < 2; i++) {
        int ob = o0 + wo * 32 + i * 16 + g;
#pragma unroll
        for (int rr = 0; rr < 2; rr++) {
            int orow = ob + rr * 8;
            float bi = bias[orow];
#pragma unroll
            for (int j = 0; j < 2; j++) {
                int n = n0 + wn * 16 + j * 8 + 2 * t;
                size_t addr = (size_t)z * CDIM * HWN + (size_t)orow * HWN + n;
                float2 v = make_float2(acc[i][j][rr * 2 + 0] + bi,
                                       acc[i][j][rr * 2 + 1] + bi);
                float2 x2 = *(const float2*)&resid[addr];
                v.x += x2.x; v.y += x2.y;
                *(float2*)&C[addr] = v;
            }
        }
    }
}

// ---------------------------------------------------------------------------
// Warp-specialized attention, m-tile 128 (bf16 m16n8k16 + ldmatrix), 512 thr.
// S-warps 0-7 produce P; V-warps 8-15 consume one tile behind.
// SMEM (bytes): Kbuf[2] @ 0,34816 ([128][136] bf16); Vbuf[2] @ 69632,104448;
//               Pbuf @ 139264 (2 x 32768); rinv @ 204800 (128 f32). Tot 205312.
// ---------------------------------------------------------------------------
__device__ __forceinline__ void pv_half(float (&oacc)[16][4], uint32_t vs_a,
                                        const uint32_t* Pr, int h, int l7, int mi) {
    uint32_t pa[4][4];
#pragma unroll
    for (int r = 0; r < 16; r++)
        pa[r >> 2][r & 3] = Pr[(h * 16 + r) * 256];
#pragma unroll
    for (int d8 = 0; d8 < 16; d8++) {
        uint32_t base = vs_a + (uint32_t)((d8 * 8 + l7) * 272 + mi * 16 + h * 128);
        uint32_t v0[4], v1[4];
        ldsm4(v0, base);
        ldsm4(v1, base + 64);
        mma16(oacc[d8], pa[0], v0[0], v0[1]);
        mma16(oacc[d8], pa[1], v0[2], v0[3]);
        mma16(oacc[d8], pa[2], v1[0], v1[1]);
        mma16(oacc[d8], pa[3], v1[2], v1[3]);
    }
}

__global__ __launch_bounds__(512, 1) void attn_mma(
    const __nv_bfloat16* __restrict__ gq, const __nv_bfloat16* __restrict__ gk,
    const __nv_bfloat16* __restrict__ gv, __nv_bfloat16* __restrict__ gwsv)
{
    extern __shared__ __nv_bfloat16 smb[];
    char* base = (char*)smb;
    const uint32_t sm_a = smem_u32(base);
    uint32_t* Pbuf = (uint32_t*)(base + 139264);
    float* rinv_s = (float*)(base + 204800);

    const int tid = threadIdx.x;
    const int w = tid >> 5, lane = tid & 31;
    const int g = lane >> 2, t = lane & 3;
    const int l7 = lane & 7, mi = lane >> 3;
    const int b = blockIdx.z, h = blockIdx.y;
    const int bh = b * 4 + h;
    const int n0 = blockIdx.x * 128;
    const float CEXP = 0.08838834764831843f * 1.4426950408889634f;

    const __nv_bfloat16* Qg = gq + ((size_t)bh * HWN + n0) * CDIM;
    const __nv_bfloat16* Kg = gk + (size_t)bh * HWN * CDIM;
    const __nv_bfloat16* Vg = gv + (size_t)bh * CDIM * HWN;

    // ---- stage Q [128][136] into Kbuf0 (all 512 threads) ----
#pragma unroll
    for (int p = 0; p < 4; p++) {
        int idx = tid + p * 512;
        int r = idx >> 4, c = idx & 15;
        cpa16(sm_a + (uint32_t)(r * 272 + c * 16), &Qg[(size_t)r * CDIM + c * 8]);
    }
    CP_COMMIT();
    CP_WAIT0();
    BARX();   // (A) Q visible

    if (w < 8) {
        // ================= S-warps =================
        uint32_t qa[8][4];
        {
            uint32_t qoff = sm_a + (uint32_t)((w * 16 + (mi & 1) * 8 + l7) * 272
                                              + (mi >> 1) * 16);
#pragma unroll
            for (int k = 0; k < 8; k++)
                ldsm4(qa[k], qoff + k * 32);
        }
        BARX();   // (B) qa extracted; safe to overwrite Kbuf0

        // issue K(0)
#pragma unroll
        for (int p = 0; p < 8; p++) {
            int idx = tid + p * 256;
            int r = idx >> 4, c = idx & 15;
            cpa16(sm_a + (uint32_t)(r * 272 + c * 16),
                  &Kg[(size_t)r * CDIM + c * 8]);
        }
        CP_COMMIT();

        float rs0 = 0.f, rs1 = 0.f;
        for (int mt = 0; mt < 8; mt++) {
            CP_WAIT0();        // K(mt) ready
            BARX();            // top

            // prefetch K(mt+1)
            if (mt + 1 < 8) {
                const int m0 = (mt + 1) * 128;
                const uint32_t kb = sm_a + (uint32_t)(((mt + 1) & 1) * 34816);
#pragma unroll
                for (int p = 0; p < 8; p++) {
                    int idx = tid + p * 256;
                    int r = idx >> 4, c = idx & 15;
                    cpa16(kb + (uint32_t)(r * 272 + c * 16),
                          &Kg[(size_t)(m0 + r) * CDIM + c * 8]);
                }
            }
            CP_COMMIT();

            const uint32_t ks = sm_a + (uint32_t)((mt & 1) * 34816);
            uint32_t* Pw = Pbuf + (mt & 1) * 8192 + w * 32 + lane;
#pragma unroll
            for (int m8 = 0; m8 < 16; m8++) {
                uint32_t kb0[4], kb1[4], kb2[4], kb3[4];
                uint32_t kbase = ks + (uint32_t)((m8 * 8 + l7) * 272 + mi * 16);
                ldsm4(kb0, kbase);
                ldsm4(kb1, kbase + 64);
                ldsm4(kb2, kbase + 128);
                ldsm4(kb3, kbase + 192);
                float s0[4] = {0.f, 0.f, 0.f, 0.f};
                float s1[4] = {0.f, 0.f, 0.f, 0.f};
                mma16(s0, qa[0], kb0[0], kb0[1]);
                mma16(s0, qa[1], kb0[2], kb0[3]);
                mma16(s0, qa[2], kb1[0], kb1[1]);
                mma16(s0, qa[3], kb1[2], kb1[3]);
                mma16(s1, qa[4], kb2[0], kb2[1]);
                mma16(s1, qa[5], kb2[2], kb2[3]);
                mma16(s1, qa[6], kb3[0], kb3[1]);
                mma16(s1, qa[7], kb3[2], kb3[3]);
                float e0 = ex2a((s0[0] + s1[0]) * CEXP);
                float e1 = ex2a((s0[1] + s1[1]) * CEXP);
                float e2 = ex2a((s0[2] + s1[2]) * CEXP);
                float e3 = ex2a((s0[3] + s1[3]) * CEXP);
                rs0 += e0 + e1;
                rs1 += e2 + e3;
                int r = m8 * 2;
                Pw[(r + 0) * 256] = packbf(e0, e1);
                Pw[(r + 1) * 256] = packbf(e2, e3);
            }
            BARX();            // end: P(mt) published
        }

        BARX();   // post
        rs0 += __shfl_xor_sync(~0u, rs0, 1);
        rs0 += __shfl_xor_sync(~0u, rs0, 2);
        rs1 += __shfl_xor_sync(~0u, rs1, 1);
        rs1 += __shfl_xor_sync(~0u, rs1, 2);
        if (t == 0) {
            rinv_s[w * 16 + g]     = 1.f / rs0;
            rinv_s[w * 16 + g + 8] = 1.f / rs1;
        }
        BARX();   // final
    } else {
        // ================= V-warps =================
        const int v = w - 8;
        const int vt = tid - 256;
        BARX();   // (B)

        // issue V(0)
#pragma unroll
        for (int p = 0; p < 8; p++) {
            int idx = vt + p * 256;
            int r = idx >> 4, c = idx & 15;
            cpa16(sm_a + (uint32_t)(69632 + r * 272 + c * 16),
                  &Vg[(size_t)r * HWN + c * 8]);
        }
        CP_COMMIT();

        float oacc[16][4] = {};
        for (int mt = 0; mt < 8; mt++) {
            CP_WAIT1();        // V(mt-1) ready (V(mt) still flying)
            BARX();            // top

            if (mt >= 1) {
                uint32_t vs = sm_a + (uint32_t)(69632 + ((mt - 1) & 1) * 34816);
                const uint32_t* Pr = Pbuf + ((mt - 1) & 1) * 8192 + v * 32 + lane;
                pv_half(oacc, vs, Pr, 0, l7, mi);
                pv_half(oacc, vs, Pr, 1, l7, mi);
            }
            BARX();            // end: all V-warps done with V(mt-1)

            if (mt + 1 < 8) {
                const int m0 = (mt + 1) * 128;
                const uint32_t vb = sm_a + (uint32_t)(69632 + ((mt + 1) & 1) * 34816);
#pragma unroll
                for (int p = 0; p < 8; p++) {
                    int idx = vt + p * 256;
                    int r = idx >> 4, c = idx & 15;
                    cpa16(vb + (uint32_t)(r * 272 + c * 16),
                          &Vg[(size_t)r * HWN + m0 + c * 8]);
                }
            }
            CP_COMMIT();
        }

        CP_WAIT0();   // V(7) done
        BARX();       // post
        {
            uint32_t vs = sm_a + (uint32_t)(69632 + 34816);   // buf 7&1 = 1
            const uint32_t* Pr = Pbuf + 8192 + v * 32 + lane; // P(7) buf 1
            pv_half(oacc, vs, Pr, 0, l7, mi);
            pv_half(oacc, vs, Pr, 1, l7, mi);
        }
        BARX();       // final: rinv ready

        const float ri0 = rinv_s[v * 16 + g];
        const float ri1 = rinv_s[v * 16 + g + 8];
        const int nA = n0 + v * 16 + g;
        const int nB = nA + 8;
        const size_t obA = ((size_t)b * EXPD + h * CDIM + (nA >> 3)) * HWN
                         + (size_t)(nA & 7) * CDIM;
        const size_t obB = ((size_t)b * EXPD + h * CDIM + (nB >> 3)) * HWN
                         + (size_t)(nB & 7) * CDIM;
#pragma unroll
        for (int d8 = 0; d8 < 16; d8++) {
            int d = d8 * 8 + 2 * t;
            *(uint32_t*)&gwsv[obA + d] = packbf(oacc[d8][0] * ri0,
                                                oacc[d8][1] * ri0);
            *(uint32_t*)&gwsv[obB + d] = packbf(oacc[d8][2] * ri1,
                                                oacc[d8][3] * ri1);
        }
    }
}

// ---------------------------------------------------------------------------
extern "C" void kernel_launch(void* const* d_in, const int* in_sizes, int n_in,
                              void* d_out, int out_size)
{
    const float* x  = (const float*)d_in[0];
    const float* Wq = (const float*)d_in[1];
    const float* Wk = (const float*)d_in[2];
    const float* Wv = (const float*)d_in[3];
    const float* bv = (const float*)d_in[4];
    const float* Wt = (const float*)d_in[5];
    const float* bt = (const float*)d_in[6];
    float* out = (float*)d_out;

    __nv_bfloat16 *pq, *pk, *pv, *pw, *pxb, *pwq, *pwk, *pwv, *pwt;
    cudaGetSymbolAddress((void**)&pq, g_q);
    cudaGetSymbolAddress((void**)&pk, g_k);
    cudaGetSymbolAddress((void**)&pv, g_v);
    cudaGetSymbolAddress((void**)&pw, g_wsv);
    cudaGetSymbolAddress((void**)&pxb, g_xb);
    cudaGetSymbolAddress((void**)&pwq, g_wqb);
    cudaGetSymbolAddress((void**)&pwk, g_wkb);
    cudaGetSymbolAddress((void**)&pwv, g_wvb);
    cudaGetSymbolAddress((void**)&pwt, g_wtb);

    // All weight conversions in one launch; x transpose in another
    cvt_all<<<512, 256>>>(Wq, Wk, Wv, Wt, pwq, pwk, pwv, pwt);
    xpose<<<dim3(HWN / 32, CDIM / 32, NB), 256>>>(x, pxb);

    // Fused QKV projections (bf16 mma + ldmatrix)
    const int qkvsmem = 3 * 17408;   // 52224 B
    cudaFuncSetAttribute(gemm_qkv, cudaFuncAttributeMaxDynamicSharedMemorySize,
                         qkvsmem);
    gemm_qkv<<<dim3(HWN / 64, EXPD / 64, NB), 256, qkvsmem>>>(
        pxb, pwq, pwk, pwv, bv, pq, pk, pv);

    // Warp-specialized bf16 attention, m-tile 128
    const int asmem = 205312;
    cudaFuncSetAttribute(attn_mma, cudaFuncAttributeMaxDynamicSharedMemorySize,
                         asmem);
    attn_mma<<<dim3(8, 4, NB), 512, asmem>>>(pq, pk, pv, pw);

    // Output projection + bias + residual (bf16 mma + ldmatrix, f32 out)
    const int psmem = 17408 + 18432;  // 35840 B
    cudaFuncSetAttribute(gemm_proj, cudaFuncAttributeMaxDynamicSharedMemorySize,
                         psmem);
    gemm_proj<<<dim3(HWN / 64, CDIM / 64, NB), 256, psmem>>>(
        pwt, pw, bt, x, out);
}

// round 11
// speedup vs baseline: 10.5055x; 1.0939x over previous
#include <cuda_runtime.h>
#include <cuda_bf16.h>
#include <cstdint>

#define HWN 1024
#define CDIM 128
#define EXPD 512
#define NB   16

// Scratch (allocation-free rule: static __device__ arrays)
__device__ __align__(128) __nv_bfloat16 g_q[NB * EXPD * HWN]; // [b][h][n][d]
__device__ __align__(128) __nv_bfloat16 g_k[NB * EXPD * HWN]; // [b][h][m][d]
__device__ __align__(128) __nv_bfloat16 g_v[NB * EXPD * HWN]; // [b][h][d][m]
__device__ __align__(128) __nv_bfloat16 g_wsv[NB * EXPD * HWN]; // bf16 [b][c'][pix]
__device__ __align__(128) __nv_bfloat16 g_xb[NB * HWN * CDIM];  // x^T bf16 [b][n][c]
__device__ __align__(128) __nv_bfloat16 g_wqb[EXPD * CDIM];
__device__ __align__(128) __nv_bfloat16 g_wkb[EXPD * CDIM];
__device__ __align__(128) __nv_bfloat16 g_wvb[EXPD * CDIM];
__device__ __align__(128) __nv_bfloat16 g_wtb[CDIM * EXPD];

// ---------------------------------------------------------------------------
__device__ __forceinline__ uint32_t smem_u32(const void* p) {
    uint32_t a;
    asm("{ .reg .u64 t; cvta.to.shared.u64 t, %1; cvt.u32.u64 %0, t; }"
        : "=r"(a) : "l"(p));
    return a;
}

__device__ __forceinline__ void cpa16(uint32_t dst, const void* src) {
    asm volatile("cp.async.ca.shared.global [%0], [%1], 16;"
                 :: "r"(dst), "l"(src));
}
#define CP_COMMIT() asm volatile("cp.async.commit_group;")
#define CP_WAIT0()  asm volatile("cp.async.wait_group 0;")
#define CP_WAIT1()  asm volatile("cp.async.wait_group 1;")

// bf16 m16n8k16 mma
__device__ __forceinline__ void mma16(float (&d)[4], const uint32_t (&a)[4],
                                      uint32_t b0, uint32_t b1) {
    asm volatile(
        "mma.sync.aligned.m16n8k16.row.col.f32.bf16.bf16.f32 "
        "{%0,%1,%2,%3}, {%4,%5,%6,%7}, {%8,%9}, {%0,%1,%2,%3};"
        : "+f"(d[0]), "+f"(d[1]), "+f"(d[2]), "+f"(d[3])
        : "r"(a[0]), "r"(a[1]), "r"(a[2]), "r"(a[3]), "r"(b0), "r"(b1));
}

__device__ __forceinline__ void ldsm4(uint32_t (&r)[4], uint32_t addr) {
    asm volatile("ldmatrix.sync.aligned.m8n8.x4.shared.b16 {%0,%1,%2,%3}, [%4];"
                 : "=r"(r[0]), "=r"(r[1]), "=r"(r[2]), "=r"(r[3]) : "r"(addr));
}
__device__ __forceinline__ void ldsm4t(uint32_t (&r)[4], uint32_t addr) {
    asm volatile("ldmatrix.sync.aligned.m8n8.x4.trans.shared.b16 {%0,%1,%2,%3}, [%4];"
                 : "=r"(r[0]), "=r"(r[1]), "=r"(r[2]), "=r"(r[3]) : "r"(addr));
}

__device__ __forceinline__ uint32_t packbf(float lo, float hi) {
    uint32_t d;
    asm("cvt.rn.bf16x2.f32 %0, %1, %2;" : "=r"(d) : "f"(hi), "f"(lo));
    return d;
}

__device__ __forceinline__ float ex2a(float x) {
    float r;
    asm("ex2.approx.ftz.f32 %0, %1;" : "=f"(r) : "f"(x));
    return r;
}

// ---------------------------------------------------------------------------
// All four weight conversions in ONE launch. 4 segments x 65536 elems.
__global__ __launch_bounds__(256) void cvt_all(
    const float* __restrict__ s0, const float* __restrict__ s1,
    const float* __restrict__ s2, const float* __restrict__ s3,
    __nv_bfloat16* __restrict__ d0, __nv_bfloat16* __restrict__ d1,
    __nv_bfloat16* __restrict__ d2, __nv_bfloat16* __restrict__ d3)
{
    const int seg = blockIdx.x >> 7;
    const int i = ((blockIdx.x & 127) * 256 + threadIdx.x) * 2;
    const float* s = (seg == 0) ? s0 : (seg == 1) ? s1 : (seg == 2) ? s2 : s3;
    __nv_bfloat16* d = (seg == 0) ? d0 : (seg == 1) ? d1 : (seg == 2) ? d2 : d3;
    float2 v = *(const float2*)&s[i];
    *(uint32_t*)&d[i] = packbf(v.x, v.y);
}

// x[z][c][n] f32 -> xb[z][n][c] bf16 (32x32 smem-tile transpose)
__global__ __launch_bounds__(256) void xpose(
    const float* __restrict__ x, __nv_bfloat16* __restrict__ xb)
{
    __shared__ float ts[32][33];
    const int z = blockIdx.z;
    const int nx = blockIdx.x * 32, cy = blockIdx.y * 32;
    const int tx = threadIdx.x & 31, ty = threadIdx.x >> 5;
#pragma unroll
    for (int i = 0; i < 4; i++) {
        int c = cy + ty + i * 8;
        ts[ty + i * 8][tx] = x[((size_t)z * CDIM + c) * HWN + nx + tx];
    }
    __syncthreads();
#pragma unroll
    for (int i = 0; i < 4; i++) {
        int n = nx + ty + i * 8;
        xb[((size_t)z * HWN + n) * CDIM + cy + tx] =
            __float2bfloat16(ts[tx][ty + i * 8]);
    }
}

// ---------------------------------------------------------------------------
// Fused QKV GEMM, bf16 m16n8k16, ldmatrix (unchanged R9/R10).
// ---------------------------------------------------------------------------
__global__ __launch_bounds__(256) void gemm_qkv(
    const __nv_bfloat16* __restrict__ xb,
    const __nv_bfloat16* __restrict__ Wqb, const __nv_bfloat16* __restrict__ Wkb,
    const __nv_bfloat16* __restrict__ Wvb, const float* __restrict__ bv,
    __nv_bfloat16* __restrict__ qo, __nv_bfloat16* __restrict__ ko,
    __nv_bfloat16* __restrict__ vo)
{
    extern __shared__ __nv_bfloat16 sb[];
    __nv_bfloat16* Xs = sb;                       // [64][136]
    __nv_bfloat16* WsA[2] = {sb + 8704, sb + 17408};
    const uint32_t xs_a = smem_u32(Xs);
    const uint32_t ws_a[2] = {smem_u32(WsA[0]), smem_u32(WsA[1])};

    const int z = blockIdx.z;
    const int n0 = blockIdx.x * 64;
    const int o0 = blockIdx.y * 64;
    const int tid = threadIdx.x;
    const int w = tid >> 5, lane = tid & 31;
    const int g = lane >> 2, t = lane & 3;
    const int wo = w >> 2, wn = w & 3;
    const int l7 = lane & 7, mi = lane >> 3;

    uint32_t a_off[2], b_off;
#pragma unroll
    for (int i = 0; i < 2; i++)
        a_off[i] = (uint32_t)((wo * 32 + i * 16 + (mi & 1) * 8 + l7) * 272
                              + (mi >> 1) * 16);
    b_off = (uint32_t)((wn * 16 + (mi >> 1) * 8 + l7) * 272 + (mi & 1) * 16);

    const __nv_bfloat16* Wmat[3] = {Wqb, Wkb, Wvb};
    const __nv_bfloat16* xrow = xb + ((size_t)z * HWN + n0) * CDIM;

#pragma unroll
    for (int p = 0; p < 4; p++) {
        int idx = tid + p * 256;
        int r = idx >> 4, c = idx & 15;
        cpa16(xs_a + (uint32_t)(r * 272 + c * 16), &xrow[(size_t)r * CDIM + c * 8]);
    }
#pragma unroll
    for (int p = 0; p < 4; p++) {
        int idx = tid + p * 256;
        int r = idx >> 4, c = idx & 15;
        cpa16(ws_a[0] + (uint32_t)(r * 272 + c * 16),
              &Wqb[(size_t)(o0 + r) * CDIM + c * 8]);
    }
    CP_COMMIT();

    for (int mat = 0; mat < 3; mat++) {
        if (mat < 2) {
            const __nv_bfloat16* Wn = Wmat[mat + 1];
#pragma unroll
            for (int p = 0; p < 4; p++) {
                int idx = tid + p * 256;
                int r = idx >> 4, c = idx & 15;
                cpa16(ws_a[(mat + 1) & 1] + (uint32_t)(r * 272 + c * 16),
                      &Wn[(size_t)(o0 + r) * CDIM + c * 8]);
            }
            CP_COMMIT();
            CP_WAIT1();
        } else {
            CP_WAIT0();
        }
        __syncthreads();

        const uint32_t wcur = ws_a[mat & 1];
        float acc[2][2][4] = {};
#pragma unroll
        for (int kk = 0; kk < 8; kk++) {
            uint32_t a0[4], a1[4], bb[4];
            ldsm4(a0, wcur + a_off[0] + kk * 32);
            ldsm4(a1, wcur + a_off[1] + kk * 32);
            ldsm4(bb, xs_a + b_off + kk * 32);
            mma16(acc[0][0], a0, bb[0], bb[1]);
            mma16(acc[0][1], a0, bb[2], bb[3]);
            mma16(acc[1][0], a1, bb[0], bb[1]);
            mma16(acc[1][1], a1, bb[2], bb[3]);
        }
        __syncthreads();

        if (mat < 2) {
            float* Cs = (float*)WsA[mat & 1];
#pragma unroll
            for (int i = 0; i < 2; i++) {
                int ol = wo * 32 + i * 16 + g;
#pragma unroll
                for (int j = 0; j < 2; j++) {
                    int nl = wn * 16 + j * 8 + 2 * t;
                    Cs[nl * 68 + ol]           = acc[i][j][0];
                    Cs[(nl + 1) * 68 + ol]     = acc[i][j][1];
                    Cs[nl * 68 + ol + 8]       = acc[i][j][2];
                    Cs[(nl + 1) * 68 + ol + 8] = acc[i][j][3];
                }
            }
            __syncthreads();
            __nv_bfloat16* C = (mat == 0) ? qo : ko;
            const int head = o0 >> 7, d0 = o0 & 127;
#pragma unroll
            for (int p = 0; p < 4; p++) {
                int idx = p * 256 + tid;
                int nl = idx >> 4, o4 = (idx & 15) * 4;
                float4 vv = *(float4*)&Cs[nl * 68 + o4];
                uint2 pk = make_uint2(packbf(vv.x, vv.y), packbf(vv.z, vv.w));
                *(uint2*)&C[(((size_t)z * 4 + head) * HWN + n0 + nl) * CDIM + d0 + o4] = pk;
            }
            __syncthreads();
        } else {
#pragma unroll
            for (int i = 0; i < 2; i++) {
                int ob = o0 + wo * 32 + i * 16 + g;
#pragma unroll
                for (int rr = 0; rr < 2; rr++) {
                    int orow = ob + rr * 8;
                    float bi = bv[orow];
#pragma unroll
                    for (int j = 0; j < 2; j++) {
                        int n = n0 + wn * 16 + j * 8 + 2 * t;
                        size_t addr = (size_t)z * EXPD * HWN + (size_t)orow * HWN + n;
                        *(uint32_t*)&vo[addr] = packbf(acc[i][j][rr * 2 + 0] + bi,
                                                       acc[i][j][rr * 2 + 1] + bi);
                    }
                }
            }
        }
    }
}

// ---------------------------------------------------------------------------
// Projection GEMM, bf16 m16n8k16 (unchanged R9/R10).
// ---------------------------------------------------------------------------
__global__ __launch_bounds__(256) void gemm_proj(
    const __nv_bfloat16* __restrict__ A, const __nv_bfloat16* __restrict__ Bbase,
    const float* __restrict__ bias, const float* __restrict__ resid,
    float* __restrict__ C)
{
    extern __shared__ __nv_bfloat16 sb[];
    __nv_bfloat16* Ws = sb;            // [64][136]
    __nv_bfloat16* Xs = sb + 8704;     // [128][72]
    const uint32_t ws_a = smem_u32(Ws), xs_a = smem_u32(Xs);

    const int z = blockIdx.z;
    const __nv_bfloat16* B = Bbase + (size_t)z * EXPD * HWN;
    const int n0 = blockIdx.x * 64;
    const int o0 = blockIdx.y * 64;
    const int tid = threadIdx.x;
    const int w = tid >> 5, lane = tid & 31;
    const int g = lane >> 2, t = lane & 3;
    const int wo = w >> 2, wn = w & 3;
    const int l7 = lane & 7, mi = lane >> 3;

    uint32_t a_off[2];
#pragma unroll
    for (int i = 0; i < 2; i++)
        a_off[i] = (uint32_t)((wo * 32 + i * 16 + (mi & 1) * 8 + l7) * 272
                              + (mi >> 1) * 16);
    const uint32_t b_off = (uint32_t)(((mi & 1) * 8 + l7) * 144
                                      + (wn * 16 + (mi >> 1) * 8) * 2);

    float acc[2][2][4] = {};

    for (int k0 = 0; k0 < EXPD; k0 += 128) {
#pragma unroll
        for (int p = 0; p < 4; p++) {
            int idx = tid + p * 256;
            int r = idx >> 4, c = idx & 15;
            cpa16(ws_a + (uint32_t)(r * 272 + c * 16),
                  &A[(size_t)(o0 + r) * EXPD + k0 + c * 8]);
        }
#pragma unroll
        for (int p = 0; p < 4; p++) {
            int idx = tid + p * 256;
            int r = idx >> 3, c = idx & 7;
            cpa16(xs_a + (uint32_t)(r * 144 + c * 16),
                  &B[(size_t)(k0 + r) * HWN + n0 + c * 8]);
        }
        CP_COMMIT();
        CP_WAIT0();
        __syncthreads();

#pragma unroll
        for (int kk = 0; kk < 8; kk++) {
            uint32_t a0[4], a1[4], bb[4];
            ldsm4(a0, ws_a + a_off[0] + kk * 32);
            ldsm4(a1, ws_a + a_off[1] + kk * 32);
            ldsm4t(bb, xs_a + b_off + (uint32_t)kk * 2304);
            mma16(acc[0][0], a0, bb[0], bb[1]);
            mma16(acc[0][1], a0, bb[2], bb[3]);
            mma16(acc[1][0], a1, bb[0], bb[1]);
            mma16(acc[1][1], a1, bb[2], bb[3]);
        }
        __syncthreads();
    }

#pragma unroll
    for (int i = 0; i < 2; i++) {
        int ob = o0 + wo * 32 + i * 16 + g;
#pragma unroll
        for (int rr = 0; rr < 2; rr++) {
            int orow = ob + rr * 8;
            float bi = bias[orow];
#pragma unroll
            for (int j = 0; j < 2; j++) {
                int n = n0 + wn * 16 + j * 8 + 2 * t;
                size_t addr = (size_t)z * CDIM * HWN + (size_t)orow * HWN + n;
                float2 v = make_float2(acc[i][j][rr * 2 + 0] + bi,
                                       acc[i][j][rr * 2 + 1] + bi);
                float2 x2 = *(const float2*)&resid[addr];
                v.x += x2.x; v.y += x2.y;
                *(float2*)&C[addr] = v;
            }
        }
    }
}

// ---------------------------------------------------------------------------
// Monolithic attention, 256 threads, 8 warps, 2 CTAs/SM.
// Warp owns 16 q-rows end-to-end; per km (16 m): S (8 K-ldsm4 + 16 MMA)
// -> exp -> pa (A-frag identity, 4 regs) -> PV (8 V-ldsm4 + 16 MMA).
// m-tile 64, double-buffered K/V cp.async, ONE barrier per tile.
// SMEM (bytes): Qs @0 (34816, persistent [128][136]);
//   Kb[2] @34816,52224 ([64][136]); Vb[2] @69632,88064 ([128][72]).
//   Total 106496 -> 2 CTAs/SM.
// ---------------------------------------------------------------------------
__global__ __launch_bounds__(256, 2) void attn_mma(
    const __nv_bfloat16* __restrict__ gq, const __nv_bfloat16* __restrict__ gk,
    const __nv_bfloat16* __restrict__ gv, __nv_bfloat16* __restrict__ gwsv)
{
    extern __shared__ __nv_bfloat16 smb[];
    const uint32_t sm_a = smem_u32(smb);

    const int tid = threadIdx.x;
    const int w = tid >> 5, lane = tid & 31;
    const int g = lane >> 2, t = lane & 3;
    const int l7 = lane & 7, mi = lane >> 3;
    const int b = blockIdx.z, h = blockIdx.y;
    const int bh = b * 4 + h;
    const int n0 = blockIdx.x * 128;
    const float CEXP = 0.08838834764831843f * 1.4426950408889634f;

    const __nv_bfloat16* Qg = gq + ((size_t)bh * HWN + n0) * CDIM;
    const __nv_bfloat16* Kg = gk + (size_t)bh * HWN * CDIM;
    const __nv_bfloat16* Vg = gv + (size_t)bh * CDIM * HWN;

    // ---- stage Q [128][136] (persistent) ----
#pragma unroll
    for (int p = 0; p < 8; p++) {
        int idx = tid + p * 256;
        int r = idx >> 4, c = idx & 15;
        cpa16(sm_a + (uint32_t)(r * 272 + c * 16), &Qg[(size_t)r * CDIM + c * 8]);
    }
    CP_COMMIT();
    CP_WAIT0();
    __syncthreads();

    // ---- persistent Q A-fragments (8 k16 chunks) ----
    uint32_t qa[8][4];
    {
        uint32_t qoff = sm_a + (uint32_t)((w * 16 + (mi & 1) * 8 + l7) * 272
                                          + (mi >> 1) * 16);
#pragma unroll
        for (int k = 0; k < 8; k++)
            ldsm4(qa[k], qoff + k * 32);
    }

    // ---- prefetch K(0),V(0) ----
#pragma unroll
    for (int p = 0; p < 4; p++) {
        int idx = tid + p * 256;
        int r = idx >> 4, c = idx & 15;
        cpa16(sm_a + (uint32_t)(34816 + r * 272 + c * 16),
              &Kg[(size_t)r * CDIM + c * 8]);
    }
#pragma unroll
    for (int p = 0; p < 4; p++) {
        int idx = tid + p * 256;
        int r = idx >> 3, c = idx & 7;
        cpa16(sm_a + (uint32_t)(69632 + r * 144 + c * 16),
              &Vg[(size_t)r * HWN + c * 8]);
    }
    CP_COMMIT();

    float oacc[16][4] = {};
    float rs0 = 0.f, rs1 = 0.f;

    for (int mt = 0; mt < 16; mt++) {
        CP_WAIT0();
        __syncthreads();   // tile mt visible; all warps done with tile mt-1

        // prefetch tile mt+1 into the other buffer
        if (mt + 1 < 16) {
            const int m0 = (mt + 1) * 64;
            const uint32_t kb = sm_a + (uint32_t)(34816 + ((mt + 1) & 1) * 17408);
            const uint32_t vb = sm_a + (uint32_t)(69632 + ((mt + 1) & 1) * 18432);
#pragma unroll
            for (int p = 0; p < 4; p++) {
                int idx = tid + p * 256;
                int r = idx >> 4, c = idx & 15;
                cpa16(kb + (uint32_t)(r * 272 + c * 16),
                      &Kg[(size_t)(m0 + r) * CDIM + c * 8]);
            }
#pragma unroll
            for (int p = 0; p < 4; p++) {
                int idx = tid + p * 256;
                int r = idx >> 3, c = idx & 7;
                cpa16(vb + (uint32_t)(r * 144 + c * 16),
                      &Vg[(size_t)r * HWN + m0 + c * 8]);
            }
            CP_COMMIT();
        }

        const uint32_t ks = sm_a + (uint32_t)(34816 + (mt & 1) * 17408);
        const uint32_t vs = sm_a + (uint32_t)(69632 + (mt & 1) * 18432);

#pragma unroll
        for (int km = 0; km < 4; km++) {
            // ---- S for 16 q-rows x 16 m (two m8 blocks) ----
            const uint32_t kbA = ks + (uint32_t)((km * 16 + l7) * 272 + mi * 16);
            const uint32_t kbB = kbA + 8 * 272;
            uint32_t k0[4], k1[4], k2[4], k3[4];
            float sa0[4] = {0.f, 0.f, 0.f, 0.f}, sa1[4] = {0.f, 0.f, 0.f, 0.f};
            float sb0[4] = {0.f, 0.f, 0.f, 0.f}, sb1[4] = {0.f, 0.f, 0.f, 0.f};
            ldsm4(k0, kbA);       // m8a, k0-31
            ldsm4(k1, kbA + 64);  // m8a, k32-63
            ldsm4(k2, kbA + 128); // m8a, k64-95
            ldsm4(k3, kbA + 192); // m8a, k96-127
            mma16(sa0, qa[0], k0[0], k0[1]);
            mma16(sa0, qa[1], k0[2], k0[3]);
            mma16(sa0, qa[2], k1[0], k1[1]);
            mma16(sa0, qa[3], k1[2], k1[3]);
            mma16(sa1, qa[4], k2[0], k2[1]);
            mma16(sa1, qa[5], k2[2], k2[3]);
            mma16(sa1, qa[6], k3[0], k3[1]);
            mma16(sa1, qa[7], k3[2], k3[3]);
            ldsm4(k0, kbB);
            ldsm4(k1, kbB + 64);
            ldsm4(k2, kbB + 128);
            ldsm4(k3, kbB + 192);
            mma16(sb0, qa[0], k0[0], k0[1]);
            mma16(sb0, qa[1], k0[2], k0[3]);
            mma16(sb0, qa[2], k1[0], k1[1]);
            mma16(sb0, qa[3], k1[2], k1[3]);
            mma16(sb1, qa[4], k2[0], k2[1]);
            mma16(sb1, qa[5], k2[2], k2[3]);
            mma16(sb1, qa[6], k3[0], k3[1]);
            mma16(sb1, qa[7], k3[2], k3[3]);

            // ---- exp -> P A-fragments (layout identity, no shuffles) ----
            float ea0 = ex2a((sa0[0] + sa1[0]) * CEXP);
            float ea1 = ex2a((sa0[1] + sa1[1]) * CEXP);
            float ea2 = ex2a((sa0[2] + sa1[2]) * CEXP);
            float ea3 = ex2a((sa0[3] + sa1[3]) * CEXP);
            float eb0 = ex2a((sb0[0] + sb1[0]) * CEXP);
            float eb1 = ex2a((sb0[1] + sb1[1]) * CEXP);
            float eb2 = ex2a((sb0[2] + sb1[2]) * CEXP);
            float eb3 = ex2a((sb0[3] + sb1[3]) * CEXP);
            rs0 += ea0 + ea1 + eb0 + eb1;
            rs1 += ea2 + ea3 + eb2 + eb3;
            uint32_t pa[4];
            pa[0] = packbf(ea0, ea1);   // rows g,   k = m lo8
            pa[1] = packbf(ea2, ea3);   // rows g+8, k = m lo8
            pa[2] = packbf(eb0, eb1);   // rows g,   k = m hi8
            pa[3] = packbf(eb2, eb3);   // rows g+8, k = m hi8

            // ---- PV: O += P V^T over this km (16 independent MMAs) ----
#pragma unroll
            for (int d8p = 0; d8p < 8; d8p++) {
                uint32_t vv[4];
                ldsm4(vv, vs + (uint32_t)((d8p * 16 + (mi & 1) * 8 + l7) * 144
                                          + km * 32 + (mi >> 1) * 16));
                mma16(oacc[2 * d8p],     pa, vv[0], vv[2]);
                mma16(oacc[2 * d8p + 1], pa, vv[1], vv[3]);
            }
        }
    }

    // ---- rowsum quad reduction, normalize, store ----
    rs0 += __shfl_xor_sync(~0u, rs0, 1);
    rs0 += __shfl_xor_sync(~0u, rs0, 2);
    rs1 += __shfl_xor_sync(~0u, rs1, 1);
    rs1 += __shfl_xor_sync(~0u, rs1, 2);
    const float ri0 = 1.f / rs0, ri1 = 1.f / rs1;

    const int nA = n0 + w * 16 + g;
    const int nB = nA + 8;
    const size_t obA = ((size_t)b * EXPD + h * CDIM + (nA >> 3)) * HWN
                     + (size_t)(nA & 7) * CDIM;
    const size_t obB = ((size_t)b * EXPD + h * CDIM + (nB >> 3)) * HWN
                     + (size_t)(nB & 7) * CDIM;
#pragma unroll
    for (int d8 = 0; d8 < 16; d8++) {
        int d = d8 * 8 + 2 * t;
        *(uint32_t*)&gwsv[obA + d] = packbf(oacc[d8][0] * ri0,
                                            oacc[d8][1] * ri0);
        *(uint32_t*)&gwsv[obB + d] = packbf(oacc[d8][2] * ri1,
                                            oacc[d8][3] * ri1);
    }
}

// ---------------------------------------------------------------------------
extern "C" void kernel_launch(void* const* d_in, const int* in_sizes, int n_in,
                              void* d_out, int out_size)
{
    const float* x  = (const float*)d_in[0];
    const float* Wq = (const float*)d_in[1];
    const float* Wk = (const float*)d_in[2];
    const float* Wv = (const float*)d_in[3];
    const float* bv = (const float*)d_in[4];
    const float* Wt = (const float*)d_in[5];
    const float* bt = (const float*)d_in[6];
    float* out = (float*)d_out;

    __nv_bfloat16 *pq, *pk, *pv, *pw, *pxb, *pwq, *pwk, *pwv, *pwt;
    cudaGetSymbolAddress((void**)&pq, g_q);
    cudaGetSymbolAddress((void**)&pk, g_k);
    cudaGetSymbolAddress((void**)&pv, g_v);
    cudaGetSymbolAddress((void**)&pw, g_wsv);
    cudaGetSymbolAddress((void**)&pxb, g_xb);
    cudaGetSymbolAddress((void**)&pwq, g_wqb);
    cudaGetSymbolAddress((void**)&pwk, g_wkb);
    cudaGetSymbolAddress((void**)&pwv, g_wvb);
    cudaGetSymbolAddress((void**)&pwt, g_wtb);

    cvt_all<<<512, 256>>>(Wq, Wk, Wv, Wt, pwq, pwk, pwv, pwt);
    xpose<<<dim3(HWN / 32, CDIM / 32, NB), 256>>>(x, pxb);

    // Fused QKV projections (bf16 mma + ldmatrix)
    const int qkvsmem = 3 * 17408;   // 52224 B
    cudaFuncSetAttribute(gemm_qkv, cudaFuncAttributeMaxDynamicSharedMemorySize,
                         qkvsmem);
    gemm_qkv<<<dim3(HWN / 64, EXPD / 64, NB), 256, qkvsmem>>>(
        pxb, pwq, pwk, pwv, bv, pq, pk, pv);

    // Monolithic bf16 attention, 2 CTAs/SM
    const int asmem = 106496;
    cudaFuncSetAttribute(attn_mma, cudaFuncAttributeMaxDynamicSharedMemorySize,
                         asmem);
    attn_mma<<<dim3(8, 4, NB), 256, asmem>>>(pq, pk, pv, pw);

    // Output projection + bias + residual (bf16 mma + ldmatrix, f32 out)
    const int psmem = 17408 + 18432;  // 35840 B
    cudaFuncSetAttribute(gemm_proj, cudaFuncAttributeMaxDynamicSharedMemorySize,
                         psmem);
    gemm_proj<<<dim3(HWN / 64, CDIM / 64, NB), 256, psmem>>>(
        pwt, pw, bt, x, out);
}